// round 4
// baseline (speedup 1.0000x reference)
#include <cuda_runtime.h>
#include <cstdint>

#define NN 100000
#define NE 1600000
#define NG 64

// ---------------- scratch ----------------
__device__ __align__(256) float g_xA[(size_t)NN * 128];
__device__ __align__(256) float g_xB[(size_t)NN * 128];
__device__ __align__(256) float g_xp[(size_t)NN * 128];
__device__ __align__(256) float g_msg[(size_t)NN * 128];
__device__ int g_deg[NN];
__device__ int g_cursor[NN];
__device__ int g_rowptr[NN + 1];
__device__ int g_adj[NE];
__device__ unsigned g_gmax[NG * 64];
__device__ float g_gsum[NG * 64];
__device__ int g_gcnt[NG];

// ---------------- helpers ----------------
__device__ __forceinline__ uint32_t f2tf(float f) {
    uint32_t r;
    asm("cvt.rna.tf32.f32 %0, %1;" : "=r"(r) : "f"(f));
    return r;
}
__device__ __forceinline__ void mma8(float* c, const uint32_t* a, const uint32_t* b) {
    asm volatile(
        "mma.sync.aligned.m16n8k8.row.col.f32.tf32.tf32.f32 "
        "{%0,%1,%2,%3}, {%4,%5,%6,%7}, {%8,%9}, {%0,%1,%2,%3};"
        : "+f"(c[0]), "+f"(c[1]), "+f"(c[2]), "+f"(c[3])
        : "r"(a[0]), "r"(a[1]), "r"(a[2]), "r"(a[3]), "r"(b[0]), "r"(b[1]));
}
__device__ __forceinline__ unsigned fenc(float f) {
    unsigned u = __float_as_uint(f);
    return (u & 0x80000000u) ? ~u : (u | 0x80000000u);
}
__device__ __forceinline__ float fdec(unsigned e) {
    return __uint_as_float((e & 0x80000000u) ? (e ^ 0x80000000u) : ~e);
}

// shared-tile geometry
#define APAD 33
#define BPAD 65

struct SmTiles {
    uint32_t a[128][APAD];   // 128 x 32 tf32 (padded)
    uint32_t b[32][BPAD];    // 32 x 64 tf32 (padded)
};
union SmU {
    SmTiles t;
    float out[128][BPAD];    // combine epilogue staging
};

// warp-tile mma over one BK=32 chunk. acc[2][4][4].
__device__ __forceinline__ void chunk_mma(const SmTiles& sm, float acc[2][4][4],
                                          int warpM, int warpN, int lane) {
    const int qr = lane >> 2, qc = lane & 3;
#pragma unroll
    for (int ks = 0; ks < 4; ks++) {
        const int k = ks * 8;
        uint32_t a[2][4], b[4][2];
#pragma unroll
        for (int mt = 0; mt < 2; mt++) {
            int r = warpM * 32 + mt * 16 + qr;
            a[mt][0] = sm.a[r][k + qc];
            a[mt][1] = sm.a[r + 8][k + qc];
            a[mt][2] = sm.a[r][k + qc + 4];
            a[mt][3] = sm.a[r + 8][k + qc + 4];
        }
#pragma unroll
        for (int nt = 0; nt < 4; nt++) {
            int n = warpN * 32 + nt * 8 + qr;
            b[nt][0] = sm.b[k + qc][n];
            b[nt][1] = sm.b[k + qc + 4][n];
        }
#pragma unroll
        for (int mt = 0; mt < 2; mt++)
#pragma unroll
            for (int nt = 0; nt < 4; nt++) mma8(acc[mt][nt], a[mt], b[nt]);
    }
}

// ---------------- init ----------------
__global__ void init_kernel() {
    int j = blockIdx.x * blockDim.x + threadIdx.x;
    if (j < NN) { g_deg[j] = 0; g_cursor[j] = 0; }
    if (j < NG * 64) { g_gmax[j] = 0x007FFFFFu; g_gsum[j] = 0.f; }
    if (j < NG) g_gcnt[j] = 0;
}

// ---------------- CSR build ----------------
__global__ void hist_kernel(const int* __restrict__ dst) {
    int e = blockIdx.x * blockDim.x + threadIdx.x;
    if (e < NE) atomicAdd(&g_deg[dst[e]], 1);
}

__global__ void scan_kernel() {
    __shared__ int warpsum[32];
    __shared__ int carry;
    const int tid = threadIdx.x, lane = tid & 31, w = tid >> 5;
    if (tid == 0) carry = 0;
    __syncthreads();
    for (int base = 0; base < NN; base += 1024) {
        int i = base + tid;
        int v = (i < NN) ? g_deg[i] : 0;
        int s = v;
#pragma unroll
        for (int off = 1; off < 32; off <<= 1) {
            int t = __shfl_up_sync(0xffffffffu, s, off);
            if (lane >= off) s += t;
        }
        if (lane == 31) warpsum[w] = s;
        __syncthreads();
        if (w == 0) {
            int ws = warpsum[lane];
#pragma unroll
            for (int off = 1; off < 32; off <<= 1) {
                int t = __shfl_up_sync(0xffffffffu, ws, off);
                if (lane >= off) ws += t;
            }
            warpsum[lane] = ws;
        }
        __syncthreads();
        int pre = (w > 0) ? warpsum[w - 1] : 0;
        int incl = s + pre;
        if (i < NN) g_rowptr[i] = carry + incl - v;
        int tot = warpsum[31];
        __syncthreads();
        if (tid == 0) carry += tot;
        __syncthreads();
    }
    if (tid == 0) g_rowptr[NN] = carry;
}

__global__ void fill_adj_kernel(const int* __restrict__ src, const int* __restrict__ dst) {
    int e = blockIdx.x * blockDim.x + threadIdx.x;
    if (e < NE) {
        int d = dst[e];
        int p = atomicAdd(&g_cursor[d], 1);
        g_adj[g_rowptr[d] + p] = src[e];
    }
}

// ---------------- lin: C = relu(concat(nf,emb,cf) @ W + b), W: 190x128 ----------------
__global__ void __launch_bounds__(256)
lin_mma(const float* __restrict__ nf, const float* __restrict__ cf,
        const int* __restrict__ opc, const float* __restrict__ emb,
        const float* __restrict__ W, const float* __restrict__ bias,
        float* __restrict__ C) {
    constexpr int NDIM = 128;
    __shared__ SmU sm;
    __shared__ float sBias[64];
    const int tid = threadIdx.x, lane = tid & 31, wid = tid >> 5;
    const int warpM = wid & 3, warpN = wid >> 2;
    const int rowBase = blockIdx.x * 128;
    const int n0 = blockIdx.y * 64;

    if (tid < 64) sBias[tid] = bias[n0 + tid];

    float acc[2][4][4];
#pragma unroll
    for (int mt = 0; mt < 2; mt++)
#pragma unroll
        for (int nt = 0; nt < 4; nt++)
#pragma unroll
            for (int q = 0; q < 4; q++) acc[mt][nt][q] = 0.f;

    for (int c = 0; c < 6; c++) {
        __syncthreads();
#pragma unroll
        for (int i = 0; i < 16; i++) {
            int e = tid + i * 256;
            int row = e >> 5, kc = e & 31;
            int grow = rowBase + row, k = c * 32 + kc;
            float v = 0.f;
            if (grow < NN) {
                if (k < 140)      v = nf[(size_t)grow * 140 + k];
                else if (k < 172) v = emb[opc[grow] * 32 + (k - 140)];
                else if (k < 190) v = cf[(size_t)grow * 18 + (k - 172)];
            }
            sm.t.a[row][kc] = f2tf(v);
        }
#pragma unroll
        for (int i = 0; i < 8; i++) {
            int e = tid + i * 256;
            int kl = e >> 6, n = e & 63;
            int k = c * 32 + kl;
            float w = (k < 190) ? W[(size_t)k * NDIM + n0 + n] : 0.f;
            sm.t.b[kl][n] = f2tf(w);
        }
        __syncthreads();
        chunk_mma(sm.t, acc, warpM, warpN, lane);
    }
    // epilogue: bias + relu, float2 stores
    const int qr = lane >> 2, qc = lane & 3;
#pragma unroll
    for (int mt = 0; mt < 2; mt++) {
        int r0 = rowBase + warpM * 32 + mt * 16 + qr;
#pragma unroll
        for (int nt = 0; nt < 4; nt++) {
            int cl = warpN * 32 + nt * 8 + qc * 2;
            int gc = n0 + cl;
            if (r0 < NN) {
                float2 o;
                o.x = fmaxf(acc[mt][nt][0] + sBias[cl], 0.f);
                o.y = fmaxf(acc[mt][nt][1] + sBias[cl + 1], 0.f);
                *(float2*)(C + (size_t)r0 * NDIM + gc) = o;
            }
            if (r0 + 8 < NN) {
                float2 o;
                o.x = fmaxf(acc[mt][nt][2] + sBias[cl], 0.f);
                o.y = fmaxf(acc[mt][nt][3] + sBias[cl + 1], 0.f);
                *(float2*)(C + (size_t)(r0 + 8) * NDIM + gc) = o;
            }
        }
    }
}

// ---------------- proj: C = relu(A @ W + b) ----------------
template <int K, int NDIM>
__global__ void __launch_bounds__(256)
proj_mma(const float* __restrict__ A, const float* __restrict__ W,
         const float* __restrict__ bias, float* __restrict__ C) {
    __shared__ SmU sm;
    __shared__ float sBias[64];
    const int tid = threadIdx.x, lane = tid & 31, wid = tid >> 5;
    const int warpM = wid & 3, warpN = wid >> 2;
    const int rowBase = blockIdx.x * 128;
    const int n0 = blockIdx.y * 64;

    if (tid < 64) sBias[tid] = bias[n0 + tid];

    float acc[2][4][4];
#pragma unroll
    for (int mt = 0; mt < 2; mt++)
#pragma unroll
        for (int nt = 0; nt < 4; nt++)
#pragma unroll
            for (int q = 0; q < 4; q++) acc[mt][nt][q] = 0.f;

    for (int c = 0; c < K / 32; c++) {
        __syncthreads();
#pragma unroll
        for (int i = 0; i < 4; i++) {
            int e4 = tid + i * 256;
            int row = e4 >> 3, c4 = e4 & 7;
            int grow = rowBase + row;
            float4 v = make_float4(0, 0, 0, 0);
            if (grow < NN) v = *(const float4*)(A + (size_t)grow * K + c * 32 + c4 * 4);
            sm.t.a[row][c4 * 4 + 0] = f2tf(v.x);
            sm.t.a[row][c4 * 4 + 1] = f2tf(v.y);
            sm.t.a[row][c4 * 4 + 2] = f2tf(v.z);
            sm.t.a[row][c4 * 4 + 3] = f2tf(v.w);
        }
#pragma unroll
        for (int i = 0; i < 8; i++) {
            int e = tid + i * 256;
            int kl = e >> 6, n = e & 63;
            sm.t.b[kl][n] = f2tf(W[(size_t)(c * 32 + kl) * NDIM + n0 + n]);
        }
        __syncthreads();
        chunk_mma(sm.t, acc, warpM, warpN, lane);
    }
    const int qr = lane >> 2, qc = lane & 3;
#pragma unroll
    for (int mt = 0; mt < 2; mt++) {
        int r0 = rowBase + warpM * 32 + mt * 16 + qr;
#pragma unroll
        for (int nt = 0; nt < 4; nt++) {
            int cl = warpN * 32 + nt * 8 + qc * 2;
            int gc = n0 + cl;
            if (r0 < NN) {
                float2 o;
                o.x = fmaxf(acc[mt][nt][0] + sBias[cl], 0.f);
                o.y = fmaxf(acc[mt][nt][1] + sBias[cl + 1], 0.f);
                *(float2*)(C + (size_t)r0 * NDIM + gc) = o;
            }
            if (r0 + 8 < NN) {
                float2 o;
                o.x = fmaxf(acc[mt][nt][2] + sBias[cl], 0.f);
                o.y = fmaxf(acc[mt][nt][3] + sBias[cl + 1], 0.f);
                *(float2*)(C + (size_t)(r0 + 8) * NDIM + gc) = o;
            }
        }
    }
}

// ---------------- combine: C = normalize(M@Wl + X@Wr + bl), N=64 ----------------
template <int K>
__global__ void __launch_bounds__(256)
combine_mma(const float* __restrict__ M, const float* __restrict__ X,
            const float* __restrict__ Wl, const float* __restrict__ Wr,
            const float* __restrict__ bl, float* __restrict__ C) {
    __shared__ SmU sm;
    __shared__ float sBias[64];
    const int tid = threadIdx.x, lane = tid & 31, wid = tid >> 5;
    const int warpM = wid & 3, warpN = wid >> 2;
    const int rowBase = blockIdx.x * 128;

    if (tid < 64) sBias[tid] = bl[tid];

    float acc[2][4][4];
#pragma unroll
    for (int mt = 0; mt < 2; mt++)
#pragma unroll
        for (int nt = 0; nt < 4; nt++)
#pragma unroll
            for (int q = 0; q < 4; q++) acc[mt][nt][q] = 0.f;

    constexpr int HC = K / 32;
    for (int c = 0; c < 2 * HC; c++) {
        const float* Ap = (c < HC) ? M : X;
        const float* Bp = (c < HC) ? Wl : Wr;
        const int k0 = (c < HC ? c : c - HC) * 32;
        __syncthreads();
#pragma unroll
        for (int i = 0; i < 4; i++) {
            int e4 = tid + i * 256;
            int row = e4 >> 3, c4 = e4 & 7;
            int grow = rowBase + row;
            float4 v = make_float4(0, 0, 0, 0);
            if (grow < NN) v = *(const float4*)(Ap + (size_t)grow * K + k0 + c4 * 4);
            sm.t.a[row][c4 * 4 + 0] = f2tf(v.x);
            sm.t.a[row][c4 * 4 + 1] = f2tf(v.y);
            sm.t.a[row][c4 * 4 + 2] = f2tf(v.z);
            sm.t.a[row][c4 * 4 + 3] = f2tf(v.w);
        }
#pragma unroll
        for (int i = 0; i < 8; i++) {
            int e = tid + i * 256;
            int kl = e >> 6, n = e & 63;
            sm.t.b[kl][n] = f2tf(Bp[(size_t)(k0 + kl) * 64 + n]);
        }
        __syncthreads();
        chunk_mma(sm.t, acc, warpM, warpN, lane);
    }
    // stage to smem, then row-normalize
    __syncthreads();
    const int qr = lane >> 2, qc = lane & 3;
#pragma unroll
    for (int mt = 0; mt < 2; mt++) {
        int r0 = warpM * 32 + mt * 16 + qr;
#pragma unroll
        for (int nt = 0; nt < 4; nt++) {
            int cl = warpN * 32 + nt * 8 + qc * 2;
            sm.out[r0][cl]     = acc[mt][nt][0] + sBias[cl];
            sm.out[r0][cl + 1] = acc[mt][nt][1] + sBias[cl + 1];
            sm.out[r0 + 8][cl]     = acc[mt][nt][2] + sBias[cl];
            sm.out[r0 + 8][cl + 1] = acc[mt][nt][3] + sBias[cl + 1];
        }
    }
    __syncthreads();
#pragma unroll
    for (int rr = 0; rr < 16; rr++) {
        int r = wid * 16 + rr;
        int grow = rowBase + r;
        float v0 = sm.out[r][lane];
        float v1 = sm.out[r][lane + 32];
        float ss = v0 * v0 + v1 * v1;
#pragma unroll
        for (int o = 16; o > 0; o >>= 1) ss += __shfl_xor_sync(0xffffffffu, ss, o);
        float sc = 1.0f / fmaxf(sqrtf(ss), 1e-12f);
        if (grow < NN) {
            C[(size_t)grow * 64 + lane] = v0 * sc;
            C[(size_t)grow * 64 + lane + 32] = v1 * sc;
        }
    }
}

// ---------------- mean aggregation over CSR ----------------
__global__ void agg_kernel128(const float* __restrict__ xp, float* __restrict__ msg) {
    int w = (blockIdx.x * blockDim.x + threadIdx.x) >> 5;
    int lane = threadIdx.x & 31;
    if (w >= NN) return;
    int beg = g_rowptr[w], end = g_rowptr[w + 1];
    float4 acc = make_float4(0, 0, 0, 0);
    for (int e = beg; e < end; e++) {
        int s = __ldg(&g_adj[e]);
        float4 v = *reinterpret_cast<const float4*>(xp + (size_t)s * 128 + lane * 4);
        acc.x += v.x; acc.y += v.y; acc.z += v.z; acc.w += v.w;
    }
    float inv = 1.0f / fmaxf((float)(end - beg), 1.0f);
    *reinterpret_cast<float4*>(msg + (size_t)w * 128 + lane * 4) =
        make_float4(acc.x * inv, acc.y * inv, acc.z * inv, acc.w * inv);
}

__global__ void agg_kernel64(const float* __restrict__ xp, float* __restrict__ msg) {
    int w = (blockIdx.x * blockDim.x + threadIdx.x) >> 5;
    int lane = threadIdx.x & 31;
    if (w >= NN) return;
    int beg = g_rowptr[w], end = g_rowptr[w + 1];
    float2 acc = make_float2(0, 0);
    for (int e = beg; e < end; e++) {
        int s = __ldg(&g_adj[e]);
        float2 v = *reinterpret_cast<const float2*>(xp + (size_t)s * 64 + lane * 2);
        acc.x += v.x; acc.y += v.y;
    }
    float inv = 1.0f / fmaxf((float)(end - beg), 1.0f);
    *reinterpret_cast<float2*>(msg + (size_t)w * 64 + lane * 2) =
        make_float2(acc.x * inv, acc.y * inv);
}

// ---------------- pooling ----------------
__global__ void pool_kernel(const float* __restrict__ x, const int* __restrict__ batch) {
    int nwarps = (gridDim.x * blockDim.x) >> 5;
    int w = (blockIdx.x * blockDim.x + threadIdx.x) >> 5;
    int lane = threadIdx.x & 31;
    int per = (NN + nwarps - 1) / nwarps;
    int s = w * per;
    int e = min(NN, s + per);
    if (s >= e) return;
    float m0 = -__int_as_float(0x7f800000), m1 = m0;
    float s0 = 0.f, s1 = 0.f;
    int cnt = 0;
    int curg = __ldg(&batch[s]);
    for (int i = s; i < e; i++) {
        int g = __ldg(&batch[i]);
        if (g != curg) {
            atomicMax(&g_gmax[curg * 64 + lane], fenc(m0));
            atomicMax(&g_gmax[curg * 64 + lane + 32], fenc(m1));
            atomicAdd(&g_gsum[curg * 64 + lane], s0);
            atomicAdd(&g_gsum[curg * 64 + lane + 32], s1);
            if (lane == 0) atomicAdd(&g_gcnt[curg], cnt);
            m0 = m1 = -__int_as_float(0x7f800000);
            s0 = s1 = 0.f; cnt = 0; curg = g;
        }
        float v0 = x[(size_t)i * 64 + lane];
        float v1 = x[(size_t)i * 64 + lane + 32];
        m0 = fmaxf(m0, v0); m1 = fmaxf(m1, v1);
        s0 += v0; s1 += v1; cnt++;
    }
    atomicMax(&g_gmax[curg * 64 + lane], fenc(m0));
    atomicMax(&g_gmax[curg * 64 + lane + 32], fenc(m1));
    atomicAdd(&g_gsum[curg * 64 + lane], s0);
    atomicAdd(&g_gsum[curg * 64 + lane + 32], s1);
    if (lane == 0) atomicAdd(&g_gcnt[curg], cnt);
}

// ---------------- final ----------------
__global__ void final_kernel(const float* __restrict__ post_w, const float* __restrict__ post_b,
                             float* __restrict__ out) {
    int g = threadIdx.x;
    if (g >= NG) return;
    float inv = 1.0f / (float)g_gcnt[g];
    float v[64];
    float ss = 0.f;
#pragma unroll
    for (int c = 0; c < 64; c++) {
        float t = fdec(g_gmax[g * 64 + c]) + g_gsum[g * 64 + c] * inv;
        v[c] = t;
        ss += t * t;
    }
    float norm = sqrtf(ss);
    float dot = 0.f;
#pragma unroll
    for (int c = 0; c < 64; c++) dot += v[c] * post_w[c];
    out[g] = dot / norm + post_b[0];
}

// ---------------- launch ----------------
extern "C" void kernel_launch(void* const* d_in, const int* in_sizes, int n_in,
                              void* d_out, int out_size) {
    const float* node_feat = (const float*)d_in[0];
    const float* cfg_feat  = (const float*)d_in[1];
    const int*   opcode    = (const int*)d_in[2];
    const int*   edge      = (const int*)d_in[3];
    const int*   batch     = (const int*)d_in[4];
    const float* op_emb    = (const float*)d_in[5];
    const float* lin_w     = (const float*)d_in[6];
    const float* lin_b     = (const float*)d_in[7];
    const float* post_w    = (const float*)d_in[8];
    const float* post_b    = (const float*)d_in[9];
    const float* pw0 = (const float*)d_in[10];
    const float* pb0 = (const float*)d_in[11];
    const float* wl0 = (const float*)d_in[12];
    const float* bl0 = (const float*)d_in[13];
    const float* wr0 = (const float*)d_in[14];
    const float* pw1 = (const float*)d_in[15];
    const float* pb1 = (const float*)d_in[16];
    const float* wl1 = (const float*)d_in[17];
    const float* bl1 = (const float*)d_in[18];
    const float* wr1 = (const float*)d_in[19];
    const float* pw2 = (const float*)d_in[20];
    const float* pb2 = (const float*)d_in[21];
    const float* wl2 = (const float*)d_in[22];
    const float* bl2 = (const float*)d_in[23];
    const float* wr2 = (const float*)d_in[24];
    float* out = (float*)d_out;

    const int* src = edge;
    const int* dst = edge + NE;

    const int MB = (NN + 127) / 128;   // 782
    const int EB = (NE + 255) / 256;
    const int AGGB = (NN * 32 + 255) / 256;

    init_kernel<<<(NN + 255) / 256, 256>>>();
    hist_kernel<<<EB, 256>>>(dst);
    scan_kernel<<<1, 1024>>>();
    fill_adj_kernel<<<EB, 256>>>(src, dst);

    float* dA; cudaGetSymbolAddress((void**)&dA, g_xA);
    float* dB; cudaGetSymbolAddress((void**)&dB, g_xB);
    float* dP; cudaGetSymbolAddress((void**)&dP, g_xp);
    float* dM; cudaGetSymbolAddress((void**)&dM, g_msg);

    lin_mma<<<dim3(MB, 2), 256>>>(node_feat, cfg_feat, opcode, op_emb, lin_w, lin_b, dA);

    // layer 0 (d=128 -> 64)
    proj_mma<128, 128><<<dim3(MB, 2), 256>>>(dA, pw0, pb0, dP);
    agg_kernel128<<<AGGB, 256>>>(dP, dM);
    combine_mma<128><<<MB, 256>>>(dM, dA, wl0, wr0, bl0, dB);

    // layer 1 (d=64 -> 64)
    proj_mma<64, 64><<<dim3(MB, 1), 256>>>(dB, pw1, pb1, dP);
    agg_kernel64<<<AGGB, 256>>>(dP, dM);
    combine_mma<64><<<MB, 256>>>(dM, dB, wl1, wr1, bl1, dA);

    // layer 2 (d=64 -> 64)
    proj_mma<64, 64><<<dim3(MB, 1), 256>>>(dA, pw2, pb2, dP);
    agg_kernel64<<<AGGB, 256>>>(dP, dM);
    combine_mma<64><<<MB, 256>>>(dM, dA, wl2, wr2, bl2, dB);

    pool_kernel<<<128, 256>>>(dB, batch);
    final_kernel<<<1, 64>>>(post_w, post_b, out);
}

// round 5
// speedup vs baseline: 1.2895x; 1.2895x over previous
#include <cuda_runtime.h>
#include <cstdint>

#define NN 100000
#define NE 1600000
#define NG 64

// ---------------- scratch ----------------
__device__ __align__(256) float g_xA[(size_t)NN * 128];
__device__ __align__(256) float g_xB[(size_t)NN * 128];
__device__ __align__(256) float g_xp[(size_t)NN * 128];
__device__ __align__(256) float g_msg[(size_t)NN * 128];
__device__ int g_deg[NN];
__device__ int g_cursor[NN];
__device__ int g_rowptr[NN + 1];
__device__ int g_adj[NE];
__device__ unsigned g_gmax[NG * 64];
__device__ float g_gsum[NG * 64];
__device__ int g_gcnt[NG];

// ---------------- helpers ----------------
__device__ __forceinline__ uint32_t f2tf(float f) {
    uint32_t r;
    asm("cvt.rna.tf32.f32 %0, %1;" : "=r"(r) : "f"(f));
    return r;
}
__device__ __forceinline__ void mma8(float* c, const uint32_t* a, const uint32_t* b) {
    asm volatile(
        "mma.sync.aligned.m16n8k8.row.col.f32.tf32.tf32.f32 "
        "{%0,%1,%2,%3}, {%4,%5,%6,%7}, {%8,%9}, {%0,%1,%2,%3};"
        : "+f"(c[0]), "+f"(c[1]), "+f"(c[2]), "+f"(c[3])
        : "r"(a[0]), "r"(a[1]), "r"(a[2]), "r"(a[3]), "r"(b[0]), "r"(b[1]));
}
__device__ __forceinline__ unsigned fenc(float f) {
    unsigned u = __float_as_uint(f);
    return (u & 0x80000000u) ? ~u : (u | 0x80000000u);
}
__device__ __forceinline__ float fdec(unsigned e) {
    return __uint_as_float((e & 0x80000000u) ? (e ^ 0x80000000u) : ~e);
}

// ---------------- fragment-layout staging ----------------
// A tile 128x32 tf32: word addr = (((rb*4+ks)*2+mt)*32 + lane)*4 + (jj*2+rh)
// lane = qr*4+qc; element (row,col): rb=row>>5, mt=(row>>4)&1, rh=(row>>3)&1,
// qr=row&7, ks=col>>3, jj=(col>>2)&1, qc=col&3.  4096 words.
__device__ __forceinline__ void stA(uint32_t* sA, int row, int c4, float4 v) {
    int rb = row >> 5, mt = (row >> 4) & 1, rh = (row >> 3) & 1, qr = row & 7;
    int ks = c4 >> 1, jj = c4 & 1;
    uint32_t* p = sA + ((((rb * 4 + ks) * 2 + mt) * 32) + qr * 4) * 4 + jj * 2 + rh;
    p[0]  = f2tf(v.x);
    p[4]  = f2tf(v.y);
    p[8]  = f2tf(v.z);
    p[12] = f2tf(v.w);
}
// B tile 32x64 tf32: word addr = (((nb*4+ks)*4+nt)*32 + lane)*2 + jj
// element (k,n): ks=k>>3, jj=(k>>2)&1, qc=k&3, nb=n>>5, nt=(n>>3)&3, qr=n&7.
// 2048 words.
__device__ __forceinline__ void stB(uint32_t* sB, int k, int n4, float4 v) {
    int ks = k >> 3, kr = k & 7, jj = kr >> 2, qc = kr & 3;
    int n = n4 * 4;
    int nb = n >> 5, nt = (n >> 3) & 3, qr0 = n & 7;
    uint32_t* p = sB + ((((nb * 4 + ks) * 4 + nt) * 32) + qr0 * 4 + qc) * 2 + jj;
    p[0]  = f2tf(v.x);
    p[8]  = f2tf(v.y);
    p[16] = f2tf(v.z);
    p[24] = f2tf(v.w);
}

// conflict-free fragment consumer: 8x LDS.128 + 16x LDS.64, 32 mma per warp-chunk
__device__ __forceinline__ void chunk_mma_frag(const uint32_t* sA, const uint32_t* sB,
                                               float acc[2][4][4], int warpM, int warpN, int lane) {
#pragma unroll
    for (int ks = 0; ks < 4; ks++) {
        uint32_t a[2][4];
#pragma unroll
        for (int mt = 0; mt < 2; mt++) {
            uint4 t = *reinterpret_cast<const uint4*>(sA + ((((warpM * 4 + ks) * 2 + mt) * 32) + lane) * 4);
            a[mt][0] = t.x; a[mt][1] = t.y; a[mt][2] = t.z; a[mt][3] = t.w;
        }
#pragma unroll
        for (int nt = 0; nt < 4; nt++) {
            uint2 t = *reinterpret_cast<const uint2*>(sB + ((((warpN * 4 + ks) * 4 + nt) * 32) + lane) * 2);
            uint32_t b[2] = { t.x, t.y };
#pragma unroll
            for (int mt = 0; mt < 2; mt++) mma8(acc[mt][nt], a[mt], b);
        }
    }
}

// ---------------- init ----------------
__global__ void init_kernel() {
    int j = blockIdx.x * blockDim.x + threadIdx.x;
    if (j < NN) { g_deg[j] = 0; g_cursor[j] = 0; }
    if (j < NG * 64) { g_gmax[j] = 0x007FFFFFu; g_gsum[j] = 0.f; }
    if (j < NG) g_gcnt[j] = 0;
}

// ---------------- CSR build ----------------
__global__ void hist_kernel(const int* __restrict__ dst) {
    int e = blockIdx.x * blockDim.x + threadIdx.x;
    if (e < NE) atomicAdd(&g_deg[dst[e]], 1);
}

__global__ void scan_kernel() {
    __shared__ int warpsum[32];
    __shared__ int carry;
    const int tid = threadIdx.x, lane = tid & 31, w = tid >> 5;
    if (tid == 0) carry = 0;
    __syncthreads();
    for (int base = 0; base < NN; base += 1024) {
        int i = base + tid;
        int v = (i < NN) ? g_deg[i] : 0;
        int s = v;
#pragma unroll
        for (int off = 1; off < 32; off <<= 1) {
            int t = __shfl_up_sync(0xffffffffu, s, off);
            if (lane >= off) s += t;
        }
        if (lane == 31) warpsum[w] = s;
        __syncthreads();
        if (w == 0) {
            int ws = warpsum[lane];
#pragma unroll
            for (int off = 1; off < 32; off <<= 1) {
                int t = __shfl_up_sync(0xffffffffu, ws, off);
                if (lane >= off) ws += t;
            }
            warpsum[lane] = ws;
        }
        __syncthreads();
        int pre = (w > 0) ? warpsum[w - 1] : 0;
        int incl = s + pre;
        if (i < NN) g_rowptr[i] = carry + incl - v;
        int tot = warpsum[31];
        __syncthreads();
        if (tid == 0) carry += tot;
        __syncthreads();
    }
    if (tid == 0) g_rowptr[NN] = carry;
}

__global__ void fill_adj_kernel(const int* __restrict__ src, const int* __restrict__ dst) {
    int e = blockIdx.x * blockDim.x + threadIdx.x;
    if (e < NE) {
        int d = dst[e];
        int p = atomicAdd(&g_cursor[d], 1);
        g_adj[g_rowptr[d] + p] = src[e];
    }
}

// ---------------- lin: C = relu(concat(nf,emb,cf) @ W + b), 64 cols per y-block ----------------
__global__ void __launch_bounds__(256)
lin_frag(const float* __restrict__ nf, const float* __restrict__ cf,
         const int* __restrict__ opc, const float* __restrict__ emb,
         const float* __restrict__ W, const float* __restrict__ bias,
         float* __restrict__ C) {
    extern __shared__ uint32_t smem[];
    const int tid = threadIdx.x, lane = tid & 31, wid = tid >> 5;
    const int warpM = wid & 3, warpN = wid >> 2;
    const int rowBase = blockIdx.x * 128;
    const int n0 = blockIdx.y * 64;

    float acc[2][4][4];
#pragma unroll
    for (int mt = 0; mt < 2; mt++)
#pragma unroll
        for (int nt = 0; nt < 4; nt++)
#pragma unroll
            for (int q = 0; q < 4; q++) acc[mt][nt][q] = 0.f;

    float4 ra[4], rb[2];
    auto loadC = [&](int c) {
#pragma unroll
        for (int i = 0; i < 4; i++) {
            int e4 = tid + i * 256;
            int row = e4 >> 3, c4 = e4 & 7;
            int grow = rowBase + row;
            int k = c * 32 + c4 * 4;
            float4 v = make_float4(0, 0, 0, 0);
            if (grow < NN) {
                if (k < 140)      v = *(const float4*)(nf + (size_t)grow * 140 + k);
                else if (k < 172) v = *(const float4*)(emb + (size_t)opc[grow] * 32 + (k - 140));
                else {
                    const float* cp = cf + (size_t)grow * 18;
                    int off = k - 172;
                    v.x = (off + 0 < 18) ? cp[off + 0] : 0.f;
                    v.y = (off + 1 < 18) ? cp[off + 1] : 0.f;
                    v.z = (off + 2 < 18) ? cp[off + 2] : 0.f;
                    v.w = (off + 3 < 18) ? cp[off + 3] : 0.f;
                }
            }
            ra[i] = v;
        }
#pragma unroll
        for (int i = 0; i < 2; i++) {
            int e4 = tid + i * 256;
            int k = e4 >> 4, n4 = e4 & 15;
            int kg = c * 32 + k;
            rb[i] = (kg < 190) ? *(const float4*)(W + (size_t)kg * 128 + n0 + n4 * 4)
                               : make_float4(0, 0, 0, 0);
        }
    };
    auto stage = [&](int b) {
        uint32_t* sa = smem + (b ? 4096 : 0);
        uint32_t* sb = smem + 8192 + (b ? 2048 : 0);
#pragma unroll
        for (int i = 0; i < 4; i++) { int e4 = tid + i * 256; stA(sa, e4 >> 3, e4 & 7, ra[i]); }
#pragma unroll
        for (int i = 0; i < 2; i++) { int e4 = tid + i * 256; stB(sb, e4 >> 4, e4 & 15, rb[i]); }
    };

    loadC(0); stage(0); __syncthreads();
#pragma unroll 1
    for (int c = 0; c < 6; c++) {
        if (c < 5) loadC(c + 1);
        const uint32_t* sa = smem + ((c & 1) ? 4096 : 0);
        const uint32_t* sb = smem + 8192 + ((c & 1) ? 2048 : 0);
        chunk_mma_frag(sa, sb, acc, warpM, warpN, lane);
        if (c < 5) { stage((c + 1) & 1); __syncthreads(); }
    }

    const int qr = lane >> 2, qc = lane & 3;
#pragma unroll
    for (int mt = 0; mt < 2; mt++) {
        int r0 = rowBase + warpM * 32 + mt * 16 + qr;
#pragma unroll
        for (int nt = 0; nt < 4; nt++) {
            int gc = n0 + warpN * 32 + nt * 8 + qc * 2;
            float b0 = __ldg(&bias[gc]), b1 = __ldg(&bias[gc + 1]);
            if (r0 < NN) {
                float2 o = { fmaxf(acc[mt][nt][0] + b0, 0.f), fmaxf(acc[mt][nt][1] + b1, 0.f) };
                *(float2*)(C + (size_t)r0 * 128 + gc) = o;
            }
            if (r0 + 8 < NN) {
                float2 o = { fmaxf(acc[mt][nt][2] + b0, 0.f), fmaxf(acc[mt][nt][3] + b1, 0.f) };
                *(float2*)(C + (size_t)(r0 + 8) * 128 + gc) = o;
            }
        }
    }
}

// ---------------- proj: C = relu(A @ W + b), 64 cols per y-block ----------------
template <int K, int NDIM>
__global__ void __launch_bounds__(256)
proj_frag(const float* __restrict__ A, const float* __restrict__ W,
          const float* __restrict__ bias, float* __restrict__ C) {
    constexpr int NCH = K / 32;
    extern __shared__ uint32_t smem[];
    const int tid = threadIdx.x, lane = tid & 31, wid = tid >> 5;
    const int warpM = wid & 3, warpN = wid >> 2;
    const int rowBase = blockIdx.x * 128;
    const int n0 = blockIdx.y * 64;

    float acc[2][4][4];
#pragma unroll
    for (int mt = 0; mt < 2; mt++)
#pragma unroll
        for (int nt = 0; nt < 4; nt++)
#pragma unroll
            for (int q = 0; q < 4; q++) acc[mt][nt][q] = 0.f;

    float4 ra[4], rb[2];
    auto loadC = [&](int c) {
#pragma unroll
        for (int i = 0; i < 4; i++) {
            int e4 = tid + i * 256;
            int row = e4 >> 3, c4 = e4 & 7;
            int grow = rowBase + row;
            ra[i] = (grow < NN) ? *(const float4*)(A + (size_t)grow * K + c * 32 + c4 * 4)
                                : make_float4(0, 0, 0, 0);
        }
#pragma unroll
        for (int i = 0; i < 2; i++) {
            int e4 = tid + i * 256;
            int k = e4 >> 4, n4 = e4 & 15;
            rb[i] = *(const float4*)(W + (size_t)(c * 32 + k) * NDIM + n0 + n4 * 4);
        }
    };
    auto stage = [&](int b) {
        uint32_t* sa = smem + (b ? 4096 : 0);
        uint32_t* sb = smem + 8192 + (b ? 2048 : 0);
#pragma unroll
        for (int i = 0; i < 4; i++) { int e4 = tid + i * 256; stA(sa, e4 >> 3, e4 & 7, ra[i]); }
#pragma unroll
        for (int i = 0; i < 2; i++) { int e4 = tid + i * 256; stB(sb, e4 >> 4, e4 & 15, rb[i]); }
    };

    loadC(0); stage(0); __syncthreads();
#pragma unroll 1
    for (int c = 0; c < NCH; c++) {
        if (c + 1 < NCH) loadC(c + 1);
        const uint32_t* sa = smem + ((c & 1) ? 4096 : 0);
        const uint32_t* sb = smem + 8192 + ((c & 1) ? 2048 : 0);
        chunk_mma_frag(sa, sb, acc, warpM, warpN, lane);
        if (c + 1 < NCH) { stage((c + 1) & 1); __syncthreads(); }
    }

    const int qr = lane >> 2, qc = lane & 3;
#pragma unroll
    for (int mt = 0; mt < 2; mt++) {
        int r0 = rowBase + warpM * 32 + mt * 16 + qr;
#pragma unroll
        for (int nt = 0; nt < 4; nt++) {
            int gc = n0 + warpN * 32 + nt * 8 + qc * 2;
            float b0 = __ldg(&bias[gc]), b1 = __ldg(&bias[gc + 1]);
            if (r0 < NN) {
                float2 o = { fmaxf(acc[mt][nt][0] + b0, 0.f), fmaxf(acc[mt][nt][1] + b1, 0.f) };
                *(float2*)(C + (size_t)r0 * NDIM + gc) = o;
            }
            if (r0 + 8 < NN) {
                float2 o = { fmaxf(acc[mt][nt][2] + b0, 0.f), fmaxf(acc[mt][nt][3] + b1, 0.f) };
                *(float2*)(C + (size_t)(r0 + 8) * NDIM + gc) = o;
            }
        }
    }
}

// ---------------- combine: C = normalize(M@Wl + X@Wr + bl), N=64 ----------------
template <int K>
__global__ void __launch_bounds__(256)
combine_frag(const float* __restrict__ M, const float* __restrict__ X,
             const float* __restrict__ Wl, const float* __restrict__ Wr,
             const float* __restrict__ bl, float* __restrict__ C) {
    constexpr int NCH = K / 32, TCH = 2 * NCH;
    extern __shared__ uint32_t smem[];
    const int tid = threadIdx.x, lane = tid & 31, wid = tid >> 5;
    const int warpM = wid & 3, warpN = wid >> 2;
    const int rowBase = blockIdx.x * 128;

    float acc[2][4][4];
#pragma unroll
    for (int mt = 0; mt < 2; mt++)
#pragma unroll
        for (int nt = 0; nt < 4; nt++)
#pragma unroll
            for (int q = 0; q < 4; q++) acc[mt][nt][q] = 0.f;

    float4 ra[4], rb[2];
    auto loadC = [&](int c) {
        const float* Ap = (c < NCH) ? M : X;
        const float* Bp = (c < NCH) ? Wl : Wr;
        int k0 = (c < NCH ? c : c - NCH) * 32;
#pragma unroll
        for (int i = 0; i < 4; i++) {
            int e4 = tid + i * 256;
            int row = e4 >> 3, c4 = e4 & 7;
            int grow = rowBase + row;
            ra[i] = (grow < NN) ? *(const float4*)(Ap + (size_t)grow * K + k0 + c4 * 4)
                                : make_float4(0, 0, 0, 0);
        }
#pragma unroll
        for (int i = 0; i < 2; i++) {
            int e4 = tid + i * 256;
            int k = e4 >> 4, n4 = e4 & 15;
            rb[i] = *(const float4*)(Bp + (size_t)(k0 + k) * 64 + n4 * 4);
        }
    };
    auto stage = [&](int b) {
        uint32_t* sa = smem + (b ? 4096 : 0);
        uint32_t* sb = smem + 8192 + (b ? 2048 : 0);
#pragma unroll
        for (int i = 0; i < 4; i++) { int e4 = tid + i * 256; stA(sa, e4 >> 3, e4 & 7, ra[i]); }
#pragma unroll
        for (int i = 0; i < 2; i++) { int e4 = tid + i * 256; stB(sb, e4 >> 4, e4 & 15, rb[i]); }
    };

    loadC(0); stage(0); __syncthreads();
#pragma unroll 1
    for (int c = 0; c < TCH; c++) {
        if (c + 1 < TCH) loadC(c + 1);
        const uint32_t* sa = smem + ((c & 1) ? 4096 : 0);
        const uint32_t* sb = smem + 8192 + ((c & 1) ? 2048 : 0);
        chunk_mma_frag(sa, sb, acc, warpM, warpN, lane);
        if (c + 1 < TCH) { stage((c + 1) & 1); __syncthreads(); }
    }

    // stage outputs + row L2-normalize (overlay on the smem buffers)
    __syncthreads();
    float (*sOut)[65] = reinterpret_cast<float(*)[65]>(smem);
    const int qr = lane >> 2, qc = lane & 3;
#pragma unroll
    for (int mt = 0; mt < 2; mt++) {
        int r0 = warpM * 32 + mt * 16 + qr;
#pragma unroll
        for (int nt = 0; nt < 4; nt++) {
            int cl = warpN * 32 + nt * 8 + qc * 2;
            float b0 = __ldg(&bl[cl]), b1 = __ldg(&bl[cl + 1]);
            sOut[r0][cl]         = acc[mt][nt][0] + b0;
            sOut[r0][cl + 1]     = acc[mt][nt][1] + b1;
            sOut[r0 + 8][cl]     = acc[mt][nt][2] + b0;
            sOut[r0 + 8][cl + 1] = acc[mt][nt][3] + b1;
        }
    }
    __syncthreads();
#pragma unroll
    for (int rr = 0; rr < 16; rr++) {
        int r = wid * 16 + rr;
        int grow = rowBase + r;
        float v0 = sOut[r][lane];
        float v1 = sOut[r][lane + 32];
        float ss = v0 * v0 + v1 * v1;
#pragma unroll
        for (int o = 16; o > 0; o >>= 1) ss += __shfl_xor_sync(0xffffffffu, ss, o);
        float sc = 1.0f / fmaxf(sqrtf(ss), 1e-12f);
        if (grow < NN) {
            C[(size_t)grow * 64 + lane] = v0 * sc;
            C[(size_t)grow * 64 + lane + 32] = v1 * sc;
        }
    }
}

// ---------------- mean aggregation over CSR ----------------
__global__ void agg_kernel128(const float* __restrict__ xp, float* __restrict__ msg) {
    int w = (blockIdx.x * blockDim.x + threadIdx.x) >> 5;
    int lane = threadIdx.x & 31;
    if (w >= NN) return;
    int beg = g_rowptr[w], end = g_rowptr[w + 1];
    float4 acc = make_float4(0, 0, 0, 0);
    for (int e = beg; e < end; e++) {
        int s = __ldg(&g_adj[e]);
        float4 v = *reinterpret_cast<const float4*>(xp + (size_t)s * 128 + lane * 4);
        acc.x += v.x; acc.y += v.y; acc.z += v.z; acc.w += v.w;
    }
    float inv = 1.0f / fmaxf((float)(end - beg), 1.0f);
    *reinterpret_cast<float4*>(msg + (size_t)w * 128 + lane * 4) =
        make_float4(acc.x * inv, acc.y * inv, acc.z * inv, acc.w * inv);
}

__global__ void agg_kernel64(const float* __restrict__ xp, float* __restrict__ msg) {
    int w = (blockIdx.x * blockDim.x + threadIdx.x) >> 5;
    int lane = threadIdx.x & 31;
    if (w >= NN) return;
    int beg = g_rowptr[w], end = g_rowptr[w + 1];
    float2 acc = make_float2(0, 0);
    for (int e = beg; e < end; e++) {
        int s = __ldg(&g_adj[e]);
        float2 v = *reinterpret_cast<const float2*>(xp + (size_t)s * 64 + lane * 2);
        acc.x += v.x; acc.y += v.y;
    }
    float inv = 1.0f / fmaxf((float)(end - beg), 1.0f);
    *reinterpret_cast<float2*>(msg + (size_t)w * 64 + lane * 2) =
        make_float2(acc.x * inv, acc.y * inv);
}

// ---------------- pooling ----------------
__global__ void pool_kernel(const float* __restrict__ x, const int* __restrict__ batch) {
    int nwarps = (gridDim.x * blockDim.x) >> 5;
    int w = (blockIdx.x * blockDim.x + threadIdx.x) >> 5;
    int lane = threadIdx.x & 31;
    int per = (NN + nwarps - 1) / nwarps;
    int s = w * per;
    int e = min(NN, s + per);
    if (s >= e) return;
    float m0 = -__int_as_float(0x7f800000), m1 = m0;
    float s0 = 0.f, s1 = 0.f;
    int cnt = 0;
    int curg = __ldg(&batch[s]);
    for (int i = s; i < e; i++) {
        int g = __ldg(&batch[i]);
        if (g != curg) {
            atomicMax(&g_gmax[curg * 64 + lane], fenc(m0));
            atomicMax(&g_gmax[curg * 64 + lane + 32], fenc(m1));
            atomicAdd(&g_gsum[curg * 64 + lane], s0);
            atomicAdd(&g_gsum[curg * 64 + lane + 32], s1);
            if (lane == 0) atomicAdd(&g_gcnt[curg], cnt);
            m0 = m1 = -__int_as_float(0x7f800000);
            s0 = s1 = 0.f; cnt = 0; curg = g;
        }
        float v0 = x[(size_t)i * 64 + lane];
        float v1 = x[(size_t)i * 64 + lane + 32];
        m0 = fmaxf(m0, v0); m1 = fmaxf(m1, v1);
        s0 += v0; s1 += v1; cnt++;
    }
    atomicMax(&g_gmax[curg * 64 + lane], fenc(m0));
    atomicMax(&g_gmax[curg * 64 + lane + 32], fenc(m1));
    atomicAdd(&g_gsum[curg * 64 + lane], s0);
    atomicAdd(&g_gsum[curg * 64 + lane + 32], s1);
    if (lane == 0) atomicAdd(&g_gcnt[curg], cnt);
}

// ---------------- final ----------------
__global__ void final_kernel(const float* __restrict__ post_w, const float* __restrict__ post_b,
                             float* __restrict__ out) {
    int g = threadIdx.x;
    if (g >= NG) return;
    float inv = 1.0f / (float)g_gcnt[g];
    float v[64];
    float ss = 0.f;
#pragma unroll
    for (int c = 0; c < 64; c++) {
        float t = fdec(g_gmax[g * 64 + c]) + g_gsum[g * 64 + c] * inv;
        v[c] = t;
        ss += t * t;
    }
    float norm = sqrtf(ss);
    float dot = 0.f;
#pragma unroll
    for (int c = 0; c < 64; c++) dot += v[c] * post_w[c];
    out[g] = dot / norm + post_b[0];
}

// ---------------- launch ----------------
extern "C" void kernel_launch(void* const* d_in, const int* in_sizes, int n_in,
                              void* d_out, int out_size) {
    const float* node_feat = (const float*)d_in[0];
    const float* cfg_feat  = (const float*)d_in[1];
    const int*   opcode    = (const int*)d_in[2];
    const int*   edge      = (const int*)d_in[3];
    const int*   batch     = (const int*)d_in[4];
    const float* op_emb    = (const float*)d_in[5];
    const float* lin_w     = (const float*)d_in[6];
    const float* lin_b     = (const float*)d_in[7];
    const float* post_w    = (const float*)d_in[8];
    const float* post_b    = (const float*)d_in[9];
    const float* pw0 = (const float*)d_in[10];
    const float* pb0 = (const float*)d_in[11];
    const float* wl0 = (const float*)d_in[12];
    const float* bl0 = (const float*)d_in[13];
    const float* wr0 = (const float*)d_in[14];
    const float* pw1 = (const float*)d_in[15];
    const float* pb1 = (const float*)d_in[16];
    const float* wl1 = (const float*)d_in[17];
    const float* bl1 = (const float*)d_in[18];
    const float* wr1 = (const float*)d_in[19];
    const float* pw2 = (const float*)d_in[20];
    const float* pb2 = (const float*)d_in[21];
    const float* wl2 = (const float*)d_in[22];
    const float* bl2 = (const float*)d_in[23];
    const float* wr2 = (const float*)d_in[24];
    float* out = (float*)d_out;

    const int* src = edge;
    const int* dst = edge + NE;

    const int MB = (NN + 127) / 128;   // 782
    const int EB = (NE + 255) / 256;
    const int AGGB = (NN * 32 + 255) / 256;
    const size_t SMEM = 49152;         // 2x(16KB A + 8KB B) double-buffered frag tiles

    init_kernel<<<(NN + 255) / 256, 256>>>();
    hist_kernel<<<EB, 256>>>(dst);
    scan_kernel<<<1, 1024>>>();
    fill_adj_kernel<<<EB, 256>>>(src, dst);

    float* dA; cudaGetSymbolAddress((void**)&dA, g_xA);
    float* dB; cudaGetSymbolAddress((void**)&dB, g_xB);
    float* dP; cudaGetSymbolAddress((void**)&dP, g_xp);
    float* dM; cudaGetSymbolAddress((void**)&dM, g_msg);

    lin_frag<<<dim3(MB, 2), 256, SMEM>>>(node_feat, cfg_feat, opcode, op_emb, lin_w, lin_b, dA);

    // layer 0 (d=128 -> 64)
    proj_frag<128, 128><<<dim3(MB, 2), 256, SMEM>>>(dA, pw0, pb0, dP);
    agg_kernel128<<<AGGB, 256>>>(dP, dM);
    combine_frag<128><<<MB, 256, SMEM>>>(dM, dA, wl0, wr0, bl0, dB);

    // layer 1 (d=64 -> 64)
    proj_frag<64, 64><<<dim3(MB, 1), 256, SMEM>>>(dB, pw1, pb1, dP);
    agg_kernel64<<<AGGB, 256>>>(dP, dM);
    combine_frag<64><<<MB, 256, SMEM>>>(dM, dB, wl1, wr1, bl1, dA);

    // layer 2 (d=64 -> 64)
    proj_frag<64, 64><<<dim3(MB, 1), 256, SMEM>>>(dA, pw2, pb2, dP);
    agg_kernel64<<<AGGB, 256>>>(dP, dM);
    combine_frag<64><<<MB, 256, SMEM>>>(dM, dA, wl2, wr2, bl2, dB);

    pool_kernel<<<128, 256>>>(dB, batch);
    final_kernel<<<1, 64>>>(post_w, post_b, out);
}

// round 6
// speedup vs baseline: 1.7340x; 1.3448x over previous
#include <cuda_runtime.h>
#include <cstdint>

#define NN 100000
#define NE 1600000
#define NG 64

// ---------------- scratch ----------------
__device__ __align__(256) float g_xA[(size_t)NN * 128];
__device__ __align__(256) float g_xB[(size_t)NN * 128];
__device__ __align__(256) float g_xp[(size_t)NN * 128];
__device__ __align__(256) float g_msg[(size_t)NN * 128];
__device__ int g_deg[NN];
__device__ int g_cursor[NN];
__device__ int g_rowptr[NN + 1];
__device__ int g_adj[NE];
__device__ unsigned g_gmax[NG * 64];
__device__ float g_gsum[NG * 64];
__device__ int g_gcnt[NG];

// ---------------- helpers ----------------
__device__ __forceinline__ uint32_t f2tf(float f) {
    uint32_t r;
    asm("cvt.rna.tf32.f32 %0, %1;" : "=r"(r) : "f"(f));
    return r;
}
__device__ __forceinline__ void mma8(float* c, const uint32_t* a, const uint32_t* b) {
    asm volatile(
        "mma.sync.aligned.m16n8k8.row.col.f32.tf32.tf32.f32 "
        "{%0,%1,%2,%3}, {%4,%5,%6,%7}, {%8,%9}, {%0,%1,%2,%3};"
        : "+f"(c[0]), "+f"(c[1]), "+f"(c[2]), "+f"(c[3])
        : "r"(a[0]), "r"(a[1]), "r"(a[2]), "r"(a[3]), "r"(b[0]), "r"(b[1]));
}
__device__ __forceinline__ unsigned fenc(float f) {
    unsigned u = __float_as_uint(f);
    return (u & 0x80000000u) ? ~u : (u | 0x80000000u);
}
__device__ __forceinline__ float fdec(unsigned e) {
    return __uint_as_float((e & 0x80000000u) ? (e ^ 0x80000000u) : ~e);
}

// ---------------- XOR-swizzled tiles ----------------
// A tile 128x32 tf32 (4096 words): word = row*32 + 4*((col>>2) ^ (row&7)) + (col&3)
// B tile 32(k)x64(n) tf32 (2048 words), n-major: word = n*32 + 4*((k>>2) ^ (n&7)) + (k&3)

// stage A: thread's float4 = (row, cols 4*c4 .. 4*c4+3) -> one STS.128, conflict-free
__device__ __forceinline__ void stA(uint32_t* sA, int row, int c4, float4 v) {
    uint32_t* p = sA + row * 32 + 4 * (c4 ^ (row & 7));
    *reinterpret_cast<uint4*>(p) = make_uint4(f2tf(v.x), f2tf(v.y), f2tf(v.z), f2tf(v.w));
}
// stage B: thread's 4 k-consecutive weights for one n -> one STS.128, conflict-free
__device__ __forceinline__ void stB(uint32_t* sB, int k4, int n, const float* w) {
    uint32_t* p = sB + n * 32 + 4 * (k4 ^ (n & 7));
    *reinterpret_cast<uint4*>(p) = make_uint4(f2tf(w[0]), f2tf(w[1]), f2tf(w[2]), f2tf(w[3]));
}

// conflict-free fragment consumer (scalar LDS, all banks distinct per instr)
__device__ __forceinline__ void chunk_mma_frag(const uint32_t* sA, const uint32_t* sB,
                                               float acc[2][4][4], int warpM, int warpN, int lane) {
    const int qr = lane >> 2, qc = lane & 3;
#pragma unroll
    for (int ks = 0; ks < 4; ks++) {
        uint32_t a[2][4];
#pragma unroll
        for (int mt = 0; mt < 2; mt++) {
            int r0 = warpM * 32 + mt * 16 + qr;
            int r7 = r0 & 7;
            const uint32_t* b0 = sA + r0 * 32;
            const uint32_t* b1 = sA + (r0 + 8) * 32;
            a[mt][0] = b0[4 * ((2 * ks) ^ r7) + qc];
            a[mt][1] = b1[4 * ((2 * ks) ^ r7) + qc];
            a[mt][2] = b0[4 * ((2 * ks + 1) ^ r7) + qc];
            a[mt][3] = b1[4 * ((2 * ks + 1) ^ r7) + qc];
        }
#pragma unroll
        for (int nt = 0; nt < 4; nt++) {
            int n = warpN * 32 + nt * 8 + qr;
            const uint32_t* bb = sB + n * 32;
            uint32_t b[2] = { bb[4 * ((2 * ks) ^ qr) + qc], bb[4 * ((2 * ks + 1) ^ qr) + qc] };
#pragma unroll
            for (int mt = 0; mt < 2; mt++) mma8(acc[mt][nt], a[mt], b);
        }
    }
}

// ---------------- init ----------------
__global__ void init_kernel() {
    int j = blockIdx.x * blockDim.x + threadIdx.x;
    if (j < NN) { g_deg[j] = 0; g_cursor[j] = 0; }
    if (j < NG * 64) { g_gmax[j] = 0x007FFFFFu; g_gsum[j] = 0.f; }
    if (j < NG) g_gcnt[j] = 0;
}

// ---------------- CSR build ----------------
__global__ void hist_kernel(const int* __restrict__ dst) {
    int e = blockIdx.x * blockDim.x + threadIdx.x;
    if (e < NE) atomicAdd(&g_deg[dst[e]], 1);
}

__global__ void scan_kernel() {
    __shared__ int warpsum[32];
    __shared__ int carry;
    const int tid = threadIdx.x, lane = tid & 31, w = tid >> 5;
    if (tid == 0) carry = 0;
    __syncthreads();
    for (int base = 0; base < NN; base += 1024) {
        int i = base + tid;
        int v = (i < NN) ? g_deg[i] : 0;
        int s = v;
#pragma unroll
        for (int off = 1; off < 32; off <<= 1) {
            int t = __shfl_up_sync(0xffffffffu, s, off);
            if (lane >= off) s += t;
        }
        if (lane == 31) warpsum[w] = s;
        __syncthreads();
        if (w == 0) {
            int ws = warpsum[lane];
#pragma unroll
            for (int off = 1; off < 32; off <<= 1) {
                int t = __shfl_up_sync(0xffffffffu, ws, off);
                if (lane >= off) ws += t;
            }
            warpsum[lane] = ws;
        }
        __syncthreads();
        int pre = (w > 0) ? warpsum[w - 1] : 0;
        int incl = s + pre;
        if (i < NN) g_rowptr[i] = carry + incl - v;
        int tot = warpsum[31];
        __syncthreads();
        if (tid == 0) carry += tot;
        __syncthreads();
    }
    if (tid == 0) g_rowptr[NN] = carry;
}

__global__ void fill_adj_kernel(const int* __restrict__ src, const int* __restrict__ dst) {
    int e = blockIdx.x * blockDim.x + threadIdx.x;
    if (e < NE) {
        int d = dst[e];
        int p = atomicAdd(&g_cursor[d], 1);
        g_adj[g_rowptr[d] + p] = src[e];
    }
}

// ---------------- lin: C = relu(concat(nf,emb,cf) @ W + b), 64 cols per y-block ----------------
__global__ void __launch_bounds__(256)
lin_frag(const float* __restrict__ nf, const float* __restrict__ cf,
         const int* __restrict__ opc, const float* __restrict__ emb,
         const float* __restrict__ W, const float* __restrict__ bias,
         float* __restrict__ C) {
    extern __shared__ uint32_t smem[];
    const int tid = threadIdx.x, lane = tid & 31, wid = tid >> 5;
    const int warpM = wid & 3, warpN = wid >> 2;
    const int rowBase = blockIdx.x * 128;
    const int n0 = blockIdx.y * 64;

    float acc[2][4][4];
#pragma unroll
    for (int mt = 0; mt < 2; mt++)
#pragma unroll
        for (int nt = 0; nt < 4; nt++)
#pragma unroll
            for (int q = 0; q < 4; q++) acc[mt][nt][q] = 0.f;

    float4 ra[4];
    float rb[2][4];
    auto loadC = [&](int c) {
#pragma unroll
        for (int i = 0; i < 4; i++) {
            int e4 = tid + i * 256;
            int row = e4 >> 3, c4 = e4 & 7;
            int grow = rowBase + row;
            int k = c * 32 + c4 * 4;
            float4 v = make_float4(0, 0, 0, 0);
            if (grow < NN) {
                if (k < 140)      v = *(const float4*)(nf + (size_t)grow * 140 + k);
                else if (k < 172) v = *(const float4*)(emb + (size_t)opc[grow] * 32 + (k - 140));
                else {
                    const float* cp = cf + (size_t)grow * 18;
                    int off = k - 172;
                    v.x = (off + 0 < 18) ? cp[off + 0] : 0.f;
                    v.y = (off + 1 < 18) ? cp[off + 1] : 0.f;
                    v.z = (off + 2 < 18) ? cp[off + 2] : 0.f;
                    v.w = (off + 3 < 18) ? cp[off + 3] : 0.f;
                }
            }
            ra[i] = v;
        }
#pragma unroll
        for (int i = 0; i < 2; i++) {
            int idx = tid + i * 256;
            int n = idx & 63, k4 = idx >> 6;
#pragma unroll
            for (int j = 0; j < 4; j++) {
                int kg = c * 32 + k4 * 4 + j;
                rb[i][j] = (kg < 190) ? W[(size_t)kg * 128 + n0 + n] : 0.f;
            }
        }
    };
    auto stage = [&](int b) {
        uint32_t* sa = smem + (b ? 4096 : 0);
        uint32_t* sb = smem + 8192 + (b ? 2048 : 0);
#pragma unroll
        for (int i = 0; i < 4; i++) { int e4 = tid + i * 256; stA(sa, e4 >> 3, e4 & 7, ra[i]); }
#pragma unroll
        for (int i = 0; i < 2; i++) { int idx = tid + i * 256; stB(sb, idx >> 6, idx & 63, rb[i]); }
    };

    loadC(0); stage(0); __syncthreads();
#pragma unroll 1
    for (int c = 0; c < 6; c++) {
        if (c < 5) loadC(c + 1);
        const uint32_t* sa = smem + ((c & 1) ? 4096 : 0);
        const uint32_t* sb = smem + 8192 + ((c & 1) ? 2048 : 0);
        chunk_mma_frag(sa, sb, acc, warpM, warpN, lane);
        if (c < 5) { stage((c + 1) & 1); __syncthreads(); }
    }

    const int qr = lane >> 2, qc = lane & 3;
#pragma unroll
    for (int mt = 0; mt < 2; mt++) {
        int r0 = rowBase + warpM * 32 + mt * 16 + qr;
#pragma unroll
        for (int nt = 0; nt < 4; nt++) {
            int gc = n0 + warpN * 32 + nt * 8 + qc * 2;
            float b0 = __ldg(&bias[gc]), b1 = __ldg(&bias[gc + 1]);
            if (r0 < NN) {
                float2 o = { fmaxf(acc[mt][nt][0] + b0, 0.f), fmaxf(acc[mt][nt][1] + b1, 0.f) };
                *(float2*)(C + (size_t)r0 * 128 + gc) = o;
            }
            if (r0 + 8 < NN) {
                float2 o = { fmaxf(acc[mt][nt][2] + b0, 0.f), fmaxf(acc[mt][nt][3] + b1, 0.f) };
                *(float2*)(C + (size_t)(r0 + 8) * 128 + gc) = o;
            }
        }
    }
}

// ---------------- proj: C = relu(A @ W + b), 64 cols per y-block ----------------
template <int K, int NDIM>
__global__ void __launch_bounds__(256)
proj_frag(const float* __restrict__ A, const float* __restrict__ W,
          const float* __restrict__ bias, float* __restrict__ C) {
    constexpr int NCH = K / 32;
    extern __shared__ uint32_t smem[];
    const int tid = threadIdx.x, lane = tid & 31, wid = tid >> 5;
    const int warpM = wid & 3, warpN = wid >> 2;
    const int rowBase = blockIdx.x * 128;
    const int n0 = blockIdx.y * 64;

    float acc[2][4][4];
#pragma unroll
    for (int mt = 0; mt < 2; mt++)
#pragma unroll
        for (int nt = 0; nt < 4; nt++)
#pragma unroll
            for (int q = 0; q < 4; q++) acc[mt][nt][q] = 0.f;

    float4 ra[4];
    float rb[2][4];
    auto loadC = [&](int c) {
#pragma unroll
        for (int i = 0; i < 4; i++) {
            int e4 = tid + i * 256;
            int row = e4 >> 3, c4 = e4 & 7;
            int grow = rowBase + row;
            ra[i] = (grow < NN) ? *(const float4*)(A + (size_t)grow * K + c * 32 + c4 * 4)
                                : make_float4(0, 0, 0, 0);
        }
#pragma unroll
        for (int i = 0; i < 2; i++) {
            int idx = tid + i * 256;
            int n = idx & 63, k4 = idx >> 6;
#pragma unroll
            for (int j = 0; j < 4; j++)
                rb[i][j] = W[(size_t)(c * 32 + k4 * 4 + j) * NDIM + n0 + n];
        }
    };
    auto stage = [&](int b) {
        uint32_t* sa = smem + (b ? 4096 : 0);
        uint32_t* sb = smem + 8192 + (b ? 2048 : 0);
#pragma unroll
        for (int i = 0; i < 4; i++) { int e4 = tid + i * 256; stA(sa, e4 >> 3, e4 & 7, ra[i]); }
#pragma unroll
        for (int i = 0; i < 2; i++) { int idx = tid + i * 256; stB(sb, idx >> 6, idx & 63, rb[i]); }
    };

    loadC(0); stage(0); __syncthreads();
#pragma unroll 1
    for (int c = 0; c < NCH; c++) {
        if (c + 1 < NCH) loadC(c + 1);
        const uint32_t* sa = smem + ((c & 1) ? 4096 : 0);
        const uint32_t* sb = smem + 8192 + ((c & 1) ? 2048 : 0);
        chunk_mma_frag(sa, sb, acc, warpM, warpN, lane);
        if (c + 1 < NCH) { stage((c + 1) & 1); __syncthreads(); }
    }

    const int qr = lane >> 2, qc = lane & 3;
#pragma unroll
    for (int mt = 0; mt < 2; mt++) {
        int r0 = rowBase + warpM * 32 + mt * 16 + qr;
#pragma unroll
        for (int nt = 0; nt < 4; nt++) {
            int gc = n0 + warpN * 32 + nt * 8 + qc * 2;
            float b0 = __ldg(&bias[gc]), b1 = __ldg(&bias[gc + 1]);
            if (r0 < NN) {
                float2 o = { fmaxf(acc[mt][nt][0] + b0, 0.f), fmaxf(acc[mt][nt][1] + b1, 0.f) };
                *(float2*)(C + (size_t)r0 * NDIM + gc) = o;
            }
            if (r0 + 8 < NN) {
                float2 o = { fmaxf(acc[mt][nt][2] + b0, 0.f), fmaxf(acc[mt][nt][3] + b1, 0.f) };
                *(float2*)(C + (size_t)(r0 + 8) * NDIM + gc) = o;
            }
        }
    }
}

// ---------------- combine: C = normalize(M@Wl + X@Wr + bl), N=64 ----------------
template <int K>
__global__ void __launch_bounds__(256)
combine_frag(const float* __restrict__ M, const float* __restrict__ X,
             const float* __restrict__ Wl, const float* __restrict__ Wr,
             const float* __restrict__ bl, float* __restrict__ C) {
    constexpr int NCH = K / 32, TCH = 2 * NCH;
    extern __shared__ uint32_t smem[];
    const int tid = threadIdx.x, lane = tid & 31, wid = tid >> 5;
    const int warpM = wid & 3, warpN = wid >> 2;
    const int rowBase = blockIdx.x * 128;

    float acc[2][4][4];
#pragma unroll
    for (int mt = 0; mt < 2; mt++)
#pragma unroll
        for (int nt = 0; nt < 4; nt++)
#pragma unroll
            for (int q = 0; q < 4; q++) acc[mt][nt][q] = 0.f;

    float4 ra[4];
    float rb[2][4];
    auto loadC = [&](int c) {
        const float* Ap = (c < NCH) ? M : X;
        const float* Bp = (c < NCH) ? Wl : Wr;
        int k0 = (c < NCH ? c : c - NCH) * 32;
#pragma unroll
        for (int i = 0; i < 4; i++) {
            int e4 = tid + i * 256;
            int row = e4 >> 3, c4 = e4 & 7;
            int grow = rowBase + row;
            ra[i] = (grow < NN) ? *(const float4*)(Ap + (size_t)grow * K + k0 + c4 * 4)
                                : make_float4(0, 0, 0, 0);
        }
#pragma unroll
        for (int i = 0; i < 2; i++) {
            int idx = tid + i * 256;
            int n = idx & 63, k4 = idx >> 6;
#pragma unroll
            for (int j = 0; j < 4; j++)
                rb[i][j] = Bp[(size_t)(k0 + k4 * 4 + j) * 64 + n];
        }
    };
    auto stage = [&](int b) {
        uint32_t* sa = smem + (b ? 4096 : 0);
        uint32_t* sb = smem + 8192 + (b ? 2048 : 0);
#pragma unroll
        for (int i = 0; i < 4; i++) { int e4 = tid + i * 256; stA(sa, e4 >> 3, e4 & 7, ra[i]); }
#pragma unroll
        for (int i = 0; i < 2; i++) { int idx = tid + i * 256; stB(sb, idx >> 6, idx & 63, rb[i]); }
    };

    loadC(0); stage(0); __syncthreads();
#pragma unroll 1
    for (int c = 0; c < TCH; c++) {
        if (c + 1 < TCH) loadC(c + 1);
        const uint32_t* sa = smem + ((c & 1) ? 4096 : 0);
        const uint32_t* sb = smem + 8192 + ((c & 1) ? 2048 : 0);
        chunk_mma_frag(sa, sb, acc, warpM, warpN, lane);
        if (c + 1 < TCH) { stage((c + 1) & 1); __syncthreads(); }
    }

    // stage outputs + row L2-normalize (overlay on the smem buffers)
    __syncthreads();
    float (*sOut)[65] = reinterpret_cast<float(*)[65]>(smem);
    const int qr = lane >> 2, qc = lane & 3;
#pragma unroll
    for (int mt = 0; mt < 2; mt++) {
        int r0 = warpM * 32 + mt * 16 + qr;
#pragma unroll
        for (int nt = 0; nt < 4; nt++) {
            int cl = warpN * 32 + nt * 8 + qc * 2;
            float b0 = __ldg(&bl[cl]), b1 = __ldg(&bl[cl + 1]);
            sOut[r0][cl]         = acc[mt][nt][0] + b0;
            sOut[r0][cl + 1]     = acc[mt][nt][1] + b1;
            sOut[r0 + 8][cl]     = acc[mt][nt][2] + b0;
            sOut[r0 + 8][cl + 1] = acc[mt][nt][3] + b1;
        }
    }
    __syncthreads();
#pragma unroll
    for (int rr = 0; rr < 16; rr++) {
        int r = wid * 16 + rr;
        int grow = rowBase + r;
        float v0 = sOut[r][lane];
        float v1 = sOut[r][lane + 32];
        float ss = v0 * v0 + v1 * v1;
#pragma unroll
        for (int o = 16; o > 0; o >>= 1) ss += __shfl_xor_sync(0xffffffffu, ss, o);
        float sc = 1.0f / fmaxf(sqrtf(ss), 1e-12f);
        if (grow < NN) {
            C[(size_t)grow * 64 + lane] = v0 * sc;
            C[(size_t)grow * 64 + lane + 32] = v1 * sc;
        }
    }
}

// ---------------- mean aggregation over CSR ----------------
__global__ void agg_kernel128(const float* __restrict__ xp, float* __restrict__ msg) {
    int w = (blockIdx.x * blockDim.x + threadIdx.x) >> 5;
    int lane = threadIdx.x & 31;
    if (w >= NN) return;
    int beg = g_rowptr[w], end = g_rowptr[w + 1];
    float4 acc = make_float4(0, 0, 0, 0);
    for (int e = beg; e < end; e++) {
        int s = __ldg(&g_adj[e]);
        float4 v = *reinterpret_cast<const float4*>(xp + (size_t)s * 128 + lane * 4);
        acc.x += v.x; acc.y += v.y; acc.z += v.z; acc.w += v.w;
    }
    float inv = 1.0f / fmaxf((float)(end - beg), 1.0f);
    *reinterpret_cast<float4*>(msg + (size_t)w * 128 + lane * 4) =
        make_float4(acc.x * inv, acc.y * inv, acc.z * inv, acc.w * inv);
}

__global__ void agg_kernel64(const float* __restrict__ xp, float* __restrict__ msg) {
    int w = (blockIdx.x * blockDim.x + threadIdx.x) >> 5;
    int lane = threadIdx.x & 31;
    if (w >= NN) return;
    int beg = g_rowptr[w], end = g_rowptr[w + 1];
    float2 acc = make_float2(0, 0);
    for (int e = beg; e < end; e++) {
        int s = __ldg(&g_adj[e]);
        float2 v = *reinterpret_cast<const float2*>(xp + (size_t)s * 64 + lane * 2);
        acc.x += v.x; acc.y += v.y;
    }
    float inv = 1.0f / fmaxf((float)(end - beg), 1.0f);
    *reinterpret_cast<float2*>(msg + (size_t)w * 64 + lane * 2) =
        make_float2(acc.x * inv, acc.y * inv);
}

// ---------------- pooling ----------------
__global__ void pool_kernel(const float* __restrict__ x, const int* __restrict__ batch) {
    int nwarps = (gridDim.x * blockDim.x) >> 5;
    int w = (blockIdx.x * blockDim.x + threadIdx.x) >> 5;
    int lane = threadIdx.x & 31;
    int per = (NN + nwarps - 1) / nwarps;
    int s = w * per;
    int e = min(NN, s + per);
    if (s >= e) return;
    float m0 = -__int_as_float(0x7f800000), m1 = m0;
    float s0 = 0.f, s1 = 0.f;
    int cnt = 0;
    int curg = __ldg(&batch[s]);
    for (int i = s; i < e; i++) {
        int g = __ldg(&batch[i]);
        if (g != curg) {
            atomicMax(&g_gmax[curg * 64 + lane], fenc(m0));
            atomicMax(&g_gmax[curg * 64 + lane + 32], fenc(m1));
            atomicAdd(&g_gsum[curg * 64 + lane], s0);
            atomicAdd(&g_gsum[curg * 64 + lane + 32], s1);
            if (lane == 0) atomicAdd(&g_gcnt[curg], cnt);
            m0 = m1 = -__int_as_float(0x7f800000);
            s0 = s1 = 0.f; cnt = 0; curg = g;
        }
        float v0 = x[(size_t)i * 64 + lane];
        float v1 = x[(size_t)i * 64 + lane + 32];
        m0 = fmaxf(m0, v0); m1 = fmaxf(m1, v1);
        s0 += v0; s1 += v1; cnt++;
    }
    atomicMax(&g_gmax[curg * 64 + lane], fenc(m0));
    atomicMax(&g_gmax[curg * 64 + lane + 32], fenc(m1));
    atomicAdd(&g_gsum[curg * 64 + lane], s0);
    atomicAdd(&g_gsum[curg * 64 + lane + 32], s1);
    if (lane == 0) atomicAdd(&g_gcnt[curg], cnt);
}

// ---------------- final ----------------
__global__ void final_kernel(const float* __restrict__ post_w, const float* __restrict__ post_b,
                             float* __restrict__ out) {
    int g = threadIdx.x;
    if (g >= NG) return;
    float inv = 1.0f / (float)g_gcnt[g];
    float v[64];
    float ss = 0.f;
#pragma unroll
    for (int c = 0; c < 64; c++) {
        float t = fdec(g_gmax[g * 64 + c]) + g_gsum[g * 64 + c] * inv;
        v[c] = t;
        ss += t * t;
    }
    float norm = sqrtf(ss);
    float dot = 0.f;
#pragma unroll
    for (int c = 0; c < 64; c++) dot += v[c] * post_w[c];
    out[g] = dot / norm + post_b[0];
}

// ---------------- launch ----------------
extern "C" void kernel_launch(void* const* d_in, const int* in_sizes, int n_in,
                              void* d_out, int out_size) {
    const float* node_feat = (const float*)d_in[0];
    const float* cfg_feat  = (const float*)d_in[1];
    const int*   opcode    = (const int*)d_in[2];
    const int*   edge      = (const int*)d_in[3];
    const int*   batch     = (const int*)d_in[4];
    const float* op_emb    = (const float*)d_in[5];
    const float* lin_w     = (const float*)d_in[6];
    const float* lin_b     = (const float*)d_in[7];
    const float* post_w    = (const float*)d_in[8];
    const float* post_b    = (const float*)d_in[9];
    const float* pw0 = (const float*)d_in[10];
    const float* pb0 = (const float*)d_in[11];
    const float* wl0 = (const float*)d_in[12];
    const float* bl0 = (const float*)d_in[13];
    const float* wr0 = (const float*)d_in[14];
    const float* pw1 = (const float*)d_in[15];
    const float* pb1 = (const float*)d_in[16];
    const float* wl1 = (const float*)d_in[17];
    const float* bl1 = (const float*)d_in[18];
    const float* wr1 = (const float*)d_in[19];
    const float* pw2 = (const float*)d_in[20];
    const float* pb2 = (const float*)d_in[21];
    const float* wl2 = (const float*)d_in[22];
    const float* bl2 = (const float*)d_in[23];
    const float* wr2 = (const float*)d_in[24];
    float* out = (float*)d_out;

    const int* src = edge;
    const int* dst = edge + NE;

    const int MB = (NN + 127) / 128;   // 782
    const int EB = (NE + 255) / 256;
    const int AGGB = (NN * 32 + 255) / 256;
    const size_t SMEM = 49152;         // 2x(16KB A + 8KB B) double-buffered tiles

    init_kernel<<<(NN + 255) / 256, 256>>>();
    hist_kernel<<<EB, 256>>>(dst);
    scan_kernel<<<1, 1024>>>();
    fill_adj_kernel<<<EB, 256>>>(src, dst);

    float* dA; cudaGetSymbolAddress((void**)&dA, g_xA);
    float* dB; cudaGetSymbolAddress((void**)&dB, g_xB);
    float* dP; cudaGetSymbolAddress((void**)&dP, g_xp);
    float* dM; cudaGetSymbolAddress((void**)&dM, g_msg);

    lin_frag<<<dim3(MB, 2), 256, SMEM>>>(node_feat, cfg_feat, opcode, op_emb, lin_w, lin_b, dA);

    // layer 0 (d=128 -> 64)
    proj_frag<128, 128><<<dim3(MB, 2), 256, SMEM>>>(dA, pw0, pb0, dP);
    agg_kernel128<<<AGGB, 256>>>(dP, dM);
    combine_frag<128><<<MB, 256, SMEM>>>(dM, dA, wl0, wr0, bl0, dB);

    // layer 1 (d=64 -> 64)
    proj_frag<64, 64><<<dim3(MB, 1), 256, SMEM>>>(dB, pw1, pb1, dP);
    agg_kernel64<<<AGGB, 256>>>(dP, dM);
    combine_frag<64><<<MB, 256, SMEM>>>(dM, dB, wl1, wr1, bl1, dA);

    // layer 2 (d=64 -> 64)
    proj_frag<64, 64><<<dim3(MB, 1), 256, SMEM>>>(dA, pw2, pb2, dP);
    agg_kernel64<<<AGGB, 256>>>(dP, dM);
    combine_frag<64><<<MB, 256, SMEM>>>(dM, dA, wl2, wr2, bl2, dB);

    pool_kernel<<<128, 256>>>(dB, batch);
    final_kernel<<<1, 64>>>(post_w, post_b, out);
}

// round 7
// speedup vs baseline: 1.9670x; 1.1343x over previous
#include <cuda_runtime.h>
#include <cstdint>

#define NN 100000
#define NE 1600000
#define NG 64
#define NBLK 98   // ceil(NN/1024)

// ---------------- scratch ----------------
__device__ __align__(256) float g_xA[(size_t)NN * 128];
__device__ __align__(256) float g_xB[(size_t)NN * 128];
__device__ __align__(256) float g_xp[(size_t)NN * 128];
__device__ __align__(256) float g_msg[(size_t)NN * 128];
__device__ int g_deg[NN];
__device__ int g_cursor[NN];
__device__ int g_rowptr[NN + 1];
__device__ int g_adj[NE];
__device__ int g_bsum[NBLK];
__device__ int g_boff[NBLK];
__device__ unsigned g_gmax[NG * 64];
__device__ float g_gsum[NG * 64];
__device__ int g_gcnt[NG];

// ---------------- helpers ----------------
__device__ __forceinline__ uint32_t f2tf(float f) {
    uint32_t r;
    asm("cvt.rna.tf32.f32 %0, %1;" : "=r"(r) : "f"(f));
    return r;
}
__device__ __forceinline__ void mma8(float* c, const uint32_t* a, const uint32_t* b) {
    asm volatile(
        "mma.sync.aligned.m16n8k8.row.col.f32.tf32.tf32.f32 "
        "{%0,%1,%2,%3}, {%4,%5,%6,%7}, {%8,%9}, {%0,%1,%2,%3};"
        : "+f"(c[0]), "+f"(c[1]), "+f"(c[2]), "+f"(c[3])
        : "r"(a[0]), "r"(a[1]), "r"(a[2]), "r"(a[3]), "r"(b[0]), "r"(b[1]));
}
__device__ __forceinline__ unsigned fenc(float f) {
    unsigned u = __float_as_uint(f);
    return (u & 0x80000000u) ? ~u : (u | 0x80000000u);
}
__device__ __forceinline__ float fdec(unsigned e) {
    return __uint_as_float((e & 0x80000000u) ? (e ^ 0x80000000u) : ~e);
}

// ---------------- XOR-swizzled tiles ----------------
// A tile 128x32 tf32 (4096 words): word = row*32 + 4*((col>>2) ^ (row&7)) + (col&3)
// B tile 32(k) x N(n) tf32 (N*32 words), n-major: word = n*32 + 4*((k>>2) ^ (n&7)) + (k&3)
__device__ __forceinline__ void stA(uint32_t* sA, int row, int c4, float4 v) {
    uint32_t* p = sA + row * 32 + 4 * (c4 ^ (row & 7));
    *reinterpret_cast<uint4*>(p) = make_uint4(f2tf(v.x), f2tf(v.y), f2tf(v.z), f2tf(v.w));
}
__device__ __forceinline__ void stB(uint32_t* sB, int k4, int n, const float* w) {
    uint32_t* p = sB + n * 32 + 4 * (k4 ^ (n & 7));
    *reinterpret_cast<uint4*>(p) = make_uint4(f2tf(w[0]), f2tf(w[1]), f2tf(w[2]), f2tf(w[3]));
}
// 2-wide store into chunked A tiles (4096 words each), col may span chunks
__device__ __forceinline__ void stA2(uint32_t* sX, int row, int col, float x, float y) {
    uint32_t* t = sX + (col >> 5) * 4096;
    uint32_t* p = t + row * 32 + 4 * (((col & 31) >> 2) ^ (row & 7)) + (col & 3);
    p[0] = f2tf(x);
    p[1] = f2tf(y);
}

// generalized conflict-free fragment consumer over one 128x32 A tile, B tile 32xN
template <int NT>
__device__ __forceinline__ void chunk_mma_g(const uint32_t* sA, const uint32_t* sB,
                                            float (&acc)[2][NT][4], int rowB, int colB, int lane) {
    const int qr = lane >> 2, qc = lane & 3;
#pragma unroll
    for (int ks = 0; ks < 4; ks++) {
        uint32_t a[2][4];
#pragma unroll
        for (int mt = 0; mt < 2; mt++) {
            int r0 = rowB + mt * 16 + qr;
            int r7 = r0 & 7;
            const uint32_t* b0 = sA + r0 * 32;
            const uint32_t* b1 = sA + (r0 + 8) * 32;
            a[mt][0] = b0[4 * ((2 * ks) ^ r7) + qc];
            a[mt][1] = b1[4 * ((2 * ks) ^ r7) + qc];
            a[mt][2] = b0[4 * ((2 * ks + 1) ^ r7) + qc];
            a[mt][3] = b1[4 * ((2 * ks + 1) ^ r7) + qc];
        }
#pragma unroll
        for (int nt = 0; nt < NT; nt++) {
            int n = colB + nt * 8 + qr;
            const uint32_t* bb = sB + n * 32;
            uint32_t b[2] = { bb[4 * ((2 * ks) ^ qr) + qc], bb[4 * ((2 * ks + 1) ^ qr) + qc] };
#pragma unroll
            for (int mt = 0; mt < 2; mt++) mma8(acc[mt][nt], a[mt], b);
        }
    }
}

// ---------------- init ----------------
__global__ void init_kernel() {
    int j = blockIdx.x * blockDim.x + threadIdx.x;
    if (j < NN) { g_deg[j] = 0; g_cursor[j] = 0; }
    if (j < NG * 64) { g_gmax[j] = 0x007FFFFFu; g_gsum[j] = 0.f; }
    if (j < NG) g_gcnt[j] = 0;
}

// ---------------- CSR build ----------------
__global__ void hist_kernel(const int* __restrict__ dst) {
    int e = blockIdx.x * blockDim.x + threadIdx.x;
    if (e < NE) atomicAdd(&g_deg[dst[e]], 1);
}

__global__ void scan1_kernel() {  // grid NBLK, 256 thr: per-1024-block sums
    __shared__ int wsum[8];
    int b = blockIdx.x, tid = threadIdx.x, lane = tid & 31, w = tid >> 5;
    int i0 = b * 1024 + tid * 4;
    int s = 0;
#pragma unroll
    for (int j = 0; j < 4; j++) { int i = i0 + j; if (i < NN) s += g_deg[i]; }
#pragma unroll
    for (int o = 16; o > 0; o >>= 1) s += __shfl_xor_sync(0xffffffffu, s, o);
    if (lane == 0) wsum[w] = s;
    __syncthreads();
    if (tid == 0) {
        int t = 0;
#pragma unroll
        for (int k = 0; k < 8; k++) t += wsum[k];
        g_bsum[b] = t;
    }
}

__global__ void scan2_kernel() {  // 1 block: exclusive scan of block sums
    if (threadIdx.x == 0) {
        int run = 0;
        for (int k = 0; k < NBLK; k++) { int v = g_bsum[k]; g_boff[k] = run; run += v; }
        g_rowptr[NN] = run;
    }
}

__global__ void scan3_kernel() {  // grid NBLK: write exclusive prefix
    __shared__ int wsum[8];
    int b = blockIdx.x, tid = threadIdx.x, lane = tid & 31, w = tid >> 5;
    int i0 = b * 1024 + tid * 4;
    int v[4], s = 0;
#pragma unroll
    for (int j = 0; j < 4; j++) { int i = i0 + j; v[j] = (i < NN) ? g_deg[i] : 0; s += v[j]; }
    int si = s;
#pragma unroll
    for (int o = 1; o < 32; o <<= 1) { int t = __shfl_up_sync(0xffffffffu, si, o); if (lane >= o) si += t; }
    if (lane == 31) wsum[w] = si;
    __syncthreads();
    if (tid == 0) {
        int run = 0;
#pragma unroll
        for (int k = 0; k < 8; k++) { int t = wsum[k]; wsum[k] = run; run += t; }
    }
    __syncthreads();
    int off = g_boff[b] + wsum[w] + (si - s);
#pragma unroll
    for (int j = 0; j < 4; j++) { int i = i0 + j; if (i < NN) g_rowptr[i] = off; off += v[j]; }
}

__global__ void fill_adj_kernel(const int* __restrict__ src, const int* __restrict__ dst) {
    int e = blockIdx.x * blockDim.x + threadIdx.x;
    if (e < NE) {
        int d = dst[e];
        int p = atomicAdd(&g_cursor[d], 1);
        g_adj[g_rowptr[d] + p] = src[e];
    }
}

// ---------------- lin: C = relu(concat(nf,emb,cf) @ W + b), 64 cols per y-block ----------------
__global__ void __launch_bounds__(256)
lin_frag(const float* __restrict__ nf, const float* __restrict__ cf,
         const int* __restrict__ opc, const float* __restrict__ emb,
         const float* __restrict__ W, const float* __restrict__ bias,
         float* __restrict__ C) {
    extern __shared__ uint32_t smem[];
    const int tid = threadIdx.x, lane = tid & 31, wid = tid >> 5;
    const int warpM = wid & 3, warpN = wid >> 2;
    const int rowBase = blockIdx.x * 128;
    const int n0 = blockIdx.y * 64;

    float acc[2][4][4];
#pragma unroll
    for (int mt = 0; mt < 2; mt++)
#pragma unroll
        for (int nt = 0; nt < 4; nt++)
#pragma unroll
            for (int q = 0; q < 4; q++) acc[mt][nt][q] = 0.f;

    float4 ra[4];
    float rb[2][4];
    auto loadC = [&](int c) {
#pragma unroll
        for (int i = 0; i < 4; i++) {
            int e4 = tid + i * 256;
            int row = e4 >> 3, c4 = e4 & 7;
            int grow = rowBase + row;
            int k = c * 32 + c4 * 4;
            float4 v = make_float4(0, 0, 0, 0);
            if (grow < NN) {
                if (k < 140)      v = *(const float4*)(nf + (size_t)grow * 140 + k);
                else if (k < 172) v = *(const float4*)(emb + (size_t)opc[grow] * 32 + (k - 140));
                else {
                    const float* cp = cf + (size_t)grow * 18;
                    int off = k - 172;
                    v.x = (off + 0 < 18) ? cp[off + 0] : 0.f;
                    v.y = (off + 1 < 18) ? cp[off + 1] : 0.f;
                    v.z = (off + 2 < 18) ? cp[off + 2] : 0.f;
                    v.w = (off + 3 < 18) ? cp[off + 3] : 0.f;
                }
            }
            ra[i] = v;
        }
#pragma unroll
        for (int i = 0; i < 2; i++) {
            int idx = tid + i * 256;
            int n = idx & 63, k4 = idx >> 6;
#pragma unroll
            for (int j = 0; j < 4; j++) {
                int kg = c * 32 + k4 * 4 + j;
                rb[i][j] = (kg < 190) ? W[(size_t)kg * 128 + n0 + n] : 0.f;
            }
        }
    };
    auto stage = [&](int b) {
        uint32_t* sa = smem + (b ? 4096 : 0);
        uint32_t* sb = smem + 8192 + (b ? 2048 : 0);
#pragma unroll
        for (int i = 0; i < 4; i++) { int e4 = tid + i * 256; stA(sa, e4 >> 3, e4 & 7, ra[i]); }
#pragma unroll
        for (int i = 0; i < 2; i++) { int idx = tid + i * 256; stB(sb, idx >> 6, idx & 63, rb[i]); }
    };

    loadC(0); stage(0); __syncthreads();
#pragma unroll 1
    for (int c = 0; c < 6; c++) {
        if (c < 5) loadC(c + 1);
        const uint32_t* sa = smem + ((c & 1) ? 4096 : 0);
        const uint32_t* sb = smem + 8192 + ((c & 1) ? 2048 : 0);
        chunk_mma_g<4>(sa, sb, acc, warpM * 32, warpN * 32, lane);
        if (c < 5) { stage((c + 1) & 1); __syncthreads(); }
    }

    const int qr = lane >> 2, qc = lane & 3;
#pragma unroll
    for (int mt = 0; mt < 2; mt++) {
        int r0 = rowBase + warpM * 32 + mt * 16 + qr;
#pragma unroll
        for (int nt = 0; nt < 4; nt++) {
            int gc = n0 + warpN * 32 + nt * 8 + qc * 2;
            float b0 = __ldg(&bias[gc]), b1 = __ldg(&bias[gc + 1]);
            if (r0 < NN) {
                float2 o = { fmaxf(acc[mt][nt][0] + b0, 0.f), fmaxf(acc[mt][nt][1] + b1, 0.f) };
                *(float2*)(C + (size_t)r0 * 128 + gc) = o;
            }
            if (r0 + 8 < NN) {
                float2 o = { fmaxf(acc[mt][nt][2] + b0, 0.f), fmaxf(acc[mt][nt][3] + b1, 0.f) };
                *(float2*)(C + (size_t)(r0 + 8) * 128 + gc) = o;
            }
        }
    }
}

// ---------------- projz: Z = relu(A@PW + PB) @ WL   (A: NNxK, PW: KxK, WL: Kx64) ----------------
template <int K>
__global__ void __launch_bounds__(256)
projz(const float* __restrict__ A, const float* __restrict__ PW,
      const float* __restrict__ PB, const float* __restrict__ WL,
      float* __restrict__ Z) {
    constexpr int NCH = K / 32;      // chunks for both phases
    constexpr int CW = K / 2;        // phase-1 per-warp cols
    constexpr int NT1 = CW / 8;      // 8 (K=128) or 4 (K=64)
    constexpr int INB = K * 32;      // B tile words
    constexpr int INW = 8192 + 2 * INB;
    constexpr int XW = NCH * 4096;
    constexpr int UW = (INW > XW) ? INW : XW;
    extern __shared__ uint32_t smem[];
    uint32_t* W2 = smem + UW;        // NCH * 2048 words (WL tiles)

    const int tid = threadIdx.x, lane = tid & 31, wid = tid >> 5;
    const int warpM = wid & 3, warpN = wid >> 2;
    const int rowBase = blockIdx.x * 128;
    const int qr = lane >> 2, qc = lane & 3;

    // stage WL chunks once
#pragma unroll
    for (int c = 0; c < NCH; c++)
#pragma unroll
        for (int i = 0; i < 2; i++) {
            int idx = tid + i * 256;
            int n = idx & 63, k4 = idx >> 6;
            float w[4];
#pragma unroll
            for (int j = 0; j < 4; j++) w[j] = WL[(size_t)(c * 32 + k4 * 4 + j) * 64 + n];
            stB(W2 + c * 2048, k4, n, w);
        }

    // ---- phase 1: xp = A @ PW ----
    float acc1[2][NT1][4];
#pragma unroll
    for (int mt = 0; mt < 2; mt++)
#pragma unroll
        for (int nt = 0; nt < NT1; nt++)
#pragma unroll
            for (int q = 0; q < 4; q++) acc1[mt][nt][q] = 0.f;

    float4 ra[4];
    float rb[4][4];
    auto loadC = [&](int c) {
#pragma unroll
        for (int i = 0; i < 4; i++) {
            int e4 = tid + i * 256;
            int row = e4 >> 3, c4 = e4 & 7;
            int grow = rowBase + row;
            ra[i] = (grow < NN) ? *(const float4*)(A + (size_t)grow * K + c * 32 + c4 * 4)
                                : make_float4(0, 0, 0, 0);
        }
#pragma unroll
        for (int i = 0; i < NCH; i++) {
            int idx = tid + i * 256;
            int n = idx & (K - 1), k4 = idx / K;
#pragma unroll
            for (int j = 0; j < 4; j++)
                rb[i][j] = PW[(size_t)(c * 32 + k4 * 4 + j) * K + n];
        }
    };
    auto stage = [&](int b) {
        uint32_t* sa = smem + (b ? 4096 : 0);
        uint32_t* sb = smem + 8192 + (b ? INB : 0);
#pragma unroll
        for (int i = 0; i < 4; i++) { int e4 = tid + i * 256; stA(sa, e4 >> 3, e4 & 7, ra[i]); }
#pragma unroll
        for (int i = 0; i < NCH; i++) {
            int idx = tid + i * 256;
            stB(sb, idx / K, idx & (K - 1), rb[i]);
        }
    };

    loadC(0); stage(0); __syncthreads();
#pragma unroll 1
    for (int c = 0; c < NCH; c++) {
        if (c + 1 < NCH) loadC(c + 1);
        const uint32_t* sa = smem + ((c & 1) ? 4096 : 0);
        const uint32_t* sb = smem + 8192 + ((c & 1) ? INB : 0);
        chunk_mma_g<NT1>(sa, sb, acc1, warpM * 32, warpN * CW, lane);
        if (c + 1 < NCH) { stage((c + 1) & 1); __syncthreads(); }
    }
    __syncthreads();  // phase-1 smem reads complete before overwrite

    // ---- restage xp = relu(acc1 + PB) into X tiles at smem[0..XW) ----
#pragma unroll
    for (int mt = 0; mt < 2; mt++) {
        int r0 = warpM * 32 + mt * 16 + qr;
#pragma unroll
        for (int nt = 0; nt < NT1; nt++) {
            int col = warpN * CW + nt * 8 + qc * 2;
            float b0 = __ldg(&PB[col]), b1 = __ldg(&PB[col + 1]);
            stA2(smem, r0, col, fmaxf(acc1[mt][nt][0] + b0, 0.f), fmaxf(acc1[mt][nt][1] + b1, 0.f));
            stA2(smem, r0 + 8, col, fmaxf(acc1[mt][nt][2] + b0, 0.f), fmaxf(acc1[mt][nt][3] + b1, 0.f));
        }
    }
    __syncthreads();

    // ---- phase 2: Z = xp @ WL ----
    float acc2[2][4][4];
#pragma unroll
    for (int mt = 0; mt < 2; mt++)
#pragma unroll
        for (int nt = 0; nt < 4; nt++)
#pragma unroll
            for (int q = 0; q < 4; q++) acc2[mt][nt][q] = 0.f;
#pragma unroll
    for (int c = 0; c < NCH; c++)
        chunk_mma_g<4>(smem + c * 4096, W2 + c * 2048, acc2, warpM * 32, warpN * 32, lane);

#pragma unroll
    for (int mt = 0; mt < 2; mt++) {
        int r0 = rowBase + warpM * 32 + mt * 16 + qr;
#pragma unroll
        for (int nt = 0; nt < 4; nt++) {
            int gc = warpN * 32 + nt * 8 + qc * 2;
            if (r0 < NN)
                *(float2*)(Z + (size_t)r0 * 64 + gc) = make_float2(acc2[mt][nt][0], acc2[mt][nt][1]);
            if (r0 + 8 < NN)
                *(float2*)(Z + (size_t)(r0 + 8) * 64 + gc) = make_float2(acc2[mt][nt][2], acc2[mt][nt][3]);
        }
    }
}

// ---------------- combine1: C = normalize(X@WR + MZ + BL) ----------------
template <int K>
__global__ void __launch_bounds__(256)
combine1(const float* __restrict__ X, const float* __restrict__ WR,
         const float* __restrict__ MZ, const float* __restrict__ BL,
         float* __restrict__ C) {
    constexpr int NCH = K / 32;
    extern __shared__ uint32_t smem[];
    const int tid = threadIdx.x, lane = tid & 31, wid = tid >> 5;
    const int warpM = wid & 3, warpN = wid >> 2;
    const int rowBase = blockIdx.x * 128;

    float acc[2][4][4];
#pragma unroll
    for (int mt = 0; mt < 2; mt++)
#pragma unroll
        for (int nt = 0; nt < 4; nt++)
#pragma unroll
            for (int q = 0; q < 4; q++) acc[mt][nt][q] = 0.f;

    float4 ra[4];
    float rb[2][4];
    auto loadC = [&](int c) {
#pragma unroll
        for (int i = 0; i < 4; i++) {
            int e4 = tid + i * 256;
            int row = e4 >> 3, c4 = e4 & 7;
            int grow = rowBase + row;
            ra[i] = (grow < NN) ? *(const float4*)(X + (size_t)grow * K + c * 32 + c4 * 4)
                                : make_float4(0, 0, 0, 0);
        }
#pragma unroll
        for (int i = 0; i < 2; i++) {
            int idx = tid + i * 256;
            int n = idx & 63, k4 = idx >> 6;
#pragma unroll
            for (int j = 0; j < 4; j++)
                rb[i][j] = WR[(size_t)(c * 32 + k4 * 4 + j) * 64 + n];
        }
    };
    auto stage = [&](int b) {
        uint32_t* sa = smem + (b ? 4096 : 0);
        uint32_t* sb = smem + 8192 + (b ? 2048 : 0);
#pragma unroll
        for (int i = 0; i < 4; i++) { int e4 = tid + i * 256; stA(sa, e4 >> 3, e4 & 7, ra[i]); }
#pragma unroll
        for (int i = 0; i < 2; i++) { int idx = tid + i * 256; stB(sb, idx >> 6, idx & 63, rb[i]); }
    };

    loadC(0); stage(0); __syncthreads();
#pragma unroll 1
    for (int c = 0; c < NCH; c++) {
        if (c + 1 < NCH) loadC(c + 1);
        const uint32_t* sa = smem + ((c & 1) ? 4096 : 0);
        const uint32_t* sb = smem + 8192 + ((c & 1) ? 2048 : 0);
        chunk_mma_g<4>(sa, sb, acc, warpM * 32, warpN * 32, lane);
        if (c + 1 < NCH) { stage((c + 1) & 1); __syncthreads(); }
    }

    // epilogue: + MZ + BL, stage to smem, row-normalize
    __syncthreads();
    float (*sOut)[65] = reinterpret_cast<float(*)[65]>(smem);
    const int qr = lane >> 2, qc = lane & 3;
#pragma unroll
    for (int mt = 0; mt < 2; mt++) {
        int rl = warpM * 32 + mt * 16 + qr;
        int g0 = rowBase + rl, g1 = rowBase + rl + 8;
#pragma unroll
        for (int nt = 0; nt < 4; nt++) {
            int cl = warpN * 32 + nt * 8 + qc * 2;
            float b0 = __ldg(&BL[cl]), b1 = __ldg(&BL[cl + 1]);
            float2 m0 = (g0 < NN) ? *(const float2*)(MZ + (size_t)g0 * 64 + cl) : make_float2(0, 0);
            float2 m1 = (g1 < NN) ? *(const float2*)(MZ + (size_t)g1 * 64 + cl) : make_float2(0, 0);
            sOut[rl][cl]         = acc[mt][nt][0] + b0 + m0.x;
            sOut[rl][cl + 1]     = acc[mt][nt][1] + b1 + m0.y;
            sOut[rl + 8][cl]     = acc[mt][nt][2] + b0 + m1.x;
            sOut[rl + 8][cl + 1] = acc[mt][nt][3] + b1 + m1.y;
        }
    }
    __syncthreads();
#pragma unroll
    for (int rr = 0; rr < 16; rr++) {
        int r = wid * 16 + rr;
        int grow = rowBase + r;
        float v0 = sOut[r][lane];
        float v1 = sOut[r][lane + 32];
        float ss = v0 * v0 + v1 * v1;
#pragma unroll
        for (int o = 16; o > 0; o >>= 1) ss += __shfl_xor_sync(0xffffffffu, ss, o);
        float sc = 1.0f / fmaxf(sqrtf(ss), 1e-12f);
        if (grow < NN) {
            C[(size_t)grow * 64 + lane] = v0 * sc;
            C[(size_t)grow * 64 + lane + 32] = v1 * sc;
        }
    }
}

// ---------------- mean aggregation over CSR (64-dim) ----------------
__global__ void agg_kernel64(const float* __restrict__ xp, float* __restrict__ msg) {
    int w = (blockIdx.x * blockDim.x + threadIdx.x) >> 5;
    int lane = threadIdx.x & 31;
    if (w >= NN) return;
    int beg = g_rowptr[w], end = g_rowptr[w + 1];
    float2 acc = make_float2(0, 0);
    for (int e = beg; e < end; e++) {
        int s = __ldg(&g_adj[e]);
        float2 v = *reinterpret_cast<const float2*>(xp + (size_t)s * 64 + lane * 2);
        acc.x += v.x; acc.y += v.y;
    }
    float inv = 1.0f / fmaxf((float)(end - beg), 1.0f);
    *reinterpret_cast<float2*>(msg + (size_t)w * 64 + lane * 2) =
        make_float2(acc.x * inv, acc.y * inv);
}

// ---------------- pooling ----------------
__global__ void pool_kernel(const float* __restrict__ x, const int* __restrict__ batch) {
    int nwarps = (gridDim.x * blockDim.x) >> 5;
    int w = (blockIdx.x * blockDim.x + threadIdx.x) >> 5;
    int lane = threadIdx.x & 31;
    int per = (NN + nwarps - 1) / nwarps;
    int s = w * per;
    int e = min(NN, s + per);
    if (s >= e) return;
    float m0 = -__int_as_float(0x7f800000), m1 = m0;
    float s0 = 0.f, s1 = 0.f;
    int cnt = 0;
    int curg = __ldg(&batch[s]);
    for (int i = s; i < e; i++) {
        int g = __ldg(&batch[i]);
        if (g != curg) {
            atomicMax(&g_gmax[curg * 64 + lane], fenc(m0));
            atomicMax(&g_gmax[curg * 64 + lane + 32], fenc(m1));
            atomicAdd(&g_gsum[curg * 64 + lane], s0);
            atomicAdd(&g_gsum[curg * 64 + lane + 32], s1);
            if (lane == 0) atomicAdd(&g_gcnt[curg], cnt);
            m0 = m1 = -__int_as_float(0x7f800000);
            s0 = s1 = 0.f; cnt = 0; curg = g;
        }
        float v0 = x[(size_t)i * 64 + lane];
        float v1 = x[(size_t)i * 64 + lane + 32];
        m0 = fmaxf(m0, v0); m1 = fmaxf(m1, v1);
        s0 += v0; s1 += v1; cnt++;
    }
    atomicMax(&g_gmax[curg * 64 + lane], fenc(m0));
    atomicMax(&g_gmax[curg * 64 + lane + 32], fenc(m1));
    atomicAdd(&g_gsum[curg * 64 + lane], s0);
    atomicAdd(&g_gsum[curg * 64 + lane + 32], s1);
    if (lane == 0) atomicAdd(&g_gcnt[curg], cnt);
}

// ---------------- final ----------------
__global__ void final_kernel(const float* __restrict__ post_w, const float* __restrict__ post_b,
                             float* __restrict__ out) {
    int g = threadIdx.x;
    if (g >= NG) return;
    float inv = 1.0f / (float)g_gcnt[g];
    float v[64];
    float ss = 0.f;
#pragma unroll
    for (int c = 0; c < 64; c++) {
        float t = fdec(g_gmax[g * 64 + c]) + g_gsum[g * 64 + c] * inv;
        v[c] = t;
        ss += t * t;
    }
    float norm = sqrtf(ss);
    float dot = 0.f;
#pragma unroll
    for (int c = 0; c < 64; c++) dot += v[c] * post_w[c];
    out[g] = dot / norm + post_b[0];
}

// ---------------- launch ----------------
extern "C" void kernel_launch(void* const* d_in, const int* in_sizes, int n_in,
                              void* d_out, int out_size) {
    const float* node_feat = (const float*)d_in[0];
    const float* cfg_feat  = (const float*)d_in[1];
    const int*   opcode    = (const int*)d_in[2];
    const int*   edge      = (const int*)d_in[3];
    const int*   batch     = (const int*)d_in[4];
    const float* op_emb    = (const float*)d_in[5];
    const float* lin_w     = (const float*)d_in[6];
    const float* lin_b     = (const float*)d_in[7];
    const float* post_w    = (const float*)d_in[8];
    const float* post_b    = (const float*)d_in[9];
    const float* pw0 = (const float*)d_in[10];
    const float* pb0 = (const float*)d_in[11];
    const float* wl0 = (const float*)d_in[12];
    const float* bl0 = (const float*)d_in[13];
    const float* wr0 = (const float*)d_in[14];
    const float* pw1 = (const float*)d_in[15];
    const float* pb1 = (const float*)d_in[16];
    const float* wl1 = (const float*)d_in[17];
    const float* bl1 = (const float*)d_in[18];
    const float* wr1 = (const float*)d_in[19];
    const float* pw2 = (const float*)d_in[20];
    const float* pb2 = (const float*)d_in[21];
    const float* wl2 = (const float*)d_in[22];
    const float* bl2 = (const float*)d_in[23];
    const float* wr2 = (const float*)d_in[24];
    float* out = (float*)d_out;

    const int* src = edge;
    const int* dst = edge + NE;

    const int MB = (NN + 127) / 128;   // 782
    const int EB = (NE + 255) / 256;
    const int AGGB = (NN * 32 + 255) / 256;
    const size_t SMEM48 = 49152;
    const size_t SMEM_PZ128 = 98304;   // (16384 union + 8192 W2) words * 4
    const size_t SMEM_PZ64  = 65536;   // (12288 union + 4096 W2) words * 4

    cudaFuncSetAttribute(projz<128>, cudaFuncAttributeMaxDynamicSharedMemorySize, (int)SMEM_PZ128);
    cudaFuncSetAttribute(projz<64>,  cudaFuncAttributeMaxDynamicSharedMemorySize, (int)SMEM_PZ64);

    init_kernel<<<(NN + 255) / 256, 256>>>();
    hist_kernel<<<EB, 256>>>(dst);
    scan1_kernel<<<NBLK, 256>>>();
    scan2_kernel<<<1, 32>>>();
    scan3_kernel<<<NBLK, 256>>>();
    fill_adj_kernel<<<EB, 256>>>(src, dst);

    float* dA; cudaGetSymbolAddress((void**)&dA, g_xA);
    float* dB; cudaGetSymbolAddress((void**)&dB, g_xB);
    float* dZ; cudaGetSymbolAddress((void**)&dZ, g_xp);
    float* dM; cudaGetSymbolAddress((void**)&dM, g_msg);

    lin_frag<<<dim3(MB, 2), 256, SMEM48>>>(node_feat, cfg_feat, opcode, op_emb, lin_w, lin_b, dA);

    // layer 0 (d=128 -> 64)
    projz<128><<<MB, 256, SMEM_PZ128>>>(dA, pw0, pb0, wl0, dZ);
    agg_kernel64<<<AGGB, 256>>>(dZ, dM);
    combine1<128><<<MB, 256, SMEM48>>>(dA, wr0, dM, bl0, dB);

    // layer 1 (d=64 -> 64)
    projz<64><<<MB, 256, SMEM_PZ64>>>(dB, pw1, pb1, wl1, dZ);
    agg_kernel64<<<AGGB, 256>>>(dZ, dM);
    combine1<64><<<MB, 256, SMEM48>>>(dB, wr1, dM, bl1, dA);

    // layer 2 (d=64 -> 64)
    projz<64><<<MB, 256, SMEM_PZ64>>>(dA, pw2, pb2, wl2, dZ);
    agg_kernel64<<<AGGB, 256>>>(dZ, dM);
    combine1<64><<<MB, 256, SMEM48>>>(dA, wr2, dM, bl2, dB);

    pool_kernel<<<128, 256>>>(dB, batch);
    final_kernel<<<1, 64>>>(post_w, post_b, out);
}

// round 8
// speedup vs baseline: 1.9851x; 1.0092x over previous
#include <cuda_runtime.h>
#include <cuda_fp16.h>
#include <cstdint>

#define NN 100000
#define NE 1600000
#define NG 64
#define NBLK 98   // ceil(NN/1024)

// ---------------- scratch ----------------
__device__ __align__(256) float g_xA[(size_t)NN * 128];
__device__ __align__(256) float g_xB[(size_t)NN * 128];
__device__ __align__(256) __half2 g_z[(size_t)NN * 32];
__device__ __align__(256) float g_msg[(size_t)NN * 64];
__device__ int g_deg[NN];
__device__ int g_cursor[NN];
__device__ int g_rowptr[NN + 1];
__device__ int g_adj[NE];
__device__ int g_bsum[NBLK];
__device__ int g_boff[NBLK];
__device__ unsigned g_gmax[NG * 64];
__device__ float g_gsum[NG * 64];
__device__ int g_gcnt[NG];

// ---------------- helpers ----------------
__device__ __forceinline__ uint32_t f2tf(float f) {
    uint32_t r;
    asm("cvt.rna.tf32.f32 %0, %1;" : "=r"(r) : "f"(f));
    return r;
}
__device__ __forceinline__ void mma8(float* c, const uint32_t* a, const uint32_t* b) {
    asm volatile(
        "mma.sync.aligned.m16n8k8.row.col.f32.tf32.tf32.f32 "
        "{%0,%1,%2,%3}, {%4,%5,%6,%7}, {%8,%9}, {%0,%1,%2,%3};"
        : "+f"(c[0]), "+f"(c[1]), "+f"(c[2]), "+f"(c[3])
        : "r"(a[0]), "r"(a[1]), "r"(a[2]), "r"(a[3]), "r"(b[0]), "r"(b[1]));
}
__device__ __forceinline__ unsigned fenc(float f) {
    unsigned u = __float_as_uint(f);
    return (u & 0x80000000u) ? ~u : (u | 0x80000000u);
}
__device__ __forceinline__ float fdec(unsigned e) {
    return __uint_as_float((e & 0x80000000u) ? (e ^ 0x80000000u) : ~e);
}

// ---------------- XOR-swizzled tiles ----------------
__device__ __forceinline__ void stA(uint32_t* sA, int row, int c4, float4 v) {
    uint32_t* p = sA + row * 32 + 4 * (c4 ^ (row & 7));
    *reinterpret_cast<uint4*>(p) = make_uint4(f2tf(v.x), f2tf(v.y), f2tf(v.z), f2tf(v.w));
}
__device__ __forceinline__ void stB(uint32_t* sB, int k4, int n, const float* w) {
    uint32_t* p = sB + n * 32 + 4 * (k4 ^ (n & 7));
    *reinterpret_cast<uint4*>(p) = make_uint4(f2tf(w[0]), f2tf(w[1]), f2tf(w[2]), f2tf(w[3]));
}
__device__ __forceinline__ void stA2(uint32_t* sX, int row, int col, float x, float y) {
    uint32_t* t = sX + (col >> 5) * 4096;
    uint32_t* p = t + row * 32 + 4 * (((col & 31) >> 2) ^ (row & 7)) + (col & 3);
    p[0] = f2tf(x);
    p[1] = f2tf(y);
}

template <int NT>
__device__ __forceinline__ void chunk_mma_g(const uint32_t* sA, const uint32_t* sB,
                                            float (&acc)[2][NT][4], int rowB, int colB, int lane) {
    const int qr = lane >> 2, qc = lane & 3;
#pragma unroll
    for (int ks = 0; ks < 4; ks++) {
        uint32_t a[2][4];
#pragma unroll
        for (int mt = 0; mt < 2; mt++) {
            int r0 = rowB + mt * 16 + qr;
            int r7 = r0 & 7;
            const uint32_t* b0 = sA + r0 * 32;
            const uint32_t* b1 = sA + (r0 + 8) * 32;
            a[mt][0] = b0[4 * ((2 * ks) ^ r7) + qc];
            a[mt][1] = b1[4 * ((2 * ks) ^ r7) + qc];
            a[mt][2] = b0[4 * ((2 * ks + 1) ^ r7) + qc];
            a[mt][3] = b1[4 * ((2 * ks + 1) ^ r7) + qc];
        }
#pragma unroll
        for (int nt = 0; nt < NT; nt++) {
            int n = colB + nt * 8 + qr;
            const uint32_t* bb = sB + n * 32;
            uint32_t b[2] = { bb[4 * ((2 * ks) ^ qr) + qc], bb[4 * ((2 * ks + 1) ^ qr) + qc] };
#pragma unroll
            for (int mt = 0; mt < 2; mt++) mma8(acc[mt][nt], a[mt], b);
        }
    }
}

// ---------------- init ----------------
__global__ void init_kernel() {
    int j = blockIdx.x * blockDim.x + threadIdx.x;
    if (j < NN) { g_deg[j] = 0; g_cursor[j] = 0; }
    if (j < NG * 64) { g_gmax[j] = 0x007FFFFFu; g_gsum[j] = 0.f; }
    if (j < NG) g_gcnt[j] = 0;
}

// ---------------- CSR build ----------------
__global__ void hist_kernel(const int* __restrict__ dst) {
    int e = blockIdx.x * blockDim.x + threadIdx.x;
    if (e < NE) atomicAdd(&g_deg[dst[e]], 1);
}

__global__ void scan1_kernel() {
    __shared__ int wsum[8];
    int b = blockIdx.x, tid = threadIdx.x, lane = tid & 31, w = tid >> 5;
    int i0 = b * 1024 + tid * 4;
    int s = 0;
#pragma unroll
    for (int j = 0; j < 4; j++) { int i = i0 + j; if (i < NN) s += g_deg[i]; }
#pragma unroll
    for (int o = 16; o > 0; o >>= 1) s += __shfl_xor_sync(0xffffffffu, s, o);
    if (lane == 0) wsum[w] = s;
    __syncthreads();
    if (tid == 0) {
        int t = 0;
#pragma unroll
        for (int k = 0; k < 8; k++) t += wsum[k];
        g_bsum[b] = t;
    }
}

__global__ void scan2_kernel() {  // 128 thr: parallel exclusive scan of 98 block sums
    __shared__ int ws[4];
    int tid = threadIdx.x, lane = tid & 31, w = tid >> 5;
    int v = (tid < NBLK) ? g_bsum[tid] : 0;
    int si = v;
#pragma unroll
    for (int o = 1; o < 32; o <<= 1) { int t = __shfl_up_sync(0xffffffffu, si, o); if (lane >= o) si += t; }
    if (lane == 31) ws[w] = si;
    __syncthreads();
    if (tid == 0) {
        int run = 0;
#pragma unroll
        for (int k = 0; k < 4; k++) { int t = ws[k]; ws[k] = run; run += t; }
        g_rowptr[NN] = run;
    }
    __syncthreads();
    if (tid < NBLK) g_boff[tid] = ws[w] + si - v;
}

__global__ void scan3_kernel() {
    __shared__ int wsum[8];
    int b = blockIdx.x, tid = threadIdx.x, lane = tid & 31, w = tid >> 5;
    int i0 = b * 1024 + tid * 4;
    int v[4], s = 0;
#pragma unroll
    for (int j = 0; j < 4; j++) { int i = i0 + j; v[j] = (i < NN) ? g_deg[i] : 0; s += v[j]; }
    int si = s;
#pragma unroll
    for (int o = 1; o < 32; o <<= 1) { int t = __shfl_up_sync(0xffffffffu, si, o); if (lane >= o) si += t; }
    if (lane == 31) wsum[w] = si;
    __syncthreads();
    if (tid == 0) {
        int run = 0;
#pragma unroll
        for (int k = 0; k < 8; k++) { int t = wsum[k]; wsum[k] = run; run += t; }
    }
    __syncthreads();
    int off = g_boff[b] + wsum[w] + (si - s);
#pragma unroll
    for (int j = 0; j < 4; j++) { int i = i0 + j; if (i < NN) g_rowptr[i] = off; off += v[j]; }
}

__global__ void fill_adj_kernel(const int* __restrict__ src, const int* __restrict__ dst) {
    int e = blockIdx.x * blockDim.x + threadIdx.x;
    if (e < NE) {
        int d = dst[e];
        int p = atomicAdd(&g_cursor[d], 1);
        g_adj[g_rowptr[d] + p] = src[e];
    }
}

// ---------------- lin ----------------
__global__ void __launch_bounds__(256)
lin_frag(const float* __restrict__ nf, const float* __restrict__ cf,
         const int* __restrict__ opc, const float* __restrict__ emb,
         const float* __restrict__ W, const float* __restrict__ bias,
         float* __restrict__ C) {
    extern __shared__ uint32_t smem[];
    const int tid = threadIdx.x, lane = tid & 31, wid = tid >> 5;
    const int warpM = wid & 3, warpN = wid >> 2;
    const int rowBase = blockIdx.x * 128;
    const int n0 = blockIdx.y * 64;

    float acc[2][4][4];
#pragma unroll
    for (int mt = 0; mt < 2; mt++)
#pragma unroll
        for (int nt = 0; nt < 4; nt++)
#pragma unroll
            for (int q = 0; q < 4; q++) acc[mt][nt][q] = 0.f;

    float4 ra[4];
    float rb[2][4];
    auto loadC = [&](int c) {
#pragma unroll
        for (int i = 0; i < 4; i++) {
            int e4 = tid + i * 256;
            int row = e4 >> 3, c4 = e4 & 7;
            int grow = rowBase + row;
            int k = c * 32 + c4 * 4;
            float4 v = make_float4(0, 0, 0, 0);
            if (grow < NN) {
                if (k < 140)      v = *(const float4*)(nf + (size_t)grow * 140 + k);
                else if (k < 172) v = *(const float4*)(emb + (size_t)opc[grow] * 32 + (k - 140));
                else {
                    const float* cp = cf + (size_t)grow * 18;
                    int off = k - 172;
                    v.x = (off + 0 < 18) ? cp[off + 0] : 0.f;
                    v.y = (off + 1 < 18) ? cp[off + 1] : 0.f;
                    v.z = (off + 2 < 18) ? cp[off + 2] : 0.f;
                    v.w = (off + 3 < 18) ? cp[off + 3] : 0.f;
                }
            }
            ra[i] = v;
        }
#pragma unroll
        for (int i = 0; i < 2; i++) {
            int idx = tid + i * 256;
            int n = idx & 63, k4 = idx >> 6;
#pragma unroll
            for (int j = 0; j < 4; j++) {
                int kg = c * 32 + k4 * 4 + j;
                rb[i][j] = (kg < 190) ? W[(size_t)kg * 128 + n0 + n] : 0.f;
            }
        }
    };
    auto stage = [&](int b) {
        uint32_t* sa = smem + (b ? 4096 : 0);
        uint32_t* sb = smem + 8192 + (b ? 2048 : 0);
#pragma unroll
        for (int i = 0; i < 4; i++) { int e4 = tid + i * 256; stA(sa, e4 >> 3, e4 & 7, ra[i]); }
#pragma unroll
        for (int i = 0; i < 2; i++) { int idx = tid + i * 256; stB(sb, idx >> 6, idx & 63, rb[i]); }
    };

    loadC(0); stage(0); __syncthreads();
#pragma unroll 1
    for (int c = 0; c < 6; c++) {
        if (c < 5) loadC(c + 1);
        const uint32_t* sa = smem + ((c & 1) ? 4096 : 0);
        const uint32_t* sb = smem + 8192 + ((c & 1) ? 2048 : 0);
        chunk_mma_g<4>(sa, sb, acc, warpM * 32, warpN * 32, lane);
        if (c < 5) { stage((c + 1) & 1); __syncthreads(); }
    }

    const int qr = lane >> 2, qc = lane & 3;
#pragma unroll
    for (int mt = 0; mt < 2; mt++) {
        int r0 = rowBase + warpM * 32 + mt * 16 + qr;
#pragma unroll
        for (int nt = 0; nt < 4; nt++) {
            int gc = n0 + warpN * 32 + nt * 8 + qc * 2;
            float b0 = __ldg(&bias[gc]), b1 = __ldg(&bias[gc + 1]);
            if (r0 < NN) {
                float2 o = { fmaxf(acc[mt][nt][0] + b0, 0.f), fmaxf(acc[mt][nt][1] + b1, 0.f) };
                *(float2*)(C + (size_t)r0 * 128 + gc) = o;
            }
            if (r0 + 8 < NN) {
                float2 o = { fmaxf(acc[mt][nt][2] + b0, 0.f), fmaxf(acc[mt][nt][3] + b1, 0.f) };
                *(float2*)(C + (size_t)(r0 + 8) * 128 + gc) = o;
            }
        }
    }
}

// ---------------- projz: Z(half2) = relu(A@PW + PB) @ WL ----------------
template <int K>
__global__ void __launch_bounds__(256)
projz(const float* __restrict__ A, const float* __restrict__ PW,
      const float* __restrict__ PB, const float* __restrict__ WL,
      __half2* __restrict__ Z) {
    constexpr int NCH = K / 32;
    constexpr int CW = K / 2;
    constexpr int NT1 = CW / 8;
    constexpr int INB = K * 32;
    constexpr int INW = 8192 + 2 * INB;
    constexpr int XW = NCH * 4096;
    constexpr int UW = (INW > XW) ? INW : XW;
    extern __shared__ uint32_t smem[];
    uint32_t* W2 = smem + UW;

    const int tid = threadIdx.x, lane = tid & 31, wid = tid >> 5;
    const int warpM = wid & 3, warpN = wid >> 2;
    const int rowBase = blockIdx.x * 128;
    const int qr = lane >> 2, qc = lane & 3;

#pragma unroll
    for (int c = 0; c < NCH; c++)
#pragma unroll
        for (int i = 0; i < 2; i++) {
            int idx = tid + i * 256;
            int n = idx & 63, k4 = idx >> 6;
            float w[4];
#pragma unroll
            for (int j = 0; j < 4; j++) w[j] = WL[(size_t)(c * 32 + k4 * 4 + j) * 64 + n];
            stB(W2 + c * 2048, k4, n, w);
        }

    float acc1[2][NT1][4];
#pragma unroll
    for (int mt = 0; mt < 2; mt++)
#pragma unroll
        for (int nt = 0; nt < NT1; nt++)
#pragma unroll
            for (int q = 0; q < 4; q++) acc1[mt][nt][q] = 0.f;

    float4 ra[4];
    float rb[4][4];
    auto loadC = [&](int c) {
#pragma unroll
        for (int i = 0; i < 4; i++) {
            int e4 = tid + i * 256;
            int row = e4 >> 3, c4 = e4 & 7;
            int grow = rowBase + row;
            ra[i] = (grow < NN) ? *(const float4*)(A + (size_t)grow * K + c * 32 + c4 * 4)
                                : make_float4(0, 0, 0, 0);
        }
#pragma unroll
        for (int i = 0; i < NCH; i++) {
            int idx = tid + i * 256;
            int n = idx & (K - 1), k4 = idx / K;
#pragma unroll
            for (int j = 0; j < 4; j++)
                rb[i][j] = PW[(size_t)(c * 32 + k4 * 4 + j) * K + n];
        }
    };
    auto stage = [&](int b) {
        uint32_t* sa = smem + (b ? 4096 : 0);
        uint32_t* sb = smem + 8192 + (b ? INB : 0);
#pragma unroll
        for (int i = 0; i < 4; i++) { int e4 = tid + i * 256; stA(sa, e4 >> 3, e4 & 7, ra[i]); }
#pragma unroll
        for (int i = 0; i < NCH; i++) {
            int idx = tid + i * 256;
            stB(sb, idx / K, idx & (K - 1), rb[i]);
        }
    };

    loadC(0); stage(0); __syncthreads();
#pragma unroll 1
    for (int c = 0; c < NCH; c++) {
        if (c + 1 < NCH) loadC(c + 1);
        const uint32_t* sa = smem + ((c & 1) ? 4096 : 0);
        const uint32_t* sb = smem + 8192 + ((c & 1) ? INB : 0);
        chunk_mma_g<NT1>(sa, sb, acc1, warpM * 32, warpN * CW, lane);
        if (c + 1 < NCH) { stage((c + 1) & 1); __syncthreads(); }
    }
    __syncthreads();

#pragma unroll
    for (int mt = 0; mt < 2; mt++) {
        int r0 = warpM * 32 + mt * 16 + qr;
#pragma unroll
        for (int nt = 0; nt < NT1; nt++) {
            int col = warpN * CW + nt * 8 + qc * 2;
            float b0 = __ldg(&PB[col]), b1 = __ldg(&PB[col + 1]);
            stA2(smem, r0, col, fmaxf(acc1[mt][nt][0] + b0, 0.f), fmaxf(acc1[mt][nt][1] + b1, 0.f));
            stA2(smem, r0 + 8, col, fmaxf(acc1[mt][nt][2] + b0, 0.f), fmaxf(acc1[mt][nt][3] + b1, 0.f));
        }
    }
    __syncthreads();

    float acc2[2][4][4];
#pragma unroll
    for (int mt = 0; mt < 2; mt++)
#pragma unroll
        for (int nt = 0; nt < 4; nt++)
#pragma unroll
            for (int q = 0; q < 4; q++) acc2[mt][nt][q] = 0.f;
#pragma unroll
    for (int c = 0; c < NCH; c++)
        chunk_mma_g<4>(smem + c * 4096, W2 + c * 2048, acc2, warpM * 32, warpN * 32, lane);

#pragma unroll
    for (int mt = 0; mt < 2; mt++) {
        int r0 = rowBase + warpM * 32 + mt * 16 + qr;
#pragma unroll
        for (int nt = 0; nt < 4; nt++) {
            int gc = warpN * 32 + nt * 8 + qc * 2;
            if (r0 < NN)
                Z[(size_t)r0 * 32 + gc / 2] = __floats2half2_rn(acc2[mt][nt][0], acc2[mt][nt][1]);
            if (r0 + 8 < NN)
                Z[(size_t)(r0 + 8) * 32 + gc / 2] = __floats2half2_rn(acc2[mt][nt][2], acc2[mt][nt][3]);
        }
    }
}

// ---------------- combine1: C = normalize(X@WR + MZ + BL) ----------------
template <int K>
__global__ void __launch_bounds__(256)
combine1(const float* __restrict__ X, const float* __restrict__ WR,
         const float* __restrict__ MZ, const float* __restrict__ BL,
         float* __restrict__ C) {
    constexpr int NCH = K / 32;
    extern __shared__ uint32_t smem[];
    const int tid = threadIdx.x, lane = tid & 31, wid = tid >> 5;
    const int warpM = wid & 3, warpN = wid >> 2;
    const int rowBase = blockIdx.x * 128;

    float acc[2][4][4];
#pragma unroll
    for (int mt = 0; mt < 2; mt++)
#pragma unroll
        for (int nt = 0; nt < 4; nt++)
#pragma unroll
            for (int q = 0; q < 4; q++) acc[mt][nt][q] = 0.f;

    float4 ra[4];
    float rb[2][4];
    auto loadC = [&](int c) {
#pragma unroll
        for (int i = 0; i < 4; i++) {
            int e4 = tid + i * 256;
            int row = e4 >> 3, c4 = e4 & 7;
            int grow = rowBase + row;
            ra[i] = (grow < NN) ? *(const float4*)(X + (size_t)grow * K + c * 32 + c4 * 4)
                                : make_float4(0, 0, 0, 0);
        }
#pragma unroll
        for (int i = 0; i < 2; i++) {
            int idx = tid + i * 256;
            int n = idx & 63, k4 = idx >> 6;
#pragma unroll
            for (int j = 0; j < 4; j++)
                rb[i][j] = WR[(size_t)(c * 32 + k4 * 4 + j) * 64 + n];
        }
    };
    auto stage = [&](int b) {
        uint32_t* sa = smem + (b ? 4096 : 0);
        uint32_t* sb = smem + 8192 + (b ? 2048 : 0);
#pragma unroll
        for (int i = 0; i < 4; i++) { int e4 = tid + i * 256; stA(sa, e4 >> 3, e4 & 7, ra[i]); }
#pragma unroll
        for (int i = 0; i < 2; i++) { int idx = tid + i * 256; stB(sb, idx >> 6, idx & 63, rb[i]); }
    };

    loadC(0); stage(0); __syncthreads();
#pragma unroll 1
    for (int c = 0; c < NCH; c++) {
        if (c + 1 < NCH) loadC(c + 1);
        const uint32_t* sa = smem + ((c & 1) ? 4096 : 0);
        const uint32_t* sb = smem + 8192 + ((c & 1) ? 2048 : 0);
        chunk_mma_g<4>(sa, sb, acc, warpM * 32, warpN * 32, lane);
        if (c + 1 < NCH) { stage((c + 1) & 1); __syncthreads(); }
    }

    __syncthreads();
    float (*sOut)[65] = reinterpret_cast<float(*)[65]>(smem);
    const int qr = lane >> 2, qc = lane & 3;
#pragma unroll
    for (int mt = 0; mt < 2; mt++) {
        int rl = warpM * 32 + mt * 16 + qr;
        int g0 = rowBase + rl, g1 = rowBase + rl + 8;
#pragma unroll
        for (int nt = 0; nt < 4; nt++) {
            int cl = warpN * 32 + nt * 8 + qc * 2;
            float b0 = __ldg(&BL[cl]), b1 = __ldg(&BL[cl + 1]);
            float2 m0 = (g0 < NN) ? *(const float2*)(MZ + (size_t)g0 * 64 + cl) : make_float2(0, 0);
            float2 m1 = (g1 < NN) ? *(const float2*)(MZ + (size_t)g1 * 64 + cl) : make_float2(0, 0);
            sOut[rl][cl]         = acc[mt][nt][0] + b0 + m0.x;
            sOut[rl][cl + 1]     = acc[mt][nt][1] + b1 + m0.y;
            sOut[rl + 8][cl]     = acc[mt][nt][2] + b0 + m1.x;
            sOut[rl + 8][cl + 1] = acc[mt][nt][3] + b1 + m1.y;
        }
    }
    __syncthreads();
#pragma unroll
    for (int rr = 0; rr < 16; rr++) {
        int r = wid * 16 + rr;
        int grow = rowBase + r;
        float v0 = sOut[r][lane];
        float v1 = sOut[r][lane + 32];
        float ss = v0 * v0 + v1 * v1;
#pragma unroll
        for (int o = 16; o > 0; o >>= 1) ss += __shfl_xor_sync(0xffffffffu, ss, o);
        float sc = 1.0f / fmaxf(sqrtf(ss), 1e-12f);
        if (grow < NN) {
            C[(size_t)grow * 64 + lane] = v0 * sc;
            C[(size_t)grow * 64 + lane + 32] = v1 * sc;
        }
    }
}

// ---------------- mean aggregation over CSR (64-dim, half2 source) ----------------
__global__ void agg_half(const __half2* __restrict__ zp, float* __restrict__ msg) {
    int w = (blockIdx.x * blockDim.x + threadIdx.x) >> 5;
    int lane = threadIdx.x & 31;
    if (w >= NN) return;
    int beg = g_rowptr[w], end = g_rowptr[w + 1];
    float2 acc = make_float2(0, 0);
    for (int e = beg; e < end; e++) {
        int s = __ldg(&g_adj[e]);
        __half2 h = zp[(size_t)s * 32 + lane];
        float2 v = __half22float2(h);
        acc.x += v.x; acc.y += v.y;
    }
    float inv = 1.0f / fmaxf((float)(end - beg), 1.0f);
    *reinterpret_cast<float2*>(msg + (size_t)w * 64 + lane * 2) =
        make_float2(acc.x * inv, acc.y * inv);
}

// ---------------- pooling ----------------
__global__ void pool_kernel(const float* __restrict__ x, const int* __restrict__ batch) {
    int nwarps = (gridDim.x * blockDim.x) >> 5;
    int w = (blockIdx.x * blockDim.x + threadIdx.x) >> 5;
    int lane = threadIdx.x & 31;
    int per = (NN + nwarps - 1) / nwarps;
    int s = w * per;
    int e = min(NN, s + per);
    if (s >= e) return;
    float m0 = -__int_as_float(0x7f800000), m1 = m0;
    float s0 = 0.f, s1 = 0.f;
    int cnt = 0;
    int curg = __ldg(&batch[s]);
    for (int i = s; i < e; i++) {
        int g = __ldg(&batch[i]);
        if (g != curg) {
            atomicMax(&g_gmax[curg * 64 + lane], fenc(m0));
            atomicMax(&g_gmax[curg * 64 + lane + 32], fenc(m1));
            atomicAdd(&g_gsum[curg * 64 + lane], s0);
            atomicAdd(&g_gsum[curg * 64 + lane + 32], s1);
            if (lane == 0) atomicAdd(&g_gcnt[curg], cnt);
            m0 = m1 = -__int_as_float(0x7f800000);
            s0 = s1 = 0.f; cnt = 0; curg = g;
        }
        float v0 = x[(size_t)i * 64 + lane];
        float v1 = x[(size_t)i * 64 + lane + 32];
        m0 = fmaxf(m0, v0); m1 = fmaxf(m1, v1);
        s0 += v0; s1 += v1; cnt++;
    }
    atomicMax(&g_gmax[curg * 64 + lane], fenc(m0));
    atomicMax(&g_gmax[curg * 64 + lane + 32], fenc(m1));
    atomicAdd(&g_gsum[curg * 64 + lane], s0);
    atomicAdd(&g_gsum[curg * 64 + lane + 32], s1);
    if (lane == 0) atomicAdd(&g_gcnt[curg], cnt);
}

// ---------------- final ----------------
__global__ void final_kernel(const float* __restrict__ post_w, const float* __restrict__ post_b,
                             float* __restrict__ out) {
    int g = threadIdx.x;
    if (g >= NG) return;
    float inv = 1.0f / (float)g_gcnt[g];
    float v[64];
    float ss = 0.f;
#pragma unroll
    for (int c = 0; c < 64; c++) {
        float t = fdec(g_gmax[g * 64 + c]) + g_gsum[g * 64 + c] * inv;
        v[c] = t;
        ss += t * t;
    }
    float norm = sqrtf(ss);
    float dot = 0.f;
#pragma unroll
    for (int c = 0; c < 64; c++) dot += v[c] * post_w[c];
    out[g] = dot / norm + post_b[0];
}

// ---------------- launch ----------------
extern "C" void kernel_launch(void* const* d_in, const int* in_sizes, int n_in,
                              void* d_out, int out_size) {
    const float* node_feat = (const float*)d_in[0];
    const float* cfg_feat  = (const float*)d_in[1];
    const int*   opcode    = (const int*)d_in[2];
    const int*   edge      = (const int*)d_in[3];
    const int*   batch     = (const int*)d_in[4];
    const float* op_emb    = (const float*)d_in[5];
    const float* lin_w     = (const float*)d_in[6];
    const float* lin_b     = (const float*)d_in[7];
    const float* post_w    = (const float*)d_in[8];
    const float* post_b    = (const float*)d_in[9];
    const float* pw0 = (const float*)d_in[10];
    const float* pb0 = (const float*)d_in[11];
    const float* wl0 = (const float*)d_in[12];
    const float* bl0 = (const float*)d_in[13];
    const float* wr0 = (const float*)d_in[14];
    const float* pw1 = (const float*)d_in[15];
    const float* pb1 = (const float*)d_in[16];
    const float* wl1 = (const float*)d_in[17];
    const float* bl1 = (const float*)d_in[18];
    const float* wr1 = (const float*)d_in[19];
    const float* pw2 = (const float*)d_in[20];
    const float* pb2 = (const float*)d_in[21];
    const float* wl2 = (const float*)d_in[22];
    const float* bl2 = (const float*)d_in[23];
    const float* wr2 = (const float*)d_in[24];
    float* out = (float*)d_out;

    const int* src = edge;
    const int* dst = edge + NE;

    const int MB = (NN + 127) / 128;   // 782
    const int EB = (NE + 255) / 256;
    const int AGGB = (NN * 32 + 255) / 256;
    const size_t SMEM48 = 49152;
    const size_t SMEM_PZ128 = 98304;
    const size_t SMEM_PZ64  = 65536;

    cudaFuncSetAttribute(projz<128>, cudaFuncAttributeMaxDynamicSharedMemorySize, (int)SMEM_PZ128);
    cudaFuncSetAttribute(projz<64>,  cudaFuncAttributeMaxDynamicSharedMemorySize, (int)SMEM_PZ64);

    init_kernel<<<(NN + 255) / 256, 256>>>();
    hist_kernel<<<EB, 256>>>(dst);
    scan1_kernel<<<NBLK, 256>>>();
    scan2_kernel<<<1, 128>>>();
    scan3_kernel<<<NBLK, 256>>>();
    fill_adj_kernel<<<EB, 256>>>(src, dst);

    float* dA; cudaGetSymbolAddress((void**)&dA, g_xA);
    float* dB; cudaGetSymbolAddress((void**)&dB, g_xB);
    __half2* dZ; cudaGetSymbolAddress((void**)&dZ, g_z);
    float* dM; cudaGetSymbolAddress((void**)&dM, g_msg);

    lin_frag<<<dim3(MB, 2), 256, SMEM48>>>(node_feat, cfg_feat, opcode, op_emb, lin_w, lin_b, dA);

    // layer 0 (d=128 -> 64)
    projz<128><<<MB, 256, SMEM_PZ128>>>(dA, pw0, pb0, wl0, dZ);
    agg_half<<<AGGB, 256>>>(dZ, dM);
    combine1<128><<<MB, 256, SMEM48>>>(dA, wr0, dM, bl0, dB);

    // layer 1 (d=64 -> 64)
    projz<64><<<MB, 256, SMEM_PZ64>>>(dB, pw1, pb1, wl1, dZ);
    agg_half<<<AGGB, 256>>>(dZ, dM);
    combine1<64><<<MB, 256, SMEM48>>>(dB, wr1, dM, bl1, dA);

    // layer 2 (d=64 -> 64)
    projz<64><<<MB, 256, SMEM_PZ64>>>(dA, pw2, pb2, wl2, dZ);
    agg_half<<<AGGB, 256>>>(dZ, dM);
    combine1<64><<<MB, 256, SMEM48>>>(dA, wr2, dM, bl2, dB);

    pool_kernel<<<128, 256>>>(dB, batch);
    final_kernel<<<1, 64>>>(post_w, post_b, out);
}

// round 9
// speedup vs baseline: 2.0005x; 1.0078x over previous
#include <cuda_runtime.h>
#include <cuda_fp16.h>
#include <cstdint>

#define NN 100000
#define NE 1600000
#define NG 64
#define NBLK 98   // ceil(NN/1024)

// ---------------- scratch ----------------
__device__ __align__(256) float g_xA[(size_t)NN * 128];
__device__ __align__(256) float g_xB[(size_t)NN * 128];
__device__ __align__(256) __half2 g_z[(size_t)NN * 32];
__device__ __align__(256) float g_msg[(size_t)NN * 64];
__device__ int g_deg[NN];
__device__ int g_cursor[NN];
__device__ int g_rowptr[NN + 1];
__device__ int g_adj[NE];
__device__ int g_bsum[NBLK];
__device__ int g_boff[NBLK];
__device__ unsigned g_gmax[NG * 64];
__device__ float g_gsum[NG * 64];
__device__ int g_gcnt[NG];

// ---------------- helpers ----------------
__device__ __forceinline__ uint32_t f2tf(float f) {
    uint32_t r;
    asm("cvt.rna.tf32.f32 %0, %1;" : "=r"(r) : "f"(f));
    return r;
}
__device__ __forceinline__ void mma8(float* c, const uint32_t* a, const uint32_t* b) {
    asm volatile(
        "mma.sync.aligned.m16n8k8.row.col.f32.tf32.tf32.f32 "
        "{%0,%1,%2,%3}, {%4,%5,%6,%7}, {%8,%9}, {%0,%1,%2,%3};"
        : "+f"(c[0]), "+f"(c[1]), "+f"(c[2]), "+f"(c[3])
        : "r"(a[0]), "r"(a[1]), "r"(a[2]), "r"(a[3]), "r"(b[0]), "r"(b[1]));
}
__device__ __forceinline__ unsigned fenc(float f) {
    unsigned u = __float_as_uint(f);
    return (u & 0x80000000u) ? ~u : (u | 0x80000000u);
}
__device__ __forceinline__ float fdec(unsigned e) {
    return __uint_as_float((e & 0x80000000u) ? (e ^ 0x80000000u) : ~e);
}

// ---------------- XOR-swizzled tiles ----------------
__device__ __forceinline__ void stA(uint32_t* sA, int row, int c4, float4 v) {
    uint32_t* p = sA + row * 32 + 4 * (c4 ^ (row & 7));
    *reinterpret_cast<uint4*>(p) = make_uint4(f2tf(v.x), f2tf(v.y), f2tf(v.z), f2tf(v.w));
}
__device__ __forceinline__ void stB(uint32_t* sB, int k4, int n, const float* w) {
    uint32_t* p = sB + n * 32 + 4 * (k4 ^ (n & 7));
    *reinterpret_cast<uint4*>(p) = make_uint4(f2tf(w[0]), f2tf(w[1]), f2tf(w[2]), f2tf(w[3]));
}
__device__ __forceinline__ void stA2(uint32_t* sX, int row, int col, float x, float y) {
    uint32_t* t = sX + (col >> 5) * 4096;
    uint32_t* p = t + row * 32 + 4 * (((col & 31) >> 2) ^ (row & 7)) + (col & 3);
    p[0] = f2tf(x);
    p[1] = f2tf(y);
}

template <int NT>
__device__ __forceinline__ void chunk_mma_g(const uint32_t* sA, const uint32_t* sB,
                                            float (&acc)[2][NT][4], int rowB, int colB, int lane) {
    const int qr = lane >> 2, qc = lane & 3;
#pragma unroll
    for (int ks = 0; ks < 4; ks++) {
        uint32_t a[2][4];
#pragma unroll
        for (int mt = 0; mt < 2; mt++) {
            int r0 = rowB + mt * 16 + qr;
            int r7 = r0 & 7;
            const uint32_t* b0 = sA + r0 * 32;
            const uint32_t* b1 = sA + (r0 + 8) * 32;
            a[mt][0] = b0[4 * ((2 * ks) ^ r7) + qc];
            a[mt][1] = b1[4 * ((2 * ks) ^ r7) + qc];
            a[mt][2] = b0[4 * ((2 * ks + 1) ^ r7) + qc];
            a[mt][3] = b1[4 * ((2 * ks + 1) ^ r7) + qc];
        }
#pragma unroll
        for (int nt = 0; nt < NT; nt++) {
            int n = colB + nt * 8 + qr;
            const uint32_t* bb = sB + n * 32;
            uint32_t b[2] = { bb[4 * ((2 * ks) ^ qr) + qc], bb[4 * ((2 * ks + 1) ^ qr) + qc] };
#pragma unroll
            for (int mt = 0; mt < 2; mt++) mma8(acc[mt][nt], a[mt], b);
        }
    }
}

// ---------------- init ----------------
__global__ void init_kernel() {
    int j = blockIdx.x * blockDim.x + threadIdx.x;
    if (j < NN) { g_deg[j] = 0; g_cursor[j] = 0; }
    if (j < NG * 64) { g_gmax[j] = 0x007FFFFFu; g_gsum[j] = 0.f; }
    if (j < NG) g_gcnt[j] = 0;
}

// ---------------- CSR build ----------------
__global__ void hist_kernel(const int* __restrict__ dst) {
    int e = blockIdx.x * blockDim.x + threadIdx.x;
    if (e < NE) atomicAdd(&g_deg[dst[e]], 1);
}

__global__ void scan1_kernel() {
    __shared__ int wsum[8];
    int b = blockIdx.x, tid = threadIdx.x, lane = tid & 31, w = tid >> 5;
    int i0 = b * 1024 + tid * 4;
    int s = 0;
#pragma unroll
    for (int j = 0; j < 4; j++) { int i = i0 + j; if (i < NN) s += g_deg[i]; }
#pragma unroll
    for (int o = 16; o > 0; o >>= 1) s += __shfl_xor_sync(0xffffffffu, s, o);
    if (lane == 0) wsum[w] = s;
    __syncthreads();
    if (tid == 0) {
        int t = 0;
#pragma unroll
        for (int k = 0; k < 8; k++) t += wsum[k];
        g_bsum[b] = t;
    }
}

__global__ void scan2_kernel() {
    __shared__ int ws[4];
    int tid = threadIdx.x, lane = tid & 31, w = tid >> 5;
    int v = (tid < NBLK) ? g_bsum[tid] : 0;
    int si = v;
#pragma unroll
    for (int o = 1; o < 32; o <<= 1) { int t = __shfl_up_sync(0xffffffffu, si, o); if (lane >= o) si += t; }
    if (lane == 31) ws[w] = si;
    __syncthreads();
    if (tid == 0) {
        int run = 0;
#pragma unroll
        for (int k = 0; k < 4; k++) { int t = ws[k]; ws[k] = run; run += t; }
        g_rowptr[NN] = run;
    }
    __syncthreads();
    if (tid < NBLK) g_boff[tid] = ws[w] + si - v;
}

__global__ void scan3_kernel() {
    __shared__ int wsum[8];
    int b = blockIdx.x, tid = threadIdx.x, lane = tid & 31, w = tid >> 5;
    int i0 = b * 1024 + tid * 4;
    int v[4], s = 0;
#pragma unroll
    for (int j = 0; j < 4; j++) { int i = i0 + j; v[j] = (i < NN) ? g_deg[i] : 0; s += v[j]; }
    int si = s;
#pragma unroll
    for (int o = 1; o < 32; o <<= 1) { int t = __shfl_up_sync(0xffffffffu, si, o); if (lane >= o) si += t; }
    if (lane == 31) wsum[w] = si;
    __syncthreads();
    if (tid == 0) {
        int run = 0;
#pragma unroll
        for (int k = 0; k < 8; k++) { int t = wsum[k]; wsum[k] = run; run += t; }
    }
    __syncthreads();
    int off = g_boff[b] + wsum[w] + (si - s);
#pragma unroll
    for (int j = 0; j < 4; j++) { int i = i0 + j; if (i < NN) g_rowptr[i] = off; off += v[j]; }
}

__global__ void fill_adj_kernel(const int* __restrict__ src, const int* __restrict__ dst) {
    int e = blockIdx.x * blockDim.x + threadIdx.x;
    if (e < NE) {
        int d = dst[e];
        int p = atomicAdd(&g_cursor[d], 1);
        g_adj[g_rowptr[d] + p] = src[e];
    }
}

// ---------------- lin ----------------
__global__ void __launch_bounds__(256)
lin_frag(const float* __restrict__ nf, const float* __restrict__ cf,
         const int* __restrict__ opc, const float* __restrict__ emb,
         const float* __restrict__ W, const float* __restrict__ bias,
         float* __restrict__ C) {
    extern __shared__ uint32_t smem[];
    const int tid = threadIdx.x, lane = tid & 31, wid = tid >> 5;
    const int warpM = wid & 3, warpN = wid >> 2;
    const int rowBase = blockIdx.x * 128;
    const int n0 = blockIdx.y * 64;

    float acc[2][4][4];
#pragma unroll
    for (int mt = 0; mt < 2; mt++)
#pragma unroll
        for (int nt = 0; nt < 4; nt++)
#pragma unroll
            for (int q = 0; q < 4; q++) acc[mt][nt][q] = 0.f;

    float4 ra[4];
    float rb[2][4];
    auto loadC = [&](int c) {
#pragma unroll
        for (int i = 0; i < 4; i++) {
            int e4 = tid + i * 256;
            int row = e4 >> 3, c4 = e4 & 7;
            int grow = rowBase + row;
            int k = c * 32 + c4 * 4;
            float4 v = make_float4(0, 0, 0, 0);
            if (grow < NN) {
                if (k < 140)      v = *(const float4*)(nf + (size_t)grow * 140 + k);
                else if (k < 172) v = *(const float4*)(emb + (size_t)opc[grow] * 32 + (k - 140));
                else {
                    const float* cp = cf + (size_t)grow * 18;
                    int off = k - 172;
                    v.x = (off + 0 < 18) ? cp[off + 0] : 0.f;
                    v.y = (off + 1 < 18) ? cp[off + 1] : 0.f;
                    v.z = (off + 2 < 18) ? cp[off + 2] : 0.f;
                    v.w = (off + 3 < 18) ? cp[off + 3] : 0.f;
                }
            }
            ra[i] = v;
        }
#pragma unroll
        for (int i = 0; i < 2; i++) {
            int idx = tid + i * 256;
            int n = idx & 63, k4 = idx >> 6;
#pragma unroll
            for (int j = 0; j < 4; j++) {
                int kg = c * 32 + k4 * 4 + j;
                rb[i][j] = (kg < 190) ? W[(size_t)kg * 128 + n0 + n] : 0.f;
            }
        }
    };
    auto stage = [&](int b) {
        uint32_t* sa = smem + (b ? 4096 : 0);
        uint32_t* sb = smem + 8192 + (b ? 2048 : 0);
#pragma unroll
        for (int i = 0; i < 4; i++) { int e4 = tid + i * 256; stA(sa, e4 >> 3, e4 & 7, ra[i]); }
#pragma unroll
        for (int i = 0; i < 2; i++) { int idx = tid + i * 256; stB(sb, idx >> 6, idx & 63, rb[i]); }
    };

    loadC(0); stage(0); __syncthreads();
#pragma unroll 1
    for (int c = 0; c < 6; c++) {
        if (c < 5) loadC(c + 1);
        const uint32_t* sa = smem + ((c & 1) ? 4096 : 0);
        const uint32_t* sb = smem + 8192 + ((c & 1) ? 2048 : 0);
        chunk_mma_g<4>(sa, sb, acc, warpM * 32, warpN * 32, lane);
        if (c < 5) { stage((c + 1) & 1); __syncthreads(); }
    }

    const int qr = lane >> 2, qc = lane & 3;
#pragma unroll
    for (int mt = 0; mt < 2; mt++) {
        int r0 = rowBase + warpM * 32 + mt * 16 + qr;
#pragma unroll
        for (int nt = 0; nt < 4; nt++) {
            int gc = n0 + warpN * 32 + nt * 8 + qc * 2;
            float b0 = __ldg(&bias[gc]), b1 = __ldg(&bias[gc + 1]);
            if (r0 < NN) {
                float2 o = { fmaxf(acc[mt][nt][0] + b0, 0.f), fmaxf(acc[mt][nt][1] + b1, 0.f) };
                *(float2*)(C + (size_t)r0 * 128 + gc) = o;
            }
            if (r0 + 8 < NN) {
                float2 o = { fmaxf(acc[mt][nt][2] + b0, 0.f), fmaxf(acc[mt][nt][3] + b1, 0.f) };
                *(float2*)(C + (size_t)(r0 + 8) * 128 + gc) = o;
            }
        }
    }
}

// ---------------- projz: Z(half2) = relu(A@PW + PB) @ WL ----------------
template <int K>
__global__ void __launch_bounds__(256)
projz(const float* __restrict__ A, const float* __restrict__ PW,
      const float* __restrict__ PB, const float* __restrict__ WL,
      __half2* __restrict__ Z) {
    constexpr int NCH = K / 32;
    constexpr int CW = K / 2;
    constexpr int NT1 = CW / 8;
    constexpr int INB = K * 32;
    constexpr int INW = 8192 + 2 * INB;
    constexpr int XW = NCH * 4096;
    constexpr int UW = (INW > XW) ? INW : XW;
    extern __shared__ uint32_t smem[];
    uint32_t* W2 = smem + UW;

    const int tid = threadIdx.x, lane = tid & 31, wid = tid >> 5;
    const int warpM = wid & 3, warpN = wid >> 2;
    const int rowBase = blockIdx.x * 128;
    const int qr = lane >> 2, qc = lane & 3;

#pragma unroll
    for (int c = 0; c < NCH; c++)
#pragma unroll
        for (int i = 0; i < 2; i++) {
            int idx = tid + i * 256;
            int n = idx & 63, k4 = idx >> 6;
            float w[4];
#pragma unroll
            for (int j = 0; j < 4; j++) w[j] = WL[(size_t)(c * 32 + k4 * 4 + j) * 64 + n];
            stB(W2 + c * 2048, k4, n, w);
        }

    float acc1[2][NT1][4];
#pragma unroll
    for (int mt = 0; mt < 2; mt++)
#pragma unroll
        for (int nt = 0; nt < NT1; nt++)
#pragma unroll
            for (int q = 0; q < 4; q++) acc1[mt][nt][q] = 0.f;

    float4 ra[4];
    float rb[4][4];
    auto loadC = [&](int c) {
#pragma unroll
        for (int i = 0; i < 4; i++) {
            int e4 = tid + i * 256;
            int row = e4 >> 3, c4 = e4 & 7;
            int grow = rowBase + row;
            ra[i] = (grow < NN) ? *(const float4*)(A + (size_t)grow * K + c * 32 + c4 * 4)
                                : make_float4(0, 0, 0, 0);
        }
#pragma unroll
        for (int i = 0; i < NCH; i++) {
            int idx = tid + i * 256;
            int n = idx & (K - 1), k4 = idx / K;
#pragma unroll
            for (int j = 0; j < 4; j++)
                rb[i][j] = PW[(size_t)(c * 32 + k4 * 4 + j) * K + n];
        }
    };
    auto stage = [&](int b) {
        uint32_t* sa = smem + (b ? 4096 : 0);
        uint32_t* sb = smem + 8192 + (b ? INB : 0);
#pragma unroll
        for (int i = 0; i < 4; i++) { int e4 = tid + i * 256; stA(sa, e4 >> 3, e4 & 7, ra[i]); }
#pragma unroll
        for (int i = 0; i < NCH; i++) {
            int idx = tid + i * 256;
            stB(sb, idx / K, idx & (K - 1), rb[i]);
        }
    };

    loadC(0); stage(0); __syncthreads();
#pragma unroll 1
    for (int c = 0; c < NCH; c++) {
        if (c + 1 < NCH) loadC(c + 1);
        const uint32_t* sa = smem + ((c & 1) ? 4096 : 0);
        const uint32_t* sb = smem + 8192 + ((c & 1) ? INB : 0);
        chunk_mma_g<NT1>(sa, sb, acc1, warpM * 32, warpN * CW, lane);
        if (c + 1 < NCH) { stage((c + 1) & 1); __syncthreads(); }
    }
    __syncthreads();

#pragma unroll
    for (int mt = 0; mt < 2; mt++) {
        int r0 = warpM * 32 + mt * 16 + qr;
#pragma unroll
        for (int nt = 0; nt < NT1; nt++) {
            int col = warpN * CW + nt * 8 + qc * 2;
            float b0 = __ldg(&PB[col]), b1 = __ldg(&PB[col + 1]);
            stA2(smem, r0, col, fmaxf(acc1[mt][nt][0] + b0, 0.f), fmaxf(acc1[mt][nt][1] + b1, 0.f));
            stA2(smem, r0 + 8, col, fmaxf(acc1[mt][nt][2] + b0, 0.f), fmaxf(acc1[mt][nt][3] + b1, 0.f));
        }
    }
    __syncthreads();

    float acc2[2][4][4];
#pragma unroll
    for (int mt = 0; mt < 2; mt++)
#pragma unroll
        for (int nt = 0; nt < 4; nt++)
#pragma unroll
            for (int q = 0; q < 4; q++) acc2[mt][nt][q] = 0.f;
#pragma unroll
    for (int c = 0; c < NCH; c++)
        chunk_mma_g<4>(smem + c * 4096, W2 + c * 2048, acc2, warpM * 32, warpN * 32, lane);

#pragma unroll
    for (int mt = 0; mt < 2; mt++) {
        int r0 = rowBase + warpM * 32 + mt * 16 + qr;
#pragma unroll
        for (int nt = 0; nt < 4; nt++) {
            int gc = warpN * 32 + nt * 8 + qc * 2;
            if (r0 < NN)
                Z[(size_t)r0 * 32 + gc / 2] = __floats2half2_rn(acc2[mt][nt][0], acc2[mt][nt][1]);
            if (r0 + 8 < NN)
                Z[(size_t)(r0 + 8) * 32 + gc / 2] = __floats2half2_rn(acc2[mt][nt][2], acc2[mt][nt][3]);
        }
    }
}

// ---------------- combine1: C = normalize(X@WR + MZ + BL) ----------------
template <int K>
__global__ void __launch_bounds__(256)
combine1(const float* __restrict__ X, const float* __restrict__ WR,
         const float* __restrict__ MZ, const float* __restrict__ BL,
         float* __restrict__ C) {
    constexpr int NCH = K / 32;
    extern __shared__ uint32_t smem[];
    const int tid = threadIdx.x, lane = tid & 31, wid = tid >> 5;
    const int warpM = wid & 3, warpN = wid >> 2;
    const int rowBase = blockIdx.x * 128;

    float acc[2][4][4];
#pragma unroll
    for (int mt = 0; mt < 2; mt++)
#pragma unroll
        for (int nt = 0; nt < 4; nt++)
#pragma unroll
            for (int q = 0; q < 4; q++) acc[mt][nt][q] = 0.f;

    float4 ra[4];
    float rb[2][4];
    auto loadC = [&](int c) {
#pragma unroll
        for (int i = 0; i < 4; i++) {
            int e4 = tid + i * 256;
            int row = e4 >> 3, c4 = e4 & 7;
            int grow = rowBase + row;
            ra[i] = (grow < NN) ? *(const float4*)(X + (size_t)grow * K + c * 32 + c4 * 4)
                                : make_float4(0, 0, 0, 0);
        }
#pragma unroll
        for (int i = 0; i < 2; i++) {
            int idx = tid + i * 256;
            int n = idx & 63, k4 = idx >> 6;
#pragma unroll
            for (int j = 0; j < 4; j++)
                rb[i][j] = WR[(size_t)(c * 32 + k4 * 4 + j) * 64 + n];
        }
    };
    auto stage = [&](int b) {
        uint32_t* sa = smem + (b ? 4096 : 0);
        uint32_t* sb = smem + 8192 + (b ? 2048 : 0);
#pragma unroll
        for (int i = 0; i < 4; i++) { int e4 = tid + i * 256; stA(sa, e4 >> 3, e4 & 7, ra[i]); }
#pragma unroll
        for (int i = 0; i < 2; i++) { int idx = tid + i * 256; stB(sb, idx >> 6, idx & 63, rb[i]); }
    };

    loadC(0); stage(0); __syncthreads();
#pragma unroll 1
    for (int c = 0; c < NCH; c++) {
        if (c + 1 < NCH) loadC(c + 1);
        const uint32_t* sa = smem + ((c & 1) ? 4096 : 0);
        const uint32_t* sb = smem + 8192 + ((c & 1) ? 2048 : 0);
        chunk_mma_g<4>(sa, sb, acc, warpM * 32, warpN * 32, lane);
        if (c + 1 < NCH) { stage((c + 1) & 1); __syncthreads(); }
    }

    __syncthreads();
    float (*sOut)[65] = reinterpret_cast<float(*)[65]>(smem);
    const int qr = lane >> 2, qc = lane & 3;
#pragma unroll
    for (int mt = 0; mt < 2; mt++) {
        int rl = warpM * 32 + mt * 16 + qr;
        int g0 = rowBase + rl, g1 = rowBase + rl + 8;
#pragma unroll
        for (int nt = 0; nt < 4; nt++) {
            int cl = warpN * 32 + nt * 8 + qc * 2;
            float b0 = __ldg(&BL[cl]), b1 = __ldg(&BL[cl + 1]);
            float2 m0 = (g0 < NN) ? *(const float2*)(MZ + (size_t)g0 * 64 + cl) : make_float2(0, 0);
            float2 m1 = (g1 < NN) ? *(const float2*)(MZ + (size_t)g1 * 64 + cl) : make_float2(0, 0);
            sOut[rl][cl]         = acc[mt][nt][0] + b0 + m0.x;
            sOut[rl][cl + 1]     = acc[mt][nt][1] + b1 + m0.y;
            sOut[rl + 8][cl]     = acc[mt][nt][2] + b0 + m1.x;
            sOut[rl + 8][cl + 1] = acc[mt][nt][3] + b1 + m1.y;
        }
    }
    __syncthreads();
#pragma unroll
    for (int rr = 0; rr < 16; rr++) {
        int r = wid * 16 + rr;
        int grow = rowBase + r;
        float v0 = sOut[r][lane];
        float v1 = sOut[r][lane + 32];
        float ss = v0 * v0 + v1 * v1;
#pragma unroll
        for (int o = 16; o > 0; o >>= 1) ss += __shfl_xor_sync(0xffffffffu, ss, o);
        float sc = 1.0f / fmaxf(sqrtf(ss), 1e-12f);
        if (grow < NN) {
            C[(size_t)grow * 64 + lane] = v0 * sc;
            C[(size_t)grow * 64 + lane + 32] = v1 * sc;
        }
    }
}

// ---------------- mean aggregation over CSR (64-dim, half2 source, x4 MLP) ----------------
__global__ void agg_half(const __half2* __restrict__ zp, float* __restrict__ msg) {
    int w = (blockIdx.x * blockDim.x + threadIdx.x) >> 5;
    int lane = threadIdx.x & 31;
    if (w >= NN) return;
    int beg = g_rowptr[w], end = g_rowptr[w + 1];
    float2 acc = make_float2(0, 0);
    int e = beg;
    for (; e + 4 <= end; e += 4) {
        int s0 = __ldg(&g_adj[e]);
        int s1 = __ldg(&g_adj[e + 1]);
        int s2 = __ldg(&g_adj[e + 2]);
        int s3 = __ldg(&g_adj[e + 3]);
        float2 v0 = __half22float2(zp[(size_t)s0 * 32 + lane]);
        float2 v1 = __half22float2(zp[(size_t)s1 * 32 + lane]);
        float2 v2 = __half22float2(zp[(size_t)s2 * 32 + lane]);
        float2 v3 = __half22float2(zp[(size_t)s3 * 32 + lane]);
        acc.x += (v0.x + v1.x) + (v2.x + v3.x);
        acc.y += (v0.y + v1.y) + (v2.y + v3.y);
    }
    for (; e < end; e++) {
        int s = __ldg(&g_adj[e]);
        float2 v = __half22float2(zp[(size_t)s * 32 + lane]);
        acc.x += v.x; acc.y += v.y;
    }
    float inv = 1.0f / fmaxf((float)(end - beg), 1.0f);
    *reinterpret_cast<float2*>(msg + (size_t)w * 64 + lane * 2) =
        make_float2(acc.x * inv, acc.y * inv);
}

// ---------------- pooling ----------------
__global__ void pool_kernel(const float* __restrict__ x, const int* __restrict__ batch) {
    int nwarps = (gridDim.x * blockDim.x) >> 5;
    int w = (blockIdx.x * blockDim.x + threadIdx.x) >> 5;
    int lane = threadIdx.x & 31;
    int per = (NN + nwarps - 1) / nwarps;
    int s = w * per;
    int e = min(NN, s + per);
    if (s >= e) return;
    float m0 = -__int_as_float(0x7f800000), m1 = m0;
    float s0 = 0.f, s1 = 0.f;
    int cnt = 0;
    int curg = __ldg(&batch[s]);
    for (int i = s; i < e; i++) {
        int g = __ldg(&batch[i]);
        if (g != curg) {
            atomicMax(&g_gmax[curg * 64 + lane], fenc(m0));
            atomicMax(&g_gmax[curg * 64 + lane + 32], fenc(m1));
            atomicAdd(&g_gsum[curg * 64 + lane], s0);
            atomicAdd(&g_gsum[curg * 64 + lane + 32], s1);
            if (lane == 0) atomicAdd(&g_gcnt[curg], cnt);
            m0 = m1 = -__int_as_float(0x7f800000);
            s0 = s1 = 0.f; cnt = 0; curg = g;
        }
        float v0 = x[(size_t)i * 64 + lane];
        float v1 = x[(size_t)i * 64 + lane + 32];
        m0 = fmaxf(m0, v0); m1 = fmaxf(m1, v1);
        s0 += v0; s1 += v1; cnt++;
    }
    atomicMax(&g_gmax[curg * 64 + lane], fenc(m0));
    atomicMax(&g_gmax[curg * 64 + lane + 32], fenc(m1));
    atomicAdd(&g_gsum[curg * 64 + lane], s0);
    atomicAdd(&g_gsum[curg * 64 + lane + 32], s1);
    if (lane == 0) atomicAdd(&g_gcnt[curg], cnt);
}

// ---------------- final ----------------
__global__ void final_kernel(const float* __restrict__ post_w, const float* __restrict__ post_b,
                             float* __restrict__ out) {
    int g = threadIdx.x;
    if (g >= NG) return;
    float inv = 1.0f / (float)g_gcnt[g];
    float v[64];
    float ss = 0.f;
#pragma unroll
    for (int c = 0; c < 64; c++) {
        float t = fdec(g_gmax[g * 64 + c]) + g_gsum[g * 64 + c] * inv;
        v[c] = t;
        ss += t * t;
    }
    float norm = sqrtf(ss);
    float dot = 0.f;
#pragma unroll
    for (int c = 0; c < 64; c++) dot += v[c] * post_w[c];
    out[g] = dot / norm + post_b[0];
}

// ---------------- launch ----------------
static cudaStream_t g_s2 = nullptr;
static cudaEvent_t g_ev1 = nullptr, g_ev2 = nullptr;

extern "C" void kernel_launch(void* const* d_in, const int* in_sizes, int n_in,
                              void* d_out, int out_size) {
    const float* node_feat = (const float*)d_in[0];
    const float* cfg_feat  = (const float*)d_in[1];
    const int*   opcode    = (const int*)d_in[2];
    const int*   edge      = (const int*)d_in[3];
    const int*   batch     = (const int*)d_in[4];
    const float* op_emb    = (const float*)d_in[5];
    const float* lin_w     = (const float*)d_in[6];
    const float* lin_b     = (const float*)d_in[7];
    const float* post_w    = (const float*)d_in[8];
    const float* post_b    = (const float*)d_in[9];
    const float* pw0 = (const float*)d_in[10];
    const float* pb0 = (const float*)d_in[11];
    const float* wl0 = (const float*)d_in[12];
    const float* bl0 = (const float*)d_in[13];
    const float* wr0 = (const float*)d_in[14];
    const float* pw1 = (const float*)d_in[15];
    const float* pb1 = (const float*)d_in[16];
    const float* wl1 = (const float*)d_in[17];
    const float* bl1 = (const float*)d_in[18];
    const float* wr1 = (const float*)d_in[19];
    const float* pw2 = (const float*)d_in[20];
    const float* pb2 = (const float*)d_in[21];
    const float* wl2 = (const float*)d_in[22];
    const float* bl2 = (const float*)d_in[23];
    const float* wr2 = (const float*)d_in[24];
    float* out = (float*)d_out;

    if (g_s2 == nullptr) {  // one-time infra setup (first call is the uncaptured correctness run)
        cudaStreamCreateWithFlags(&g_s2, cudaStreamNonBlocking);
        cudaEventCreateWithFlags(&g_ev1, cudaEventDisableTiming);
        cudaEventCreateWithFlags(&g_ev2, cudaEventDisableTiming);
        cudaFuncSetAttribute(projz<128>, cudaFuncAttributeMaxDynamicSharedMemorySize, 98304);
        cudaFuncSetAttribute(projz<64>,  cudaFuncAttributeMaxDynamicSharedMemorySize, 65536);
    }

    const int* src = edge;
    const int* dst = edge + NE;

    const int MB = (NN + 127) / 128;   // 782
    const int EB = (NE + 255) / 256;
    const int AGGB = (NN * 32 + 255) / 256;
    const size_t SMEM48 = 49152;
    const size_t SMEM_PZ128 = 98304;
    const size_t SMEM_PZ64  = 65536;

    float* dA; cudaGetSymbolAddress((void**)&dA, g_xA);
    float* dB; cudaGetSymbolAddress((void**)&dB, g_xB);
    __half2* dZ; cudaGetSymbolAddress((void**)&dZ, g_z);
    float* dM; cudaGetSymbolAddress((void**)&dM, g_msg);

    // ---- fork: CSR build on side stream, encoder GEMMs on main stream ----
    cudaEventRecord(g_ev1, 0);
    cudaStreamWaitEvent(g_s2, g_ev1, 0);

    init_kernel<<<(NN + 255) / 256, 256, 0, g_s2>>>();
    hist_kernel<<<EB, 256, 0, g_s2>>>(dst);
    scan1_kernel<<<NBLK, 256, 0, g_s2>>>();
    scan2_kernel<<<1, 128, 0, g_s2>>>();
    scan3_kernel<<<NBLK, 256, 0, g_s2>>>();
    fill_adj_kernel<<<EB, 256, 0, g_s2>>>(src, dst);
    cudaEventRecord(g_ev2, g_s2);

    lin_frag<<<dim3(MB, 2), 256, SMEM48>>>(node_feat, cfg_feat, opcode, op_emb, lin_w, lin_b, dA);
    projz<128><<<MB, 256, SMEM_PZ128>>>(dA, pw0, pb0, wl0, dZ);

    // ---- join: aggregation needs the CSR ----
    cudaStreamWaitEvent(0, g_ev2, 0);

    // layer 0 (d=128 -> 64)
    agg_half<<<AGGB, 256>>>(dZ, dM);
    combine1<128><<<MB, 256, SMEM48>>>(dA, wr0, dM, bl0, dB);

    // layer 1 (d=64 -> 64)
    projz<64><<<MB, 256, SMEM_PZ64>>>(dB, pw1, pb1, wl1, dZ);
    agg_half<<<AGGB, 256>>>(dZ, dM);
    combine1<64><<<MB, 256, SMEM48>>>(dB, wr1, dM, bl1, dA);

    // layer 2 (d=64 -> 64)
    projz<64><<<MB, 256, SMEM_PZ64>>>(dA, pw2, pb2, wl2, dZ);
    agg_half<<<AGGB, 256>>>(dZ, dM);
    combine1<64><<<MB, 256, SMEM48>>>(dA, wr2, dM, bl2, dB);

    pool_kernel<<<128, 256>>>(dB, batch);
    final_kernel<<<1, 64>>>(post_w, post_b, out);
}

// round 10
// speedup vs baseline: 2.3089x; 1.1542x over previous
#include <cuda_runtime.h>
#include <cuda_fp16.h>
#include <cstdint>

#define NN 100000
#define NE 1600000
#define NG 64
#define NBLK 98   // ceil(NN/1024)

// ---------------- scratch ----------------
// activation buffers as half2 words (max 128 cols = 64 words/row)
__device__ __align__(256) uint32_t g_xA[(size_t)NN * 64];
__device__ __align__(256) uint32_t g_xB[(size_t)NN * 64];
__device__ __align__(256) float g_xC[(size_t)NN * 64];   // fp32 final-layer output
__device__ __align__(256) __half2 g_z[(size_t)NN * 32];
__device__ __align__(256) float g_msg[(size_t)NN * 64];
__device__ int g_deg[NN];
__device__ int g_cursor[NN];
__device__ int g_rowptr[NN + 1];
__device__ int g_adj[NE];
__device__ int g_bsum[NBLK];
__device__ int g_boff[NBLK];
__device__ unsigned g_gmax[NG * 64];
__device__ float g_gsum[NG * 64];
__device__ int g_gcnt[NG];

// ---------------- helpers ----------------
__device__ __forceinline__ uint32_t f2h2(float lo, float hi) {
    __half2 h = __floats2half2_rn(lo, hi);
    return *reinterpret_cast<uint32_t*>(&h);
}
__device__ __forceinline__ void mma16(float* c, const uint32_t* a, const uint32_t* b) {
    asm volatile(
        "mma.sync.aligned.m16n8k16.row.col.f32.f16.f16.f32 "
        "{%0,%1,%2,%3}, {%4,%5,%6,%7}, {%8,%9}, {%0,%1,%2,%3};"
        : "+f"(c[0]), "+f"(c[1]), "+f"(c[2]), "+f"(c[3])
        : "r"(a[0]), "r"(a[1]), "r"(a[2]), "r"(a[3]), "r"(b[0]), "r"(b[1]));
}
__device__ __forceinline__ unsigned fenc(float f) {
    unsigned u = __float_as_uint(f);
    return (u & 0x80000000u) ? ~u : (u | 0x80000000u);
}
__device__ __forceinline__ float fdec(unsigned e) {
    return __uint_as_float((e & 0x80000000u) ? (e ^ 0x80000000u) : ~e);
}

// ---------------- fp16 XOR-swizzled tiles ----------------
// A tile: 128 rows x 16 half2 words (32-word row stride, 4096 words/tile)
//   word = row*32 + 4*((c2>>2) ^ (row&7)) + (c2&3),  c2 = half2-column 0..15 (32 k-halves)
// B tile: N n-rows x 16 half2 words, same form (N*32 words)
__device__ __forceinline__ void stTile4(uint32_t* s, int row, int qq, uint4 w) {
    *reinterpret_cast<uint4*>(s + row * 32 + 4 * (qq ^ (row & 7))) = w;
}
// scatter into chunked A tiles during projz restage (c2 = global half2 col)
__device__ __forceinline__ void stXh(uint32_t* sX, int row, int c2, uint32_t w) {
    uint32_t* t = sX + (c2 >> 4) * 4096;
    int lc = c2 & 15;
    t[row * 32 + 4 * ((lc >> 2) ^ (row & 7)) + (lc & 3)] = w;
}

// conflict-free fp16 fragment consumer: per 32-K chunk, 2 k16 steps
template <int NT>
__device__ __forceinline__ void chunk_mma_h(const uint32_t* sA, const uint32_t* sB,
                                            float (&acc)[2][NT][4], int rowB, int colB, int lane) {
    const int qr = lane >> 2, qc = lane & 3;
#pragma unroll
    for (int s = 0; s < 2; s++) {
        uint32_t a[2][4];
#pragma unroll
        for (int mt = 0; mt < 2; mt++) {
            int r0 = rowB + mt * 16 + qr;
            const uint32_t* p0 = sA + r0 * 32;
            const uint32_t* p1 = sA + (r0 + 8) * 32;
            a[mt][0] = p0[4 * ((2 * s) ^ qr) + qc];
            a[mt][1] = p1[4 * ((2 * s) ^ qr) + qc];
            a[mt][2] = p0[4 * ((2 * s + 1) ^ qr) + qc];
            a[mt][3] = p1[4 * ((2 * s + 1) ^ qr) + qc];
        }
#pragma unroll
        for (int nt = 0; nt < NT; nt++) {
            int n = colB + nt * 8 + qr;
            const uint32_t* bb = sB + n * 32;
            uint32_t b[2] = { bb[4 * ((2 * s) ^ qr) + qc], bb[4 * ((2 * s + 1) ^ qr) + qc] };
#pragma unroll
            for (int mt = 0; mt < 2; mt++) mma16(acc[mt][nt], a[mt], b);
        }
    }
}

// ---------------- init ----------------
__global__ void init_kernel() {
    int j = blockIdx.x * blockDim.x + threadIdx.x;
    if (j < NN) { g_deg[j] = 0; g_cursor[j] = 0; }
    if (j < NG * 64) { g_gmax[j] = 0x007FFFFFu; g_gsum[j] = 0.f; }
    if (j < NG) g_gcnt[j] = 0;
}

// ---------------- CSR build ----------------
__global__ void hist_kernel(const int* __restrict__ dst) {
    int e = blockIdx.x * blockDim.x + threadIdx.x;
    if (e < NE) atomicAdd(&g_deg[dst[e]], 1);
}

__global__ void scan1_kernel() {
    __shared__ int wsum[8];
    int b = blockIdx.x, tid = threadIdx.x, lane = tid & 31, w = tid >> 5;
    int i0 = b * 1024 + tid * 4;
    int s = 0;
#pragma unroll
    for (int j = 0; j < 4; j++) { int i = i0 + j; if (i < NN) s += g_deg[i]; }
#pragma unroll
    for (int o = 16; o > 0; o >>= 1) s += __shfl_xor_sync(0xffffffffu, s, o);
    if (lane == 0) wsum[w] = s;
    __syncthreads();
    if (tid == 0) {
        int t = 0;
#pragma unroll
        for (int k = 0; k < 8; k++) t += wsum[k];
        g_bsum[b] = t;
    }
}

__global__ void scan2_kernel() {
    __shared__ int ws[4];
    int tid = threadIdx.x, lane = tid & 31, w = tid >> 5;
    int v = (tid < NBLK) ? g_bsum[tid] : 0;
    int si = v;
#pragma unroll
    for (int o = 1; o < 32; o <<= 1) { int t = __shfl_up_sync(0xffffffffu, si, o); if (lane >= o) si += t; }
    if (lane == 31) ws[w] = si;
    __syncthreads();
    if (tid == 0) {
        int run = 0;
#pragma unroll
        for (int k = 0; k < 4; k++) { int t = ws[k]; ws[k] = run; run += t; }
        g_rowptr[NN] = run;
    }
    __syncthreads();
    if (tid < NBLK) g_boff[tid] = ws[w] + si - v;
}

__global__ void scan3_kernel() {
    __shared__ int wsum[8];
    int b = blockIdx.x, tid = threadIdx.x, lane = tid & 31, w = tid >> 5;
    int i0 = b * 1024 + tid * 4;
    int v[4], s = 0;
#pragma unroll
    for (int j = 0; j < 4; j++) { int i = i0 + j; v[j] = (i < NN) ? g_deg[i] : 0; s += v[j]; }
    int si = s;
#pragma unroll
    for (int o = 1; o < 32; o <<= 1) { int t = __shfl_up_sync(0xffffffffu, si, o); if (lane >= o) si += t; }
    if (lane == 31) wsum[w] = si;
    __syncthreads();
    if (tid == 0) {
        int run = 0;
#pragma unroll
        for (int k = 0; k < 8; k++) { int t = wsum[k]; wsum[k] = run; run += t; }
    }
    __syncthreads();
    int off = g_boff[b] + wsum[w] + (si - s);
#pragma unroll
    for (int j = 0; j < 4; j++) { int i = i0 + j; if (i < NN) g_rowptr[i] = off; off += v[j]; }
}

__global__ void fill_adj_kernel(const int* __restrict__ src, const int* __restrict__ dst) {
    int e = blockIdx.x * blockDim.x + threadIdx.x;
    if (e < NE) {
        int d = dst[e];
        int p = atomicAdd(&g_cursor[d], 1);
        g_adj[g_rowptr[d] + p] = src[e];
    }
}

// ---------------- lin: Ch = relu(concat(nf,emb,cf) @ W + b) as half2, 64 cols/y-block ----------------
__device__ __forceinline__ float4 lin_ld4(const float* nf, const float* cf,
                                          const int* opc, const float* emb, int grow, int k) {
    float4 v = make_float4(0, 0, 0, 0);
    if (k < 140)      v = *(const float4*)(nf + (size_t)grow * 140 + k);
    else if (k < 172) v = *(const float4*)(emb + (size_t)opc[grow] * 32 + (k - 140));
    else if (k < 190) {
        const float* cp = cf + (size_t)grow * 18;
        int off = k - 172;
        v.x = cp[off];
        v.y = (off + 1 < 18) ? cp[off + 1] : 0.f;
        v.z = (off + 2 < 18) ? cp[off + 2] : 0.f;
        v.w = (off + 3 < 18) ? cp[off + 3] : 0.f;
    }
    return v;
}

__global__ void __launch_bounds__(256)
lin_h(const float* __restrict__ nf, const float* __restrict__ cf,
      const int* __restrict__ opc, const float* __restrict__ emb,
      const float* __restrict__ W, const float* __restrict__ bias,
      uint32_t* __restrict__ C) {
    extern __shared__ uint32_t smem[];
    const int tid = threadIdx.x, lane = tid & 31, wid = tid >> 5;
    const int warpM = wid & 3, warpN = wid >> 2;
    const int rowBase = blockIdx.x * 128;
    const int n0 = blockIdx.y * 64;

    float acc[2][4][4];
#pragma unroll
    for (int mt = 0; mt < 2; mt++)
#pragma unroll
        for (int nt = 0; nt < 4; nt++)
#pragma unroll
            for (int q = 0; q < 4; q++) acc[mt][nt][q] = 0.f;

    uint4 ra[2], rb;
    auto loadC = [&](int c) {
#pragma unroll
        for (int i = 0; i < 2; i++) {
            int g = tid + 256 * i;
            int row = g & 127, qq = g >> 7;
            int grow = rowBase + row;
            uint4 w = make_uint4(0, 0, 0, 0);
            if (grow < NN) {
                float4 v0 = lin_ld4(nf, cf, opc, emb, grow, c * 32 + 8 * qq);
                float4 v1 = lin_ld4(nf, cf, opc, emb, grow, c * 32 + 8 * qq + 4);
                w = make_uint4(f2h2(v0.x, v0.y), f2h2(v0.z, v0.w), f2h2(v1.x, v1.y), f2h2(v1.z, v1.w));
            }
            ra[i] = w;
        }
        {
            int n = tid & 63, qq = tid >> 6;
            float f[8];
#pragma unroll
            for (int j = 0; j < 8; j++) {
                int kg = c * 32 + 8 * qq + j;
                f[j] = (kg < 190) ? W[(size_t)kg * 128 + n0 + n] : 0.f;
            }
            rb = make_uint4(f2h2(f[0], f[1]), f2h2(f[2], f[3]), f2h2(f[4], f[5]), f2h2(f[6], f[7]));
        }
    };
    auto stage = [&](int b) {
        uint32_t* sa = smem + (b ? 4096 : 0);
        uint32_t* sb = smem + 8192 + (b ? 2048 : 0);
#pragma unroll
        for (int i = 0; i < 2; i++) {
            int g = tid + 256 * i;
            stTile4(sa, g & 127, g >> 7, ra[i]);
        }
        stTile4(sb, tid & 63, tid >> 6, rb);
    };

    loadC(0); stage(0); __syncthreads();
#pragma unroll 1
    for (int c = 0; c < 6; c++) {
        if (c < 5) loadC(c + 1);
        const uint32_t* sa = smem + ((c & 1) ? 4096 : 0);
        const uint32_t* sb = smem + 8192 + ((c & 1) ? 2048 : 0);
        chunk_mma_h<4>(sa, sb, acc, warpM * 32, warpN * 32, lane);
        if (c < 5) { stage((c + 1) & 1); __syncthreads(); }
    }

    const int qr = lane >> 2, qc = lane & 3;
#pragma unroll
    for (int mt = 0; mt < 2; mt++) {
        int r0 = rowBase + warpM * 32 + mt * 16 + qr;
#pragma unroll
        for (int nt = 0; nt < 4; nt++) {
            int gc = n0 + warpN * 32 + nt * 8 + 2 * qc;
            float b0 = __ldg(&bias[gc]), b1 = __ldg(&bias[gc + 1]);
            if (r0 < NN)
                C[(size_t)r0 * 64 + gc / 2] =
                    f2h2(fmaxf(acc[mt][nt][0] + b0, 0.f), fmaxf(acc[mt][nt][1] + b1, 0.f));
            if (r0 + 8 < NN)
                C[(size_t)(r0 + 8) * 64 + gc / 2] =
                    f2h2(fmaxf(acc[mt][nt][2] + b0, 0.f), fmaxf(acc[mt][nt][3] + b1, 0.f));
        }
    }
}

// ---------------- projz: Z(half2) = relu(A@PW + PB) @ WL, A half2 ----------------
template <int K>
__global__ void __launch_bounds__(256)
projz_h(const uint32_t* __restrict__ A, const float* __restrict__ PW,
        const float* __restrict__ PB, const float* __restrict__ WL,
        __half2* __restrict__ Z) {
    constexpr int NCH = K / 32;
    constexpr int CW = K / 2;
    constexpr int NT1 = CW / 8;
    constexpr int INB = K * 32;                 // B tile words per chunk
    constexpr int INW = 8192 + 2 * INB;
    constexpr int XW = NCH * 4096;
    constexpr int UW = (INW > XW) ? INW : XW;
    constexpr int NST = K / 64;                 // PW stores per thread per chunk
    extern __shared__ uint32_t smem[];
    uint32_t* W2 = smem + UW;

    const int tid = threadIdx.x, lane = tid & 31, wid = tid >> 5;
    const int warpM = wid & 3, warpN = wid >> 2;
    const int rowBase = blockIdx.x * 128;
    const int qr = lane >> 2, qc = lane & 3;

    // stage WL chunks once (64 n-rows each)
#pragma unroll
    for (int c = 0; c < NCH; c++) {
        int n = tid & 63, qq = tid >> 6;
        float f[8];
#pragma unroll
        for (int j = 0; j < 8; j++) f[j] = WL[(size_t)(c * 32 + 8 * qq + j) * 64 + n];
        stTile4(W2 + c * 2048, n, qq,
                make_uint4(f2h2(f[0], f[1]), f2h2(f[2], f[3]), f2h2(f[4], f[5]), f2h2(f[6], f[7])));
    }

    float acc1[2][NT1][4];
#pragma unroll
    for (int mt = 0; mt < 2; mt++)
#pragma unroll
        for (int nt = 0; nt < NT1; nt++)
#pragma unroll
            for (int q = 0; q < 4; q++) acc1[mt][nt][q] = 0.f;

    uint4 ra[2], rb[NST];
    auto loadC = [&](int c) {
#pragma unroll
        for (int i = 0; i < 2; i++) {
            int g = tid + 256 * i;
            int row = g & 127, qq = g >> 7;
            int grow = rowBase + row;
            ra[i] = (grow < NN)
                ? *reinterpret_cast<const uint4*>(A + (size_t)grow * (K / 2) + c * 16 + 4 * qq)
                : make_uint4(0, 0, 0, 0);
        }
#pragma unroll
        for (int i = 0; i < NST; i++) {
            int g = tid + 256 * i;
            int n = g % K, qq = g / K;
            float f[8];
#pragma unroll
            for (int j = 0; j < 8; j++) f[j] = PW[(size_t)(c * 32 + 8 * qq + j) * K + n];
            rb[i] = make_uint4(f2h2(f[0], f[1]), f2h2(f[2], f[3]), f2h2(f[4], f[5]), f2h2(f[6], f[7]));
        }
    };
    auto stage = [&](int b) {
        uint32_t* sa = smem + (b ? 4096 : 0);
        uint32_t* sb = smem + 8192 + (b ? INB : 0);
#pragma unroll
        for (int i = 0; i < 2; i++) {
            int g = tid + 256 * i;
            stTile4(sa, g & 127, g >> 7, ra[i]);
        }
#pragma unroll
        for (int i = 0; i < NST; i++) {
            int g = tid + 256 * i;
            stTile4(sb, g % K, g / K, rb[i]);
        }
    };

    loadC(0); stage(0); __syncthreads();
#pragma unroll 1
    for (int c = 0; c < NCH; c++) {
        if (c + 1 < NCH) loadC(c + 1);
        const uint32_t* sa = smem + ((c & 1) ? 4096 : 0);
        const uint32_t* sb = smem + 8192 + ((c & 1) ? INB : 0);
        chunk_mma_h<NT1>(sa, sb, acc1, warpM * 32, warpN * CW, lane);
        if (c + 1 < NCH) { stage((c + 1) & 1); __syncthreads(); }
    }
    __syncthreads();  // phase-1 reads done before overwrite

    // restage xp = relu(acc1 + PB) into X tiles (half2)
#pragma unroll
    for (int mt = 0; mt < 2; mt++) {
        int r0 = warpM * 32 + mt * 16 + qr;
#pragma unroll
        for (int nt = 0; nt < NT1; nt++) {
            int col = warpN * CW + nt * 8 + 2 * qc;
            float b0 = __ldg(&PB[col]), b1 = __ldg(&PB[col + 1]);
            stXh(smem, r0, col / 2,
                 f2h2(fmaxf(acc1[mt][nt][0] + b0, 0.f), fmaxf(acc1[mt][nt][1] + b1, 0.f)));
            stXh(smem, r0 + 8, col / 2,
                 f2h2(fmaxf(acc1[mt][nt][2] + b0, 0.f), fmaxf(acc1[mt][nt][3] + b1, 0.f)));
        }
    }
    __syncthreads();

    float acc2[2][4][4];
#pragma unroll
    for (int mt = 0; mt < 2; mt++)
#pragma unroll
        for (int nt = 0; nt < 4; nt++)
#pragma unroll
            for (int q = 0; q < 4; q++) acc2[mt][nt][q] = 0.f;
#pragma unroll
    for (int c = 0; c < NCH; c++)
        chunk_mma_h<4>(smem + c * 4096, W2 + c * 2048, acc2, warpM * 32, warpN * 32, lane);

#pragma unroll
    for (int mt = 0; mt < 2; mt++) {
        int r0 = rowBase + warpM * 32 + mt * 16 + qr;
#pragma unroll
        for (int nt = 0; nt < 4; nt++) {
            int gc = warpN * 32 + nt * 8 + 2 * qc;
            if (r0 < NN)
                Z[(size_t)r0 * 32 + gc / 2] = __floats2half2_rn(acc2[mt][nt][0], acc2[mt][nt][1]);
            if (r0 + 8 < NN)
                Z[(size_t)(r0 + 8) * 32 + gc / 2] = __floats2half2_rn(acc2[mt][nt][2], acc2[mt][nt][3]);
        }
    }
}

// ---------------- combine: out = normalize(X@WR + MZ + BL); HOUT: half2 vs fp32 ----------------
template <int K, bool HOUT>
__global__ void __launch_bounds__(256)
combine_h(const uint32_t* __restrict__ X, const float* __restrict__ WR,
          const float* __restrict__ MZ, const float* __restrict__ BL,
          void* __restrict__ Cout) {
    constexpr int NCH = K / 32;
    extern __shared__ uint32_t smem[];
    const int tid = threadIdx.x, lane = tid & 31, wid = tid >> 5;
    const int warpM = wid & 3, warpN = wid >> 2;
    const int rowBase = blockIdx.x * 128;

    float acc[2][4][4];
#pragma unroll
    for (int mt = 0; mt < 2; mt++)
#pragma unroll
        for (int nt = 0; nt < 4; nt++)
#pragma unroll
            for (int q = 0; q < 4; q++) acc[mt][nt][q] = 0.f;

    uint4 ra[2], rb;
    auto loadC = [&](int c) {
#pragma unroll
        for (int i = 0; i < 2; i++) {
            int g = tid + 256 * i;
            int row = g & 127, qq = g >> 7;
            int grow = rowBase + row;
            ra[i] = (grow < NN)
                ? *reinterpret_cast<const uint4*>(X + (size_t)grow * (K / 2) + c * 16 + 4 * qq)
                : make_uint4(0, 0, 0, 0);
        }
        {
            int n = tid & 63, qq = tid >> 6;
            float f[8];
#pragma unroll
            for (int j = 0; j < 8; j++) f[j] = WR[(size_t)(c * 32 + 8 * qq + j) * 64 + n];
            rb = make_uint4(f2h2(f[0], f[1]), f2h2(f[2], f[3]), f2h2(f[4], f[5]), f2h2(f[6], f[7]));
        }
    };
    auto stage = [&](int b) {
        uint32_t* sa = smem + (b ? 4096 : 0);
        uint32_t* sb = smem + 8192 + (b ? 2048 : 0);
#pragma unroll
        for (int i = 0; i < 2; i++) {
            int g = tid + 256 * i;
            stTile4(sa, g & 127, g >> 7, ra[i]);
        }
        stTile4(sb, tid & 63, tid >> 6, rb);
    };

    loadC(0); stage(0); __syncthreads();
#pragma unroll 1
    for (int c = 0; c < NCH; c++) {
        if (c + 1 < NCH) loadC(c + 1);
        const uint32_t* sa = smem + ((c & 1) ? 4096 : 0);
        const uint32_t* sb = smem + 8192 + ((c & 1) ? 2048 : 0);
        chunk_mma_h<4>(sa, sb, acc, warpM * 32, warpN * 32, lane);
        if (c + 1 < NCH) { stage((c + 1) & 1); __syncthreads(); }
    }

    // epilogue: + MZ + BL, stage to smem (stride 66 for float2 reads), row-normalize
    __syncthreads();
    float (*sOut)[66] = reinterpret_cast<float(*)[66]>(smem);
    const int qr = lane >> 2, qc = lane & 3;
#pragma unroll
    for (int mt = 0; mt < 2; mt++) {
        int rl = warpM * 32 + mt * 16 + qr;
        int g0 = rowBase + rl, g1 = rowBase + rl + 8;
#pragma unroll
        for (int nt = 0; nt < 4; nt++) {
            int cl = warpN * 32 + nt * 8 + 2 * qc;
            float b0 = __ldg(&BL[cl]), b1 = __ldg(&BL[cl + 1]);
            float2 m0 = (g0 < NN) ? *(const float2*)(MZ + (size_t)g0 * 64 + cl) : make_float2(0, 0);
            float2 m1 = (g1 < NN) ? *(const float2*)(MZ + (size_t)g1 * 64 + cl) : make_float2(0, 0);
            sOut[rl][cl]         = acc[mt][nt][0] + b0 + m0.x;
            sOut[rl][cl + 1]     = acc[mt][nt][1] + b1 + m0.y;
            sOut[rl + 8][cl]     = acc[mt][nt][2] + b0 + m1.x;
            sOut[rl + 8][cl + 1] = acc[mt][nt][3] + b1 + m1.y;
        }
    }
    __syncthreads();
#pragma unroll
    for (int rr = 0; rr < 16; rr++) {
        int r = wid * 16 + rr;
        int grow = rowBase + r;
        float2 v = *(const float2*)&sOut[r][2 * lane];
        float ss = v.x * v.x + v.y * v.y;
#pragma unroll
        for (int o = 16; o > 0; o >>= 1) ss += __shfl_xor_sync(0xffffffffu, ss, o);
        float sc = 1.0f / fmaxf(sqrtf(ss), 1e-12f);
        if (grow < NN) {
            if (HOUT) {
                ((uint32_t*)Cout)[(size_t)grow * 32 + lane] = f2h2(v.x * sc, v.y * sc);
            } else {
                *(float2*)((float*)Cout + (size_t)grow * 64 + 2 * lane) =
                    make_float2(v.x * sc, v.y * sc);
            }
        }
    }
}

// ---------------- mean aggregation over CSR (64-dim, half2 source, x4 MLP) ----------------
__global__ void agg_half(const __half2* __restrict__ zp, float* __restrict__ msg) {
    int w = (blockIdx.x * blockDim.x + threadIdx.x) >> 5;
    int lane = threadIdx.x & 31;
    if (w >= NN) return;
    int beg = g_rowptr[w], end = g_rowptr[w + 1];
    float2 acc = make_float2(0, 0);
    int e = beg;
    for (; e + 4 <= end; e += 4) {
        int s0 = __ldg(&g_adj[e]);
        int s1 = __ldg(&g_adj[e + 1]);
        int s2 = __ldg(&g_adj[e + 2]);
        int s3 = __ldg(&g_adj[e + 3]);
        float2 v0 = __half22float2(zp[(size_t)s0 * 32 + lane]);
        float2 v1 = __half22float2(zp[(size_t)s1 * 32 + lane]);
        float2 v2 = __half22float2(zp[(size_t)s2 * 32 + lane]);
        float2 v3 = __half22float2(zp[(size_t)s3 * 32 + lane]);
        acc.x += (v0.x + v1.x) + (v2.x + v3.x);
        acc.y += (v0.y + v1.y) + (v2.y + v3.y);
    }
    for (; e < end; e++) {
        int s = __ldg(&g_adj[e]);
        float2 v = __half22float2(zp[(size_t)s * 32 + lane]);
        acc.x += v.x; acc.y += v.y;
    }
    float inv = 1.0f / fmaxf((float)(end - beg), 1.0f);
    *reinterpret_cast<float2*>(msg + (size_t)w * 64 + lane * 2) =
        make_float2(acc.x * inv, acc.y * inv);
}

// ---------------- pooling (fp32 final x, contiguous 64 cols) ----------------
__global__ void pool_kernel(const float* __restrict__ x, const int* __restrict__ batch) {
    int nwarps = (gridDim.x * blockDim.x) >> 5;
    int w = (blockIdx.x * blockDim.x + threadIdx.x) >> 5;
    int lane = threadIdx.x & 31;
    int per = (NN + nwarps - 1) / nwarps;
    int s = w * per;
    int e = min(NN, s + per);
    if (s >= e) return;
    float m0 = -__int_as_float(0x7f800000), m1 = m0;
    float s0 = 0.f, s1 = 0.f;
    int cnt = 0;
    int curg = __ldg(&batch[s]);
    for (int i = s; i < e; i++) {
        int g = __ldg(&batch[i]);
        if (g != curg) {
            atomicMax(&g_gmax[curg * 64 + lane], fenc(m0));
            atomicMax(&g_gmax[curg * 64 + lane + 32], fenc(m1));
            atomicAdd(&g_gsum[curg * 64 + lane], s0);
            atomicAdd(&g_gsum[curg * 64 + lane + 32], s1);
            if (lane == 0) atomicAdd(&g_gcnt[curg], cnt);
            m0 = m1 = -__int_as_float(0x7f800000);
            s0 = s1 = 0.f; cnt = 0; curg = g;
        }
        float v0 = x[(size_t)i * 64 + lane];
        float v1 = x[(size_t)i * 64 + lane + 32];
        m0 = fmaxf(m0, v0); m1 = fmaxf(m1, v1);
        s0 += v0; s1 += v1; cnt++;
    }
    atomicMax(&g_gmax[curg * 64 + lane], fenc(m0));
    atomicMax(&g_gmax[curg * 64 + lane + 32], fenc(m1));
    atomicAdd(&g_gsum[curg * 64 + lane], s0);
    atomicAdd(&g_gsum[curg * 64 + lane + 32], s1);
    if (lane == 0) atomicAdd(&g_gcnt[curg], cnt);
}

// ---------------- final ----------------
__global__ void final_kernel(const float* __restrict__ post_w, const float* __restrict__ post_b,
                             float* __restrict__ out) {
    int g = threadIdx.x;
    if (g >= NG) return;
    float inv = 1.0f / (float)g_gcnt[g];
    float v[64];
    float ss = 0.f;
#pragma unroll
    for (int c = 0; c < 64; c++) {
        float t = fdec(g_gmax[g * 64 + c]) + g_gsum[g * 64 + c] * inv;
        v[c] = t;
        ss += t * t;
    }
    float norm = sqrtf(ss);
    float dot = 0.f;
#pragma unroll
    for (int c = 0; c < 64; c++) dot += v[c] * post_w[c];
    out[g] = dot / norm + post_b[0];
}

// ---------------- launch ----------------
static cudaStream_t g_s2 = nullptr;
static cudaEvent_t g_ev1 = nullptr, g_ev2 = nullptr;

extern "C" void kernel_launch(void* const* d_in, const int* in_sizes, int n_in,
                              void* d_out, int out_size) {
    const float* node_feat = (const float*)d_in[0];
    const float* cfg_feat  = (const float*)d_in[1];
    const int*   opcode    = (const int*)d_in[2];
    const int*   edge      = (const int*)d_in[3];
    const int*   batch     = (const int*)d_in[4];
    const float* op_emb    = (const float*)d_in[5];
    const float* lin_w     = (const float*)d_in[6];
    const float* lin_b     = (const float*)d_in[7];
    const float* post_w    = (const float*)d_in[8];
    const float* post_b    = (const float*)d_in[9];
    const float* pw0 = (const float*)d_in[10];
    const float* pb0 = (const float*)d_in[11];
    const float* wl0 = (const float*)d_in[12];
    const float* bl0 = (const float*)d_in[13];
    const float* wr0 = (const float*)d_in[14];
    const float* pw1 = (const float*)d_in[15];
    const float* pb1 = (const float*)d_in[16];
    const float* wl1 = (const float*)d_in[17];
    const float* bl1 = (const float*)d_in[18];
    const float* wr1 = (const float*)d_in[19];
    const float* pw2 = (const float*)d_in[20];
    const float* pb2 = (const float*)d_in[21];
    const float* wl2 = (const float*)d_in[22];
    const float* bl2 = (const float*)d_in[23];
    const float* wr2 = (const float*)d_in[24];
    float* out = (float*)d_out;

    if (g_s2 == nullptr) {
        cudaStreamCreateWithFlags(&g_s2, cudaStreamNonBlocking);
        cudaEventCreateWithFlags(&g_ev1, cudaEventDisableTiming);
        cudaEventCreateWithFlags(&g_ev2, cudaEventDisableTiming);
        cudaFuncSetAttribute(projz_h<128>, cudaFuncAttributeMaxDynamicSharedMemorySize, 98304);
        cudaFuncSetAttribute(projz_h<64>,  cudaFuncAttributeMaxDynamicSharedMemorySize, 65536);
    }

    const int* src = edge;
    const int* dst = edge + NE;

    const int MB = (NN + 127) / 128;
    const int EB = (NE + 255) / 256;
    const int AGGB = (NN * 32 + 255) / 256;
    const size_t SMEM48 = 49152;
    const size_t SMEM_PZ128 = 98304;
    const size_t SMEM_PZ64  = 65536;

    uint32_t* dA; cudaGetSymbolAddress((void**)&dA, g_xA);
    uint32_t* dB; cudaGetSymbolAddress((void**)&dB, g_xB);
    float* dC; cudaGetSymbolAddress((void**)&dC, g_xC);
    __half2* dZ; cudaGetSymbolAddress((void**)&dZ, g_z);
    float* dM; cudaGetSymbolAddress((void**)&dM, g_msg);

    // fork: CSR build on side stream
    cudaEventRecord(g_ev1, 0);
    cudaStreamWaitEvent(g_s2, g_ev1, 0);
    init_kernel<<<(NN + 255) / 256, 256, 0, g_s2>>>();
    hist_kernel<<<EB, 256, 0, g_s2>>>(dst);
    scan1_kernel<<<NBLK, 256, 0, g_s2>>>();
    scan2_kernel<<<1, 128, 0, g_s2>>>();
    scan3_kernel<<<NBLK, 256, 0, g_s2>>>();
    fill_adj_kernel<<<EB, 256, 0, g_s2>>>(src, dst);
    cudaEventRecord(g_ev2, g_s2);

    lin_h<<<dim3(MB, 2), 256, SMEM48>>>(node_feat, cfg_feat, opcode, op_emb, lin_w, lin_b, dA);
    projz_h<128><<<MB, 256, SMEM_PZ128>>>(dA, pw0, pb0, wl0, dZ);

    cudaStreamWaitEvent(0, g_ev2, 0);

    // layer 0 (d=128 -> 64)
    agg_half<<<AGGB, 256>>>(dZ, dM);
    combine_h<128, true><<<MB, 256, SMEM48>>>(dA, wr0, dM, bl0, dB);

    // layer 1 (d=64 -> 64)
    projz_h<64><<<MB, 256, SMEM_PZ64>>>(dB, pw1, pb1, wl1, dZ);
    agg_half<<<AGGB, 256>>>(dZ, dM);
    combine_h<64, true><<<MB, 256, SMEM48>>>(dB, wr1, dM, bl1, dA);

    // layer 2 (d=64 -> 64), fp32 output for pooling precision
    projz_h<64><<<MB, 256, SMEM_PZ64>>>(dA, pw2, pb2, wl2, dZ);
    agg_half<<<AGGB, 256>>>(dZ, dM);
    combine_h<64, false><<<MB, 256, SMEM48>>>(dA, wr2, dM, bl2, dC);

    pool_kernel<<<128, 256>>>(dC, batch);
    final_kernel<<<1, 64>>>(post_w, post_b, out);
}